// round 7
// baseline (speedup 1.0000x reference)
#include <cuda_runtime.h>
#include <cuda_bf16.h>
#include <math.h>
#include <stdint.h>

// Problem constants
#define TT 512
#define BB 256
#define IN_DIM 256
#define H1 512
#define HH 256
#define OUT_DIM 18
#define MTOT (TT*BB)   // 131072
#define NCTA 128

// -------------------- scratch (static device globals; no allocs) -----------
__device__ float d_buf1[(size_t)MTOT * 512];     // fc2a out (fp32, for head)
__device__ float d_GI  [(size_t)MTOT * 768];     // gi fp32

__device__ __nv_bfloat16 d_XHI[(size_t)MTOT * 256], d_XLO[(size_t)MTOT * 256];
__device__ __nv_bfloat16 d_A1HI[(size_t)MTOT * 512], d_A1LO[(size_t)MTOT * 512];
__device__ __nv_bfloat16 d_A2HI[(size_t)MTOT * 256], d_A2LO[(size_t)MTOT * 256];
__device__ __nv_bfloat16 d_HHI[(size_t)MTOT * 256], d_HLO[(size_t)MTOT * 256];

__device__ __nv_bfloat16 d_W1AHI[512*256], d_W1ALO[512*256];
__device__ __nv_bfloat16 d_W1BHI[256*512], d_W1BLO[256*512];
__device__ __nv_bfloat16 d_WIHHI[768*256], d_WIHLO[768*256];
__device__ __nv_bfloat16 d_W2AHI[512*256], d_W2ALO[512*256];
__device__ __nv_bfloat16 d_WHHHI[768*256], d_WHHLO[768*256];

__device__ unsigned int d_flags[NCTA];           // grid barrier flags

// ==================== helpers ==============================================
__device__ __forceinline__ uint32_t smem_u32(const void* p) {
    uint32_t a;
    asm("{ .reg .u64 t; cvta.to.shared.u64 t, %1; cvt.u32.u64 %0, t; }"
        : "=r"(a) : "l"(p));
    return a;
}

__device__ __forceinline__ void ldsm4(uint32_t* r, uint32_t addr) {
    asm volatile("ldmatrix.sync.aligned.m8n8.x4.shared.b16 {%0,%1,%2,%3}, [%4];"
        : "=r"(r[0]), "=r"(r[1]), "=r"(r[2]), "=r"(r[3]) : "r"(addr));
}
__device__ __forceinline__ void ldsm2(uint32_t* r, uint32_t addr) {
    asm volatile("ldmatrix.sync.aligned.m8n8.x2.shared.b16 {%0,%1}, [%2];"
        : "=r"(r[0]), "=r"(r[1]) : "r"(addr));
}

__device__ __forceinline__ void mma16816(float* c, const uint32_t* a, const uint32_t* b) {
    asm volatile(
        "mma.sync.aligned.m16n8k16.row.col.f32.bf16.bf16.f32 "
        "{%0,%1,%2,%3}, {%4,%5,%6,%7}, {%8,%9}, {%0,%1,%2,%3};"
        : "+f"(c[0]), "+f"(c[1]), "+f"(c[2]), "+f"(c[3])
        : "r"(a[0]), "r"(a[1]), "r"(a[2]), "r"(a[3]), "r"(b[0]), "r"(b[1]));
}

__device__ __forceinline__ void cp16(uint32_t dst, const void* src) {
    asm volatile("cp.async.cg.shared.global [%0], [%1], 16;"
        :: "r"(dst), "l"(src) : "memory");
}
#define CP_COMMIT() asm volatile("cp.async.commit_group;" ::: "memory")
#define CP_WAIT0()  asm volatile("cp.async.wait_group 0;" ::: "memory")
#define CP_WAIT1()  asm volatile("cp.async.wait_group 1;" ::: "memory")

__device__ __forceinline__ void split_bf16x4(float4 v, uint2& hv, uint2& lv) {
    __nv_bfloat16 h0 = __float2bfloat16(v.x);
    __nv_bfloat16 h1 = __float2bfloat16(v.y);
    __nv_bfloat16 h2 = __float2bfloat16(v.z);
    __nv_bfloat16 h3 = __float2bfloat16(v.w);
    __nv_bfloat16 l0 = __float2bfloat16(v.x - __bfloat162float(h0));
    __nv_bfloat16 l1 = __float2bfloat16(v.y - __bfloat162float(h1));
    __nv_bfloat16 l2 = __float2bfloat16(v.z - __bfloat162float(h2));
    __nv_bfloat16 l3 = __float2bfloat16(v.w - __bfloat162float(h3));
    hv.x = (uint32_t)__bfloat16_as_ushort(h0) | ((uint32_t)__bfloat16_as_ushort(h1) << 16);
    hv.y = (uint32_t)__bfloat16_as_ushort(h2) | ((uint32_t)__bfloat16_as_ushort(h3) << 16);
    lv.x = (uint32_t)__bfloat16_as_ushort(l0) | ((uint32_t)__bfloat16_as_ushort(l1) << 16);
    lv.y = (uint32_t)__bfloat16_as_ushort(l2) | ((uint32_t)__bfloat16_as_ushort(l3) << 16);
}

__device__ __forceinline__ uint32_t pack_hi2(float a, float b, uint32_t& lo) {
    __nv_bfloat16 ha = __float2bfloat16(a);
    __nv_bfloat16 hb = __float2bfloat16(b);
    __nv_bfloat16 la = __float2bfloat16(a - __bfloat162float(ha));
    __nv_bfloat16 lb = __float2bfloat16(b - __bfloat162float(hb));
    lo = (uint32_t)__bfloat16_as_ushort(la) | ((uint32_t)__bfloat16_as_ushort(lb) << 16);
    return (uint32_t)__bfloat16_as_ushort(ha) | ((uint32_t)__bfloat16_as_ushort(hb) << 16);
}

// -------------------- split / zero kernels ---------------------------------
__global__ void split_f32(const float4* __restrict__ in,
                          uint2* __restrict__ hi, uint2* __restrict__ lo, int n4) {
    int i = blockIdx.x * blockDim.x + threadIdx.x;
    if (i < n4) {
        uint2 h, l;
        split_bf16x4(in[i], h, l);
        hi[i] = h; lo[i] = l;
    }
}
__global__ void zero_u32(uint32_t* p, int n) {
    int i = blockIdx.x * blockDim.x + threadIdx.x;
    if (i < n) p[i] = 0u;
}

// ==================== pipelined bf16-split GEMM (unchanged, passing) ========
#define GROW 144
#define G_AHI 0
#define G_ALO 18432
#define G_BHI 36864
#define G_BLO 55296
#define G_STAGE 73728
#define G_SM_TOTAL (2*G_STAGE)

template<bool RELU, int OUTM>
__global__ void __launch_bounds__(256, 1) gemm_bf(
    const __nv_bfloat16* __restrict__ Ahi, const __nv_bfloat16* __restrict__ Alo,
    const __nv_bfloat16* __restrict__ Bhi, const __nv_bfloat16* __restrict__ Blo,
    const float* __restrict__ bias,
    float* __restrict__ C, __nv_bfloat16* __restrict__ Chi, __nv_bfloat16* __restrict__ Clo,
    int M, int N, int K)
{
    extern __shared__ char sm[];
    const uint32_t smb = smem_u32(sm);
    const int tid = threadIdx.x;
    const int lane = tid & 31;
    const int wid = tid >> 5;
    const int wm = wid & 1;
    const int wn = wid >> 1;
    const int m0 = blockIdx.y * 128;
    const int n0 = blockIdx.x * 128;

    float acc[4][4][4];
    #pragma unroll
    for (int i = 0; i < 4; i++)
        #pragma unroll
        for (int j = 0; j < 4; j++)
            #pragma unroll
            for (int e = 0; e < 4; e++) acc[i][j][e] = 0.f;

    const uint32_t a_row = (uint32_t)(lane & 15);
    const uint32_t a_kb  = (uint32_t)((lane >> 4) * 16);
    const uint32_t b_row = (uint32_t)(((lane >> 4) & 1) * 8 + (lane & 7));
    const uint32_t b_kb  = (uint32_t)(((lane >> 3) & 1) * 16);

    const int nchunks = K >> 6;

    auto load_chunk = [&](int kc, int st) {
        const int kb = kc << 6;
        const uint32_t base = smb + (uint32_t)st * G_STAGE;
        #pragma unroll
        for (int j = 0; j < 4; j++) {
            int idx = tid + 256 * j;
            int r = idx >> 3;
            int c = idx & 7;
            size_t aoff = (size_t)(m0 + r) * K + kb + c * 8;
            size_t boff = (size_t)(n0 + r) * K + kb + c * 8;
            uint32_t d = (uint32_t)(r * GROW + c * 16);
            cp16(base + G_AHI + d, Ahi + aoff);
            cp16(base + G_ALO + d, Alo + aoff);
            cp16(base + G_BHI + d, Bhi + boff);
            cp16(base + G_BLO + d, Blo + boff);
        }
        CP_COMMIT();
    };

    load_chunk(0, 0);

    for (int kc = 0; kc < nchunks; kc++) {
        const int st = kc & 1;
        if (kc + 1 < nchunks) { load_chunk(kc + 1, st ^ 1); CP_WAIT1(); }
        else                  { CP_WAIT0(); }
        __syncthreads();

        const uint32_t base = smb + (uint32_t)st * G_STAGE;
        #pragma unroll
        for (int ks = 0; ks < 4; ks++) {
            const uint32_t koff = (uint32_t)(ks * 32);
            uint32_t afr[4][4], bhi2[4][2], blo2[4][2];

            #pragma unroll
            for (int mt = 0; mt < 4; mt++)
                ldsm4(afr[mt], base + G_AHI + (uint32_t)(wm*64 + mt*16 + a_row)*GROW + koff + a_kb);
            #pragma unroll
            for (int g = 0; g < 2; g++) {
                uint32_t r4[4];
                ldsm4(r4, base + G_BHI + (uint32_t)(wn*32 + g*16 + b_row)*GROW + koff + b_kb);
                bhi2[g*2  ][0] = r4[0]; bhi2[g*2  ][1] = r4[1];
                bhi2[g*2+1][0] = r4[2]; bhi2[g*2+1][1] = r4[3];
            }
            #pragma unroll
            for (int mt = 0; mt < 4; mt++)
                #pragma unroll
                for (int nt = 0; nt < 4; nt++)
                    mma16816(acc[mt][nt], afr[mt], bhi2[nt]);

            #pragma unroll
            for (int g = 0; g < 2; g++) {
                uint32_t r4[4];
                ldsm4(r4, base + G_BLO + (uint32_t)(wn*32 + g*16 + b_row)*GROW + koff + b_kb);
                blo2[g*2  ][0] = r4[0]; blo2[g*2  ][1] = r4[1];
                blo2[g*2+1][0] = r4[2]; blo2[g*2+1][1] = r4[3];
            }
            #pragma unroll
            for (int mt = 0; mt < 4; mt++)
                #pragma unroll
                for (int nt = 0; nt < 4; nt++)
                    mma16816(acc[mt][nt], afr[mt], blo2[nt]);

            #pragma unroll
            for (int mt = 0; mt < 4; mt++)
                ldsm4(afr[mt], base + G_ALO + (uint32_t)(wm*64 + mt*16 + a_row)*GROW + koff + a_kb);
            #pragma unroll
            for (int mt = 0; mt < 4; mt++)
                #pragma unroll
                for (int nt = 0; nt < 4; nt++)
                    mma16816(acc[mt][nt], afr[mt], bhi2[nt]);
        }
        __syncthreads();
    }

    const int r_in = lane >> 2;
    const int c_in = (lane & 3) * 2;
    #pragma unroll
    for (int mt = 0; mt < 4; mt++) {
        #pragma unroll
        for (int nt = 0; nt < 4; nt++) {
            int col = n0 + wn * 32 + nt * 8 + c_in;
            float b0 = bias[col], b1 = bias[col + 1];
            int row0 = m0 + wm * 64 + mt * 16 + r_in;
            float v00 = acc[mt][nt][0] + b0, v01 = acc[mt][nt][1] + b1;
            float v10 = acc[mt][nt][2] + b0, v11 = acc[mt][nt][3] + b1;
            if (RELU) {
                v00 = fmaxf(v00, 0.f); v01 = fmaxf(v01, 0.f);
                v10 = fmaxf(v10, 0.f); v11 = fmaxf(v11, 0.f);
            }
            if (OUTM == 0) {
                float2 p0, p1;
                p0.x = v00; p0.y = v01; p1.x = v10; p1.y = v11;
                *(float2*)&C[(size_t)row0 * N + col] = p0;
                *(float2*)&C[(size_t)(row0 + 8) * N + col] = p1;
            } else {
                uint32_t lo0, lo1;
                uint32_t hi0 = pack_hi2(v00, v01, lo0);
                uint32_t hi1 = pack_hi2(v10, v11, lo1);
                *(uint32_t*)&Chi[(size_t)row0 * N + col] = hi0;
                *(uint32_t*)&Clo[(size_t)row0 * N + col] = lo0;
                *(uint32_t*)&Chi[(size_t)(row0 + 8) * N + col] = hi1;
                *(uint32_t*)&Clo[(size_t)(row0 + 8) * N + col] = lo1;
            }
        }
    }
}

// ==================== persistent GRU kernel v2 ==============================
// 128 CTAs (8 b-tiles x 16 k-tiles) x 256 threads, all 512 steps.
// 8 warps: wm (M half of 16), wn (N half of 24), wk (K half of 128) —
// K-split halves MMA latency; partials summed in gate phase.
// Barrier: bar.sync -> tid0 st.release.gpu -> per-thread spin (no bar in loop)
// -> bar.sync.  gi[t+1] prefetched into regs before the wait.
#define U_WHI 0
#define U_WLO 25344            // 48*528
#define U_HHI 50688
#define U_HLO 67584            // 32*528
#define U_GH0 84480            // 32*49*4 = 6272
#define U_GH1 90752
#define U_SM_TOTAL 97024
#define USTRIDE 528

__global__ void __launch_bounds__(256, 1) gru_persist(
    const float* __restrict__ GI_,
    const __nv_bfloat16* __restrict__ whh_hi,
    const __nv_bfloat16* __restrict__ whh_lo,
    const float* __restrict__ bhh,
    __nv_bfloat16* __restrict__ HHI_,
    __nv_bfloat16* __restrict__ HLO_,
    unsigned int* __restrict__ flags)
{
    extern __shared__ char sm[];
    const uint32_t smb = smem_u32(sm);
    float* GH0 = (float*)(sm + U_GH0);
    float* GH1 = (float*)(sm + U_GH1);
    const int tid = threadIdx.x;
    const int lane = tid & 31;
    const int wid = tid >> 5;
    const int wm = wid & 1;
    const int wn = (wid >> 1) & 1;
    const int wk = wid >> 2;          // 0..1: K half
    const int cta = blockIdx.x;
    const int b0 = (cta & 7) * 32;
    const int k0 = (cta >> 3) * 16;

    // ---- load W slice once (48 rows hi+lo) ----
    for (int i = tid; i < 1536; i += 256) {
        int j = i >> 5;
        int c = i & 31;
        int g = j >> 4, jr = j & 15;
        size_t soff = (size_t)(g * 256 + k0 + jr) * 256 + c * 8;
        uint32_t d = (uint32_t)(j * USTRIDE + c * 16);
        cp16(smb + U_WHI + d, whh_hi + soff);
        cp16(smb + U_WLO + d, whh_lo + soff);
    }
    CP_COMMIT();

    // zero both GH partial buffers (t=0 uses them as gh=0)
    for (int i = tid; i < 32 * 49; i += 256) { GH0[i] = 0.f; GH1[i] = 0.f; }

    // ---- per-thread gate constants (2 outputs each) ----
    int bloc[2], kloc[2];
    size_t off_o[2], gio[2];
    float brr[2], brz[2], brn[2];
    float hp[2];
    #pragma unroll
    for (int i = 0; i < 2; i++) {
        int idx = tid + 256 * i;
        int b = idx >> 4, ko = idx & 15;
        bloc[i] = b; kloc[i] = ko;
        int kg = k0 + ko, bg = b0 + b;
        off_o[i] = (size_t)bg * 256 + kg;
        gio[i] = (size_t)bg * 768 + kg;
        brr[i] = bhh[kg];
        brz[i] = bhh[256 + kg];
        brn[i] = bhh[512 + kg];
        hp[i] = 0.f;
    }

    // ---- mma addressing (identical fragment layout to R4/R5, + wk offset) --
    const uint32_t a_row = (uint32_t)(lane & 15);
    const uint32_t a_kb  = (uint32_t)((lane >> 4) * 16);
    const uint32_t b_row = (uint32_t)(((lane >> 4) & 1) * 8 + (lane & 7));
    const uint32_t b_kb  = (uint32_t)(((lane >> 3) & 1) * 16);
    const uint32_t b2_row = (uint32_t)(lane & 7);
    const uint32_t b2_kb  = (uint32_t)(((lane >> 3) & 1) * 16);
    const uint32_t kofs = (uint32_t)(wk * 256);   // K-half byte offset (128 bf16)

    const uint32_t aBaseHi  = smb + U_HHI + (uint32_t)(wm * 16 + a_row) * USTRIDE + a_kb + kofs;
    const uint32_t aBaseLo  = smb + U_HLO + (uint32_t)(wm * 16 + a_row) * USTRIDE + a_kb + kofs;
    const uint32_t bBaseHi4 = smb + U_WHI + (uint32_t)(wn * 24 + b_row) * USTRIDE + b_kb + kofs;
    const uint32_t bBaseLo4 = smb + U_WLO + (uint32_t)(wn * 24 + b_row) * USTRIDE + b_kb + kofs;
    const uint32_t bBaseHi2 = smb + U_WHI + (uint32_t)(wn * 24 + 16 + b2_row) * USTRIDE + b2_kb + kofs;
    const uint32_t bBaseLo2 = smb + U_WLO + (uint32_t)(wn * 24 + 16 + b2_row) * USTRIDE + b2_kb + kofs;
    float* GHw = wk ? GH1 : GH0;

    CP_WAIT0();
    __syncthreads();

    unsigned int* myflag = flags + cta;
    unsigned int* pollflag = flags + (tid & (NCTA - 1));

    // prefetch gi for t=0
    float ir[2], iz[2], in_[2];
    #pragma unroll
    for (int i = 0; i < 2; i++) {
        ir[i]  = __ldg(GI_ + gio[i]);
        iz[i]  = __ldg(GI_ + gio[i] + 256);
        in_[i] = __ldg(GI_ + gio[i] + 512);
    }

    for (int t = 0; t < TT; t++) {
        if (t > 0) {
            // ---- load h_prev tile (hi/lo) ----
            const __nv_bfloat16* hph = HHI_ + (size_t)(t - 1) * (BB * HH);
            const __nv_bfloat16* hpl = HLO_ + (size_t)(t - 1) * (BB * HH);
            #pragma unroll
            for (int i = 0; i < 4; i++) {
                int idx = tid + 256 * i;      // 0..1023
                int r = idx >> 5;
                int c = idx & 31;
                size_t soff = (size_t)(b0 + r) * 256 + c * 8;
                uint32_t d = (uint32_t)(r * USTRIDE + c * 16);
                cp16(smb + U_HHI + d, hph + soff);
                cp16(smb + U_HLO + d, hpl + soff);
            }
            CP_COMMIT();
            CP_WAIT0();
            __syncthreads();

            // ---- mma: M32 x N48 x (K128 per warp-pair), 3-term split ----
            float acc[3][4];
            #pragma unroll
            for (int i = 0; i < 3; i++)
                #pragma unroll
                for (int e = 0; e < 4; e++) acc[i][e] = 0.f;

            #pragma unroll
            for (int ks = 0; ks < 8; ks++) {
                const uint32_t koff = (uint32_t)(ks * 32);
                uint32_t a[4], bh[3][2], bl[3][2], r4[4];

                ldsm4(a, aBaseHi + koff);
                ldsm4(r4, bBaseHi4 + koff);
                bh[0][0] = r4[0]; bh[0][1] = r4[1]; bh[1][0] = r4[2]; bh[1][1] = r4[3];
                ldsm2(bh[2], bBaseHi2 + koff);
                #pragma unroll
                for (int nt = 0; nt < 3; nt++) mma16816(acc[nt], a, bh[nt]);

                ldsm4(r4, bBaseLo4 + koff);
                bl[0][0] = r4[0]; bl[0][1] = r4[1]; bl[1][0] = r4[2]; bl[1][1] = r4[3];
                ldsm2(bl[2], bBaseLo2 + koff);
                #pragma unroll
                for (int nt = 0; nt < 3; nt++) mma16816(acc[nt], a, bl[nt]);

                ldsm4(a, aBaseLo + koff);
                #pragma unroll
                for (int nt = 0; nt < 3; nt++) mma16816(acc[nt], a, bh[nt]);
            }

            // ---- store gh partials ----
            {
                const int r0 = lane >> 2;
                const int cc = (lane & 3) * 2;
                #pragma unroll
                for (int nt = 0; nt < 3; nt++) {
                    int col = wn * 24 + nt * 8 + cc;
                    GHw[(wm * 16 + r0) * 49 + col]         = acc[nt][0];
                    GHw[(wm * 16 + r0) * 49 + col + 1]     = acc[nt][1];
                    GHw[(wm * 16 + r0 + 8) * 49 + col]     = acc[nt][2];
                    GHw[(wm * 16 + r0 + 8) * 49 + col + 1] = acc[nt][3];
                }
            }
            __syncthreads();
        }

        // ---- gates: 2 outputs per thread ----
        __nv_bfloat16* hoh = HHI_ + (size_t)t * (BB * HH);
        __nv_bfloat16* hol = HLO_ + (size_t)t * (BB * HH);
        #pragma unroll
        for (int i = 0; i < 2; i++) {
            int b = bloc[i], ko = kloc[i];
            float hr = GH0[b * 49 + ko]      + GH1[b * 49 + ko]      + brr[i];
            float hz = GH0[b * 49 + 16 + ko] + GH1[b * 49 + 16 + ko] + brz[i];
            float hn = GH0[b * 49 + 32 + ko] + GH1[b * 49 + 32 + ko] + brn[i];

            float r = 1.f / (1.f + __expf(-(ir[i] + hr)));
            float z = 1.f / (1.f + __expf(-(iz[i] + hz)));
            float n = tanhf(in_[i] + r * hn);
            float hnew = (1.f - z) * n + z * hp[i];
            hp[i] = hnew;

            __nv_bfloat16 hh = __float2bfloat16(hnew);
            hoh[off_o[i]] = hh;
            hol[off_o[i]] = __float2bfloat16(hnew - __bfloat162float(hh));
        }

        // ---- prefetch gi[t+1] (overlaps the barrier wait) ----
        if (t + 1 < TT) {
            const float* gin = GI_ + (size_t)(t + 1) * (BB * 768);
            #pragma unroll
            for (int i = 0; i < 2; i++) {
                ir[i]  = __ldg(gin + gio[i]);
                iz[i]  = __ldg(gin + gio[i] + 256);
                in_[i] = __ldg(gin + gio[i] + 512);
            }
        }

        // ---- grid barrier (CG-style: bar, release, spin, bar) ----
        __syncthreads();
        if (tid == 0) {
            asm volatile("st.release.gpu.u32 [%0], %1;"
                :: "l"(myflag), "r"((unsigned int)(t + 1)) : "memory");
        }
        if (tid < NCTA) {
            const unsigned int target = (unsigned int)(t + 1);
            unsigned int v;
            do {
                asm volatile("ld.acquire.gpu.u32 %0, [%1];"
                    : "=r"(v) : "l"(pollflag) : "memory");
            } while (v < target);
        }
        __syncthreads();
    }
}

// -------------------- fc2b head -------------------------------------------
__global__ void __launch_bounds__(256, 2) head_gemm(
    const float* __restrict__ A,
    const float* __restrict__ Wb,
    const float* __restrict__ bias,
    float* __restrict__ out, int M)
{
    __shared__ float Ws[18][512];
    const int tid = threadIdx.x;
    #pragma unroll
    for (int i = 0; i < 9; i++) {
        int idx = tid + 256 * i;
        ((float4*)&Ws[0][0])[idx] = ((const float4*)Wb)[idx];
    }
    __syncthreads();

    const size_t mbase = (size_t)blockIdx.x * 1024 + tid;

    float acc[4][18];
    #pragma unroll
    for (int i = 0; i < 4; i++)
        #pragma unroll
        for (int j = 0; j < 18; j++) acc[i][j] = 0.f;

    for (int k4 = 0; k4 < 128; k4++) {
        float4 a[4];
        #pragma unroll
        for (int i = 0; i < 4; i++)
            a[i] = *(const float4*)&A[(mbase + 256 * i) * 512 + k4 * 4];
        #pragma unroll
        for (int j = 0; j < 18; j++) {
            float4 w = *(const float4*)&Ws[j][k4 * 4];
            #pragma unroll
            for (int i = 0; i < 4; i++) {
                acc[i][j] += a[i].x * w.x;
                acc[i][j] += a[i].y * w.y;
                acc[i][j] += a[i].z * w.z;
                acc[i][j] += a[i].w * w.w;
            }
        }
    }

    #pragma unroll
    for (int i = 0; i < 4; i++) {
        size_t row = mbase + 256 * i;
        #pragma unroll
        for (int j = 0; j < 18; j++)
            out[row * 18 + j] = acc[i][j] + bias[j];
    }
}

// -------------------- launch ------------------------------------------------
extern "C" void kernel_launch(void* const* d_in, const int* in_sizes, int n_in,
                              void* d_out, int out_size)
{
    (void)in_sizes; (void)n_in; (void)out_size;
    const float* x    = (const float*)d_in[0];
    const float* W1a  = (const float*)d_in[1];
    const float* b1a  = (const float*)d_in[2];
    const float* W1b  = (const float*)d_in[3];
    const float* b1b  = (const float*)d_in[4];
    const float* Wih  = (const float*)d_in[5];
    const float* bih  = (const float*)d_in[6];
    const float* Whh  = (const float*)d_in[7];
    const float* bhh  = (const float*)d_in[8];
    const float* W2a  = (const float*)d_in[9];
    const float* b2a  = (const float*)d_in[10];
    const float* W2b  = (const float*)d_in[11];
    const float* b2b  = (const float*)d_in[12];
    float* out = (float*)d_out;

    float *buf1, *GI;
    __nv_bfloat16 *XHI, *XLO, *A1HI, *A1LO, *A2HI, *A2LO, *HHI, *HLO;
    __nv_bfloat16 *W1AHI, *W1ALO, *W1BHI, *W1BLO, *WIHHI, *WIHLO, *W2AHI, *W2ALO, *WHHHI, *WHHLO;
    unsigned int* FLAGS;

    cudaGetSymbolAddress((void**)&buf1, d_buf1);
    cudaGetSymbolAddress((void**)&GI,   d_GI);
    cudaGetSymbolAddress((void**)&XHI,  d_XHI);  cudaGetSymbolAddress((void**)&XLO,  d_XLO);
    cudaGetSymbolAddress((void**)&A1HI, d_A1HI); cudaGetSymbolAddress((void**)&A1LO, d_A1LO);
    cudaGetSymbolAddress((void**)&A2HI, d_A2HI); cudaGetSymbolAddress((void**)&A2LO, d_A2LO);
    cudaGetSymbolAddress((void**)&HHI,  d_HHI);  cudaGetSymbolAddress((void**)&HLO,  d_HLO);
    cudaGetSymbolAddress((void**)&W1AHI, d_W1AHI); cudaGetSymbolAddress((void**)&W1ALO, d_W1ALO);
    cudaGetSymbolAddress((void**)&W1BHI, d_W1BHI); cudaGetSymbolAddress((void**)&W1BLO, d_W1BLO);
    cudaGetSymbolAddress((void**)&WIHHI, d_WIHHI); cudaGetSymbolAddress((void**)&WIHLO, d_WIHLO);
    cudaGetSymbolAddress((void**)&W2AHI, d_W2AHI); cudaGetSymbolAddress((void**)&W2ALO, d_W2ALO);
    cudaGetSymbolAddress((void**)&WHHHI, d_WHHHI); cudaGetSymbolAddress((void**)&WHHLO, d_WHHLO);
    cudaGetSymbolAddress((void**)&FLAGS, d_flags);

    cudaFuncSetAttribute(gemm_bf<true, 0>,  cudaFuncAttributeMaxDynamicSharedMemorySize, G_SM_TOTAL);
    cudaFuncSetAttribute(gemm_bf<true, 1>,  cudaFuncAttributeMaxDynamicSharedMemorySize, G_SM_TOTAL);
    cudaFuncSetAttribute(gemm_bf<false, 0>, cudaFuncAttributeMaxDynamicSharedMemorySize, G_SM_TOTAL);
    cudaFuncSetAttribute(gru_persist, cudaFuncAttributeMaxDynamicSharedMemorySize, U_SM_TOTAL);

    const int M = MTOT;

    // ---- pre-split inputs/weights to bf16 hi/lo ----
    split_f32<<<(M * 256 / 4 + 255) / 256, 256>>>((const float4*)x, (uint2*)XHI, (uint2*)XLO, M * 256 / 4);
    split_f32<<<128, 256>>>((const float4*)W1a, (uint2*)W1AHI, (uint2*)W1ALO, 512 * 256 / 4);
    split_f32<<<128, 256>>>((const float4*)W1b, (uint2*)W1BHI, (uint2*)W1BLO, 256 * 512 / 4);
    split_f32<<<192, 256>>>((const float4*)Wih, (uint2*)WIHHI, (uint2*)WIHLO, 768 * 256 / 4);
    split_f32<<<128, 256>>>((const float4*)W2a, (uint2*)W2AHI, (uint2*)W2ALO, 512 * 256 / 4);
    split_f32<<<192, 256>>>((const float4*)Whh, (uint2*)WHHHI, (uint2*)WHHLO, 768 * 256 / 4);

    zero_u32<<<1, NCTA>>>(FLAGS, NCTA);

    // ---- batched GEMMs ----
    gemm_bf<true, 1><<<dim3(4, M / 128), 256, G_SM_TOTAL>>>(
        XHI, XLO, W1AHI, W1ALO, b1a, nullptr, A1HI, A1LO, M, 512, 256);
    gemm_bf<true, 1><<<dim3(2, M / 128), 256, G_SM_TOTAL>>>(
        A1HI, A1LO, W1BHI, W1BLO, b1b, nullptr, A2HI, A2LO, M, 256, 512);
    gemm_bf<false, 0><<<dim3(6, M / 128), 256, G_SM_TOTAL>>>(
        A2HI, A2LO, WIHHI, WIHLO, bih, GI, nullptr, nullptr, M, 768, 256);

    // ---- persistent GRU ----
    gru_persist<<<NCTA, 256, U_SM_TOTAL>>>(GI, WHHHI, WHHLO, bhh, HHI, HLO, FLAGS);

    // fc2a + head
    gemm_bf<true, 0><<<dim3(4, M / 128), 256, G_SM_TOTAL>>>(
        HHI, HLO, W2AHI, W2ALO, b2a, buf1, nullptr, nullptr, M, 512, 256);
    head_gemm<<<M / 1024, 256>>>(buf1, W2b, b2b, out, M);
}

// round 8
// speedup vs baseline: 1.0929x; 1.0929x over previous
#include <cuda_runtime.h>
#include <cuda_bf16.h>
#include <math.h>
#include <stdint.h>

// Problem constants
#define TT 512
#define BB 256
#define IN_DIM 256
#define H1 512
#define HH 256
#define OUT_DIM 18
#define MTOT (TT*BB)   // 131072
#define NCTA 128
#define GRP 8          // CTAs per sync group (share one b-tile)

// -------------------- scratch (static device globals; no allocs) -----------
__device__ float d_buf1[(size_t)MTOT * 512];     // fc2a out (fp32, for head)
__device__ float d_GI  [(size_t)MTOT * 768];     // gi fp32

__device__ __nv_bfloat16 d_XHI[(size_t)MTOT * 256], d_XLO[(size_t)MTOT * 256];
__device__ __nv_bfloat16 d_A1HI[(size_t)MTOT * 512], d_A1LO[(size_t)MTOT * 512];
__device__ __nv_bfloat16 d_A2HI[(size_t)MTOT * 256], d_A2LO[(size_t)MTOT * 256];
__device__ __nv_bfloat16 d_HHI[(size_t)MTOT * 256], d_HLO[(size_t)MTOT * 256];

__device__ __nv_bfloat16 d_W1AHI[512*256], d_W1ALO[512*256];
__device__ __nv_bfloat16 d_W1BHI[256*512], d_W1BLO[256*512];
__device__ __nv_bfloat16 d_WIHHI[768*256], d_WIHLO[768*256];
__device__ __nv_bfloat16 d_W2AHI[512*256], d_W2ALO[512*256];
__device__ __nv_bfloat16 d_WHHHI[768*256], d_WHHLO[768*256];

__device__ unsigned int d_flags[NCTA];           // group barrier flags

// ==================== helpers ==============================================
__device__ __forceinline__ uint32_t smem_u32(const void* p) {
    uint32_t a;
    asm("{ .reg .u64 t; cvta.to.shared.u64 t, %1; cvt.u32.u64 %0, t; }"
        : "=r"(a) : "l"(p));
    return a;
}

__device__ __forceinline__ void ldsm4(uint32_t* r, uint32_t addr) {
    asm volatile("ldmatrix.sync.aligned.m8n8.x4.shared.b16 {%0,%1,%2,%3}, [%4];"
        : "=r"(r[0]), "=r"(r[1]), "=r"(r[2]), "=r"(r[3]) : "r"(addr));
}
__device__ __forceinline__ void ldsm2(uint32_t* r, uint32_t addr) {
    asm volatile("ldmatrix.sync.aligned.m8n8.x2.shared.b16 {%0,%1}, [%2];"
        : "=r"(r[0]), "=r"(r[1]) : "r"(addr));
}

__device__ __forceinline__ void mma16816(float* c, const uint32_t* a, const uint32_t* b) {
    asm volatile(
        "mma.sync.aligned.m16n8k16.row.col.f32.bf16.bf16.f32 "
        "{%0,%1,%2,%3}, {%4,%5,%6,%7}, {%8,%9}, {%0,%1,%2,%3};"
        : "+f"(c[0]), "+f"(c[1]), "+f"(c[2]), "+f"(c[3])
        : "r"(a[0]), "r"(a[1]), "r"(a[2]), "r"(a[3]), "r"(b[0]), "r"(b[1]));
}

__device__ __forceinline__ void cp16(uint32_t dst, const void* src) {
    asm volatile("cp.async.cg.shared.global [%0], [%1], 16;"
        :: "r"(dst), "l"(src) : "memory");
}
#define CP_COMMIT() asm volatile("cp.async.commit_group;" ::: "memory")
#define CP_WAIT0()  asm volatile("cp.async.wait_group 0;" ::: "memory")
#define CP_WAIT1()  asm volatile("cp.async.wait_group 1;" ::: "memory")

__device__ __forceinline__ void split_bf16x4(float4 v, uint2& hv, uint2& lv) {
    __nv_bfloat16 h0 = __float2bfloat16(v.x);
    __nv_bfloat16 h1 = __float2bfloat16(v.y);
    __nv_bfloat16 h2 = __float2bfloat16(v.z);
    __nv_bfloat16 h3 = __float2bfloat16(v.w);
    __nv_bfloat16 l0 = __float2bfloat16(v.x - __bfloat162float(h0));
    __nv_bfloat16 l1 = __float2bfloat16(v.y - __bfloat162float(h1));
    __nv_bfloat16 l2 = __float2bfloat16(v.z - __bfloat162float(h2));
    __nv_bfloat16 l3 = __float2bfloat16(v.w - __bfloat162float(h3));
    hv.x = (uint32_t)__bfloat16_as_ushort(h0) | ((uint32_t)__bfloat16_as_ushort(h1) << 16);
    hv.y = (uint32_t)__bfloat16_as_ushort(h2) | ((uint32_t)__bfloat16_as_ushort(h3) << 16);
    lv.x = (uint32_t)__bfloat16_as_ushort(l0) | ((uint32_t)__bfloat16_as_ushort(l1) << 16);
    lv.y = (uint32_t)__bfloat16_as_ushort(l2) | ((uint32_t)__bfloat16_as_ushort(l3) << 16);
}

__device__ __forceinline__ uint32_t pack_hi2(float a, float b, uint32_t& lo) {
    __nv_bfloat16 ha = __float2bfloat16(a);
    __nv_bfloat16 hb = __float2bfloat16(b);
    __nv_bfloat16 la = __float2bfloat16(a - __bfloat162float(ha));
    __nv_bfloat16 lb = __float2bfloat16(b - __bfloat162float(hb));
    lo = (uint32_t)__bfloat16_as_ushort(la) | ((uint32_t)__bfloat16_as_ushort(lb) << 16);
    return (uint32_t)__bfloat16_as_ushort(ha) | ((uint32_t)__bfloat16_as_ushort(hb) << 16);
}

// -------------------- split / zero kernels ---------------------------------
__global__ void split_f32(const float4* __restrict__ in,
                          uint2* __restrict__ hi, uint2* __restrict__ lo, int n4) {
    int i = blockIdx.x * blockDim.x + threadIdx.x;
    if (i < n4) {
        uint2 h, l;
        split_bf16x4(in[i], h, l);
        hi[i] = h; lo[i] = l;
    }
}
__global__ void zero_u32(uint32_t* p, int n) {
    int i = blockIdx.x * blockDim.x + threadIdx.x;
    if (i < n) p[i] = 0u;
}

// ==================== pipelined bf16-split GEMM (unchanged, passing) ========
#define GROW 144
#define G_AHI 0
#define G_ALO 18432
#define G_BHI 36864
#define G_BLO 55296
#define G_STAGE 73728
#define G_SM_TOTAL (2*G_STAGE)

template<bool RELU, int OUTM>
__global__ void __launch_bounds__(256, 1) gemm_bf(
    const __nv_bfloat16* __restrict__ Ahi, const __nv_bfloat16* __restrict__ Alo,
    const __nv_bfloat16* __restrict__ Bhi, const __nv_bfloat16* __restrict__ Blo,
    const float* __restrict__ bias,
    float* __restrict__ C, __nv_bfloat16* __restrict__ Chi, __nv_bfloat16* __restrict__ Clo,
    int M, int N, int K)
{
    extern __shared__ char sm[];
    const uint32_t smb = smem_u32(sm);
    const int tid = threadIdx.x;
    const int lane = tid & 31;
    const int wid = tid >> 5;
    const int wm = wid & 1;
    const int wn = wid >> 1;
    const int m0 = blockIdx.y * 128;
    const int n0 = blockIdx.x * 128;

    float acc[4][4][4];
    #pragma unroll
    for (int i = 0; i < 4; i++)
        #pragma unroll
        for (int j = 0; j < 4; j++)
            #pragma unroll
            for (int e = 0; e < 4; e++) acc[i][j][e] = 0.f;

    const uint32_t a_row = (uint32_t)(lane & 15);
    const uint32_t a_kb  = (uint32_t)((lane >> 4) * 16);
    const uint32_t b_row = (uint32_t)(((lane >> 4) & 1) * 8 + (lane & 7));
    const uint32_t b_kb  = (uint32_t)(((lane >> 3) & 1) * 16);

    const int nchunks = K >> 6;

    auto load_chunk = [&](int kc, int st) {
        const int kb = kc << 6;
        const uint32_t base = smb + (uint32_t)st * G_STAGE;
        #pragma unroll
        for (int j = 0; j < 4; j++) {
            int idx = tid + 256 * j;
            int r = idx >> 3;
            int c = idx & 7;
            size_t aoff = (size_t)(m0 + r) * K + kb + c * 8;
            size_t boff = (size_t)(n0 + r) * K + kb + c * 8;
            uint32_t d = (uint32_t)(r * GROW + c * 16);
            cp16(base + G_AHI + d, Ahi + aoff);
            cp16(base + G_ALO + d, Alo + aoff);
            cp16(base + G_BHI + d, Bhi + boff);
            cp16(base + G_BLO + d, Blo + boff);
        }
        CP_COMMIT();
    };

    load_chunk(0, 0);

    for (int kc = 0; kc < nchunks; kc++) {
        const int st = kc & 1;
        if (kc + 1 < nchunks) { load_chunk(kc + 1, st ^ 1); CP_WAIT1(); }
        else                  { CP_WAIT0(); }
        __syncthreads();

        const uint32_t base = smb + (uint32_t)st * G_STAGE;
        #pragma unroll
        for (int ks = 0; ks < 4; ks++) {
            const uint32_t koff = (uint32_t)(ks * 32);
            uint32_t afr[4][4], bhi2[4][2], blo2[4][2];

            #pragma unroll
            for (int mt = 0; mt < 4; mt++)
                ldsm4(afr[mt], base + G_AHI + (uint32_t)(wm*64 + mt*16 + a_row)*GROW + koff + a_kb);
            #pragma unroll
            for (int g = 0; g < 2; g++) {
                uint32_t r4[4];
                ldsm4(r4, base + G_BHI + (uint32_t)(wn*32 + g*16 + b_row)*GROW + koff + b_kb);
                bhi2[g*2  ][0] = r4[0]; bhi2[g*2  ][1] = r4[1];
                bhi2[g*2+1][0] = r4[2]; bhi2[g*2+1][1] = r4[3];
            }
            #pragma unroll
            for (int mt = 0; mt < 4; mt++)
                #pragma unroll
                for (int nt = 0; nt < 4; nt++)
                    mma16816(acc[mt][nt], afr[mt], bhi2[nt]);

            #pragma unroll
            for (int g = 0; g < 2; g++) {
                uint32_t r4[4];
                ldsm4(r4, base + G_BLO + (uint32_t)(wn*32 + g*16 + b_row)*GROW + koff + b_kb);
                blo2[g*2  ][0] = r4[0]; blo2[g*2  ][1] = r4[1];
                blo2[g*2+1][0] = r4[2]; blo2[g*2+1][1] = r4[3];
            }
            #pragma unroll
            for (int mt = 0; mt < 4; mt++)
                #pragma unroll
                for (int nt = 0; nt < 4; nt++)
                    mma16816(acc[mt][nt], afr[mt], blo2[nt]);

            #pragma unroll
            for (int mt = 0; mt < 4; mt++)
                ldsm4(afr[mt], base + G_ALO + (uint32_t)(wm*64 + mt*16 + a_row)*GROW + koff + a_kb);
            #pragma unroll
            for (int mt = 0; mt < 4; mt++)
                #pragma unroll
                for (int nt = 0; nt < 4; nt++)
                    mma16816(acc[mt][nt], afr[mt], bhi2[nt]);
        }
        __syncthreads();
    }

    const int r_in = lane >> 2;
    const int c_in = (lane & 3) * 2;
    #pragma unroll
    for (int mt = 0; mt < 4; mt++) {
        #pragma unroll
        for (int nt = 0; nt < 4; nt++) {
            int col = n0 + wn * 32 + nt * 8 + c_in;
            float b0 = bias[col], b1 = bias[col + 1];
            int row0 = m0 + wm * 64 + mt * 16 + r_in;
            float v00 = acc[mt][nt][0] + b0, v01 = acc[mt][nt][1] + b1;
            float v10 = acc[mt][nt][2] + b0, v11 = acc[mt][nt][3] + b1;
            if (RELU) {
                v00 = fmaxf(v00, 0.f); v01 = fmaxf(v01, 0.f);
                v10 = fmaxf(v10, 0.f); v11 = fmaxf(v11, 0.f);
            }
            if (OUTM == 0) {
                float2 p0, p1;
                p0.x = v00; p0.y = v01; p1.x = v10; p1.y = v11;
                *(float2*)&C[(size_t)row0 * N + col] = p0;
                *(float2*)&C[(size_t)(row0 + 8) * N + col] = p1;
            } else {
                uint32_t lo0, lo1;
                uint32_t hi0 = pack_hi2(v00, v01, lo0);
                uint32_t hi1 = pack_hi2(v10, v11, lo1);
                *(uint32_t*)&Chi[(size_t)row0 * N + col] = hi0;
                *(uint32_t*)&Clo[(size_t)row0 * N + col] = lo0;
                *(uint32_t*)&Chi[(size_t)(row0 + 8) * N + col] = hi1;
                *(uint32_t*)&Clo[(size_t)(row0 + 8) * N + col] = lo1;
            }
        }
    }
}

// ==================== persistent GRU v3: group-local sync ===================
// 16 independent groups x 8 CTAs. Group g owns b-tile [g*16, g*16+16) for ALL
// steps; CTA kq in group owns k-slice [kq*32, kq*32+32) (96 W rows in smem).
// Only CTAs within a group synchronize (8 flags); groups drift freely.
// 256 threads = 8 warps: wk (K half) x wn (N quarter of 96).
#define U_WHI 0
#define U_WLO 50688            // 96*528
#define U_HHI 101376           // 16*528 = 8448
#define U_HLO 109824
#define U_GH0 118272           // 16*97*4 = 6208
#define U_GH1 124480
#define U_SM_TOTAL 130688
#define USTRIDE 528

__global__ void __launch_bounds__(256, 1) gru_persist(
    const float* __restrict__ GI_,
    const __nv_bfloat16* __restrict__ whh_hi,
    const __nv_bfloat16* __restrict__ whh_lo,
    const float* __restrict__ bhh,
    __nv_bfloat16* __restrict__ HHI_,
    __nv_bfloat16* __restrict__ HLO_,
    unsigned int* __restrict__ flags)
{
    extern __shared__ char sm[];
    const uint32_t smb = smem_u32(sm);
    float* GH0 = (float*)(sm + U_GH0);
    float* GH1 = (float*)(sm + U_GH1);
    const int tid = threadIdx.x;
    const int lane = tid & 31;
    const int wid = tid >> 5;
    const int wk = wid >> 2;          // 0..1: K half
    const int wn = wid & 3;           // 0..3: N quarter (24 cols)
    const int cta = blockIdx.x;
    const int grp = cta >> 3;         // 0..15
    const int kq  = cta & 7;          // 0..7
    const int b0 = grp * 16;
    const int k0 = kq * 32;

    // ---- load W slice once: 96 rows (3 gates x 32 k-offsets), hi+lo ----
    for (int i = tid; i < 3072; i += 256) {       // 96 rows x 32 x 16B
        int j = i >> 5;          // 0..95
        int c = i & 31;
        int gate = j >> 5, jr = j & 31;
        size_t soff = (size_t)(gate * 256 + k0 + jr) * 256 + c * 8;
        uint32_t d = (uint32_t)(j * USTRIDE + c * 16);
        cp16(smb + U_WHI + d, whh_hi + soff);
        cp16(smb + U_WLO + d, whh_lo + soff);
    }
    CP_COMMIT();

    // zero GH partial buffers (used as gh=0 at t=0)
    for (int i = tid; i < 16 * 97; i += 256) { GH0[i] = 0.f; GH1[i] = 0.f; }

    // ---- per-thread gate constants (2 outputs each: 512 outputs/CTA) ----
    size_t off_o[2], gio[2];
    int bloc[2], kloc[2];
    float brr[2], brz[2], brn[2], hp[2];
    #pragma unroll
    for (int i = 0; i < 2; i++) {
        int idx = tid + 256 * i;
        int b = idx >> 5, ko = idx & 31;
        bloc[i] = b; kloc[i] = ko;
        int kg = k0 + ko, bg = b0 + b;
        off_o[i] = (size_t)bg * 256 + kg;
        gio[i] = (size_t)bg * 768 + kg;
        brr[i] = bhh[kg];
        brz[i] = bhh[256 + kg];
        brn[i] = bhh[512 + kg];
        hp[i] = 0.f;
    }

    // ---- mma addressing ----
    const uint32_t a_row = (uint32_t)(lane & 15);
    const uint32_t a_kb  = (uint32_t)((lane >> 4) * 16);
    const uint32_t b_row = (uint32_t)(((lane >> 4) & 1) * 8 + (lane & 7));
    const uint32_t b_kb  = (uint32_t)(((lane >> 3) & 1) * 16);
    const uint32_t b2_row = (uint32_t)(lane & 7);
    const uint32_t b2_kb  = (uint32_t)(((lane >> 3) & 1) * 16);
    const uint32_t kofs = (uint32_t)(wk * 256);   // K-half byte offset

    const uint32_t aBaseHi  = smb + U_HHI + a_row * USTRIDE + a_kb + kofs;
    const uint32_t aBaseLo  = smb + U_HLO + a_row * USTRIDE + a_kb + kofs;
    const uint32_t bBaseHi4 = smb + U_WHI + (uint32_t)(wn * 24 + b_row) * USTRIDE + b_kb + kofs;
    const uint32_t bBaseLo4 = smb + U_WLO + (uint32_t)(wn * 24 + b_row) * USTRIDE + b_kb + kofs;
    const uint32_t bBaseHi2 = smb + U_WHI + (uint32_t)(wn * 24 + 16 + b2_row) * USTRIDE + b2_kb + kofs;
    const uint32_t bBaseLo2 = smb + U_WLO + (uint32_t)(wn * 24 + 16 + b2_row) * USTRIDE + b2_kb + kofs;
    float* GHw = wk ? GH1 : GH0;

    CP_WAIT0();
    __syncthreads();

    unsigned int* myflag = flags + cta;
    unsigned int* grpflags = flags + grp * GRP;

    // prefetch gi for t=0
    float ir[2], iz[2], in_[2];
    #pragma unroll
    for (int i = 0; i < 2; i++) {
        ir[i]  = __ldg(GI_ + gio[i]);
        iz[i]  = __ldg(GI_ + gio[i] + 256);
        in_[i] = __ldg(GI_ + gio[i] + 512);
    }

    for (int t = 0; t < TT; t++) {
        if (t > 0) {
            // ---- load h_prev tile 16 x 256 (hi/lo) ----
            const __nv_bfloat16* hph = HHI_ + (size_t)(t - 1) * (BB * HH);
            const __nv_bfloat16* hpl = HLO_ + (size_t)(t - 1) * (BB * HH);
            #pragma unroll
            for (int i = 0; i < 2; i++) {
                int idx = tid + 256 * i;      // 0..511
                int r = idx >> 5;             // 0..15
                int c = idx & 31;
                size_t soff = (size_t)(b0 + r) * 256 + c * 8;
                uint32_t d = (uint32_t)(r * USTRIDE + c * 16);
                cp16(smb + U_HHI + d, hph + soff);
                cp16(smb + U_HLO + d, hpl + soff);
            }
            CP_COMMIT();
            CP_WAIT0();
            __syncthreads();

            // ---- mma: M16 x N24(per warp) x K128(per k-half), 3 terms ----
            float acc[3][4];
            #pragma unroll
            for (int i = 0; i < 3; i++)
                #pragma unroll
                for (int e = 0; e < 4; e++) acc[i][e] = 0.f;

            #pragma unroll
            for (int ks = 0; ks < 8; ks++) {
                const uint32_t koff = (uint32_t)(ks * 32);
                uint32_t a[4], bh[3][2], bl[3][2], r4[4];

                ldsm4(a, aBaseHi + koff);
                ldsm4(r4, bBaseHi4 + koff);
                bh[0][0] = r4[0]; bh[0][1] = r4[1]; bh[1][0] = r4[2]; bh[1][1] = r4[3];
                ldsm2(bh[2], bBaseHi2 + koff);
                #pragma unroll
                for (int nt = 0; nt < 3; nt++) mma16816(acc[nt], a, bh[nt]);

                ldsm4(r4, bBaseLo4 + koff);
                bl[0][0] = r4[0]; bl[0][1] = r4[1]; bl[1][0] = r4[2]; bl[1][1] = r4[3];
                ldsm2(bl[2], bBaseLo2 + koff);
                #pragma unroll
                for (int nt = 0; nt < 3; nt++) mma16816(acc[nt], a, bl[nt]);

                ldsm4(a, aBaseLo + koff);
                #pragma unroll
                for (int nt = 0; nt < 3; nt++) mma16816(acc[nt], a, bh[nt]);
            }

            // ---- store gh partials (N col j = gate*32 + jr) ----
            {
                const int r0 = lane >> 2;
                const int cc = (lane & 3) * 2;
                #pragma unroll
                for (int nt = 0; nt < 3; nt++) {
                    int col = wn * 24 + nt * 8 + cc;
                    GHw[r0 * 97 + col]           = acc[nt][0];
                    GHw[r0 * 97 + col + 1]       = acc[nt][1];
                    GHw[(r0 + 8) * 97 + col]     = acc[nt][2];
                    GHw[(r0 + 8) * 97 + col + 1] = acc[nt][3];
                }
            }
            __syncthreads();
        }

        // ---- gates: 2 outputs per thread; gh col layout j = gate*32 + ko --
        __nv_bfloat16* hoh = HHI_ + (size_t)t * (BB * HH);
        __nv_bfloat16* hol = HLO_ + (size_t)t * (BB * HH);
        #pragma unroll
        for (int i = 0; i < 2; i++) {
            int b = bloc[i], ko = kloc[i];
            float hr = GH0[b * 97 + ko]      + GH1[b * 97 + ko]      + brr[i];
            float hz = GH0[b * 97 + 32 + ko] + GH1[b * 97 + 32 + ko] + brz[i];
            float hn = GH0[b * 97 + 64 + ko] + GH1[b * 97 + 64 + ko] + brn[i];

            float r = 1.f / (1.f + __expf(-(ir[i] + hr)));
            float z = 1.f / (1.f + __expf(-(iz[i] + hz)));
            float n = tanhf(in_[i] + r * hn);
            float hnew = (1.f - z) * n + z * hp[i];
            hp[i] = hnew;

            __nv_bfloat16 hh = __float2bfloat16(hnew);
            hoh[off_o[i]] = hh;
            hol[off_o[i]] = __float2bfloat16(hnew - __bfloat162float(hh));
        }

        // ---- prefetch gi[t+1] (overlaps wait) ----
        if (t + 1 < TT) {
            const float* gin = GI_ + (size_t)(t + 1) * (BB * 768);
            #pragma unroll
            for (int i = 0; i < 2; i++) {
                ir[i]  = __ldg(gin + gio[i]);
                iz[i]  = __ldg(gin + gio[i] + 256);
                in_[i] = __ldg(gin + gio[i] + 512);
            }

            // ---- group-local barrier ----
            __syncthreads();
            if (tid == 0) {
                asm volatile("st.release.gpu.u32 [%0], %1;"
                    :: "l"(myflag), "r"((unsigned int)(t + 1)) : "memory");
            }
            if (tid < GRP) {
                const unsigned int target = (unsigned int)(t + 1);
                unsigned int v;
                do {
                    asm volatile("ld.acquire.gpu.u32 %0, [%1];"
                        : "=r"(v) : "l"(grpflags + tid) : "memory");
                } while (v < target);
            }
            __syncthreads();
        }
    }
}

// -------------------- fc2b head -------------------------------------------
__global__ void __launch_bounds__(256, 2) head_gemm(
    const float* __restrict__ A,
    const float* __restrict__ Wb,
    const float* __restrict__ bias,
    float* __restrict__ out, int M)
{
    __shared__ float Ws[18][512];
    const int tid = threadIdx.x;
    #pragma unroll
    for (int i = 0; i < 9; i++) {
        int idx = tid + 256 * i;
        ((float4*)&Ws[0][0])[idx] = ((const float4*)Wb)[idx];
    }
    __syncthreads();

    const size_t mbase = (size_t)blockIdx.x * 1024 + tid;

    float acc[4][18];
    #pragma unroll
    for (int i = 0; i < 4; i++)
        #pragma unroll
        for (int j = 0; j < 18; j++) acc[i][j] = 0.f;

    for (int k4 = 0; k4 < 128; k4++) {
        float4 a[4];
        #pragma unroll
        for (int i = 0; i < 4; i++)
            a[i] = *(const float4*)&A[(mbase + 256 * i) * 512 + k4 * 4];
        #pragma unroll
        for (int j = 0; j < 18; j++) {
            float4 w = *(const float4*)&Ws[j][k4 * 4];
            #pragma unroll
            for (int i = 0; i < 4; i++) {
                acc[i][j] += a[i].x * w.x;
                acc[i][j] += a[i].y * w.y;
                acc[i][j] += a[i].z * w.z;
                acc[i][j] += a[i].w * w.w;
            }
        }
    }

    #pragma unroll
    for (int i = 0; i < 4; i++) {
        size_t row = mbase + 256 * i;
        #pragma unroll
        for (int j = 0; j < 18; j++)
            out[row * 18 + j] = acc[i][j] + bias[j];
    }
}

// -------------------- launch ------------------------------------------------
extern "C" void kernel_launch(void* const* d_in, const int* in_sizes, int n_in,
                              void* d_out, int out_size)
{
    (void)in_sizes; (void)n_in; (void)out_size;
    const float* x    = (const float*)d_in[0];
    const float* W1a  = (const float*)d_in[1];
    const float* b1a  = (const float*)d_in[2];
    const float* W1b  = (const float*)d_in[3];
    const float* b1b  = (const float*)d_in[4];
    const float* Wih  = (const float*)d_in[5];
    const float* bih  = (const float*)d_in[6];
    const float* Whh  = (const float*)d_in[7];
    const float* bhh  = (const float*)d_in[8];
    const float* W2a  = (const float*)d_in[9];
    const float* b2a  = (const float*)d_in[10];
    const float* W2b  = (const float*)d_in[11];
    const float* b2b  = (const float*)d_in[12];
    float* out = (float*)d_out;

    float *buf1, *GI;
    __nv_bfloat16 *XHI, *XLO, *A1HI, *A1LO, *A2HI, *A2LO, *HHI, *HLO;
    __nv_bfloat16 *W1AHI, *W1ALO, *W1BHI, *W1BLO, *WIHHI, *WIHLO, *W2AHI, *W2ALO, *WHHHI, *WHHLO;
    unsigned int* FLAGS;

    cudaGetSymbolAddress((void**)&buf1, d_buf1);
    cudaGetSymbolAddress((void**)&GI,   d_GI);
    cudaGetSymbolAddress((void**)&XHI,  d_XHI);  cudaGetSymbolAddress((void**)&XLO,  d_XLO);
    cudaGetSymbolAddress((void**)&A1HI, d_A1HI); cudaGetSymbolAddress((void**)&A1LO, d_A1LO);
    cudaGetSymbolAddress((void**)&A2HI, d_A2HI); cudaGetSymbolAddress((void**)&A2LO, d_A2LO);
    cudaGetSymbolAddress((void**)&HHI,  d_HHI);  cudaGetSymbolAddress((void**)&HLO,  d_HLO);
    cudaGetSymbolAddress((void**)&W1AHI, d_W1AHI); cudaGetSymbolAddress((void**)&W1ALO, d_W1ALO);
    cudaGetSymbolAddress((void**)&W1BHI, d_W1BHI); cudaGetSymbolAddress((void**)&W1BLO, d_W1BLO);
    cudaGetSymbolAddress((void**)&WIHHI, d_WIHHI); cudaGetSymbolAddress((void**)&WIHLO, d_WIHLO);
    cudaGetSymbolAddress((void**)&W2AHI, d_W2AHI); cudaGetSymbolAddress((void**)&W2ALO, d_W2ALO);
    cudaGetSymbolAddress((void**)&WHHHI, d_WHHHI); cudaGetSymbolAddress((void**)&WHHLO, d_WHHLO);
    cudaGetSymbolAddress((void**)&FLAGS, d_flags);

    cudaFuncSetAttribute(gemm_bf<true, 0>,  cudaFuncAttributeMaxDynamicSharedMemorySize, G_SM_TOTAL);
    cudaFuncSetAttribute(gemm_bf<true, 1>,  cudaFuncAttributeMaxDynamicSharedMemorySize, G_SM_TOTAL);
    cudaFuncSetAttribute(gemm_bf<false, 0>, cudaFuncAttributeMaxDynamicSharedMemorySize, G_SM_TOTAL);
    cudaFuncSetAttribute(gru_persist, cudaFuncAttributeMaxDynamicSharedMemorySize, U_SM_TOTAL);

    const int M = MTOT;

    // ---- pre-split inputs/weights to bf16 hi/lo ----
    split_f32<<<(M * 256 / 4 + 255) / 256, 256>>>((const float4*)x, (uint2*)XHI, (uint2*)XLO, M * 256 / 4);
    split_f32<<<128, 256>>>((const float4*)W1a, (uint2*)W1AHI, (uint2*)W1ALO, 512 * 256 / 4);
    split_f32<<<128, 256>>>((const float4*)W1b, (uint2*)W1BHI, (uint2*)W1BLO, 256 * 512 / 4);
    split_f32<<<192, 256>>>((const float4*)Wih, (uint2*)WIHHI, (uint2*)WIHLO, 768 * 256 / 4);
    split_f32<<<128, 256>>>((const float4*)W2a, (uint2*)W2AHI, (uint2*)W2ALO, 512 * 256 / 4);
    split_f32<<<192, 256>>>((const float4*)Whh, (uint2*)WHHHI, (uint2*)WHHLO, 768 * 256 / 4);

    zero_u32<<<1, NCTA>>>(FLAGS, NCTA);

    // ---- batched GEMMs ----
    gemm_bf<true, 1><<<dim3(4, M / 128), 256, G_SM_TOTAL>>>(
        XHI, XLO, W1AHI, W1ALO, b1a, nullptr, A1HI, A1LO, M, 512, 256);
    gemm_bf<true, 1><<<dim3(2, M / 128), 256, G_SM_TOTAL>>>(
        A1HI, A1LO, W1BHI, W1BLO, b1b, nullptr, A2HI, A2LO, M, 256, 512);
    gemm_bf<false, 0><<<dim3(6, M / 128), 256, G_SM_TOTAL>>>(
        A2HI, A2LO, WIHHI, WIHLO, bih, GI, nullptr, nullptr, M, 768, 256);

    // ---- persistent GRU: group-local sync ----
    gru_persist<<<NCTA, 256, U_SM_TOTAL>>>(GI, WHHHI, WHHLO, bhh, HHI, HLO, FLAGS);

    // fc2a + head
    gemm_bf<true, 0><<<dim3(4, M / 128), 256, G_SM_TOTAL>>>(
        HHI, HLO, W2AHI, W2ALO, b2a, buf1, nullptr, nullptr, M, 512, 256);
    head_gemm<<<M / 1024, 256>>>(buf1, W2b, b2b, out, M);
}

// round 9
// speedup vs baseline: 1.2255x; 1.1213x over previous
#include <cuda_runtime.h>
#include <cuda_bf16.h>
#include <math.h>
#include <stdint.h>

// Problem constants
#define TT 512
#define BB 256
#define IN_DIM 256
#define H1 512
#define HH 256
#define OUT_DIM 18
#define MTOT (TT*BB)   // 131072
#define NCTA_GRU 64
#define GRP 8          // CTAs per sync group

// -------------------- scratch (static device globals; no allocs) -----------
__device__ float d_buf1[(size_t)MTOT * 512];     // fc2a out (fp32, for head)
__device__ float d_GI  [(size_t)MTOT * 768];     // gi fp32

__device__ __nv_bfloat16 d_XHI[(size_t)MTOT * 256], d_XLO[(size_t)MTOT * 256];
__device__ __nv_bfloat16 d_A1HI[(size_t)MTOT * 512], d_A1LO[(size_t)MTOT * 512];
__device__ __nv_bfloat16 d_A2HI[(size_t)MTOT * 256], d_A2LO[(size_t)MTOT * 256];
__device__ __nv_bfloat16 d_HHI[(size_t)MTOT * 256], d_HLO[(size_t)MTOT * 256];

__device__ __nv_bfloat16 d_W1AHI[512*256], d_W1ALO[512*256];
__device__ __nv_bfloat16 d_W1BHI[256*512], d_W1BLO[256*512];
__device__ __nv_bfloat16 d_WIHHI[768*256], d_WIHLO[768*256];
__device__ __nv_bfloat16 d_W2AHI[512*256], d_W2ALO[512*256];
__device__ __nv_bfloat16 d_WHHHI[768*256], d_WHHLO[768*256];

// padded flags: one 128B line per (cta, chain)
__device__ unsigned int d_flags[NCTA_GRU * 2 * 32];

// ==================== helpers ==============================================
__device__ __forceinline__ uint32_t smem_u32(const void* p) {
    uint32_t a;
    asm("{ .reg .u64 t; cvta.to.shared.u64 t, %1; cvt.u32.u64 %0, t; }"
        : "=r"(a) : "l"(p));
    return a;
}

__device__ __forceinline__ void ldsm4(uint32_t* r, uint32_t addr) {
    asm volatile("ldmatrix.sync.aligned.m8n8.x4.shared.b16 {%0,%1,%2,%3}, [%4];"
        : "=r"(r[0]), "=r"(r[1]), "=r"(r[2]), "=r"(r[3]) : "r"(addr));
}
__device__ __forceinline__ void ldsm2(uint32_t* r, uint32_t addr) {
    asm volatile("ldmatrix.sync.aligned.m8n8.x2.shared.b16 {%0,%1}, [%2];"
        : "=r"(r[0]), "=r"(r[1]) : "r"(addr));
}

__device__ __forceinline__ void mma16816(float* c, const uint32_t* a, const uint32_t* b) {
    asm volatile(
        "mma.sync.aligned.m16n8k16.row.col.f32.bf16.bf16.f32 "
        "{%0,%1,%2,%3}, {%4,%5,%6,%7}, {%8,%9}, {%0,%1,%2,%3};"
        : "+f"(c[0]), "+f"(c[1]), "+f"(c[2]), "+f"(c[3])
        : "r"(a[0]), "r"(a[1]), "r"(a[2]), "r"(a[3]), "r"(b[0]), "r"(b[1]));
}

__device__ __forceinline__ void cp16(uint32_t dst, const void* src) {
    asm volatile("cp.async.cg.shared.global [%0], [%1], 16;"
        :: "r"(dst), "l"(src) : "memory");
}
#define CP_COMMIT() asm volatile("cp.async.commit_group;" ::: "memory")
#define CP_WAIT0()  asm volatile("cp.async.wait_group 0;" ::: "memory")
#define CP_WAIT1()  asm volatile("cp.async.wait_group 1;" ::: "memory")

__device__ __forceinline__ void split_bf16x4(float4 v, uint2& hv, uint2& lv) {
    __nv_bfloat16 h0 = __float2bfloat16(v.x);
    __nv_bfloat16 h1 = __float2bfloat16(v.y);
    __nv_bfloat16 h2 = __float2bfloat16(v.z);
    __nv_bfloat16 h3 = __float2bfloat16(v.w);
    __nv_bfloat16 l0 = __float2bfloat16(v.x - __bfloat162float(h0));
    __nv_bfloat16 l1 = __float2bfloat16(v.y - __bfloat162float(h1));
    __nv_bfloat16 l2 = __float2bfloat16(v.z - __bfloat162float(h2));
    __nv_bfloat16 l3 = __float2bfloat16(v.w - __bfloat162float(h3));
    hv.x = (uint32_t)__bfloat16_as_ushort(h0) | ((uint32_t)__bfloat16_as_ushort(h1) << 16);
    hv.y = (uint32_t)__bfloat16_as_ushort(h2) | ((uint32_t)__bfloat16_as_ushort(h3) << 16);
    lv.x = (uint32_t)__bfloat16_as_ushort(l0) | ((uint32_t)__bfloat16_as_ushort(l1) << 16);
    lv.y = (uint32_t)__bfloat16_as_ushort(l2) | ((uint32_t)__bfloat16_as_ushort(l3) << 16);
}

__device__ __forceinline__ uint32_t pack_hi2(float a, float b, uint32_t& lo) {
    __nv_bfloat16 ha = __float2bfloat16(a);
    __nv_bfloat16 hb = __float2bfloat16(b);
    __nv_bfloat16 la = __float2bfloat16(a - __bfloat162float(ha));
    __nv_bfloat16 lb = __float2bfloat16(b - __bfloat162float(hb));
    lo = (uint32_t)__bfloat16_as_ushort(la) | ((uint32_t)__bfloat16_as_ushort(lb) << 16);
    return (uint32_t)__bfloat16_as_ushort(ha) | ((uint32_t)__bfloat16_as_ushort(hb) << 16);
}

// -------------------- split / zero kernels ---------------------------------
__global__ void split_f32(const float4* __restrict__ in,
                          uint2* __restrict__ hi, uint2* __restrict__ lo, int n4) {
    int i = blockIdx.x * blockDim.x + threadIdx.x;
    if (i < n4) {
        uint2 h, l;
        split_bf16x4(in[i], h, l);
        hi[i] = h; lo[i] = l;
    }
}
__global__ void zero_u32(uint32_t* p, int n) {
    int i = blockIdx.x * blockDim.x + threadIdx.x;
    if (i < n) p[i] = 0u;
}

// ==================== pipelined bf16-split GEMM (unchanged, passing) ========
#define GROW 144
#define G_AHI 0
#define G_ALO 18432
#define G_BHI 36864
#define G_BLO 55296
#define G_STAGE 73728
#define G_SM_TOTAL (2*G_STAGE)

template<bool RELU, int OUTM>
__global__ void __launch_bounds__(256, 1) gemm_bf(
    const __nv_bfloat16* __restrict__ Ahi, const __nv_bfloat16* __restrict__ Alo,
    const __nv_bfloat16* __restrict__ Bhi, const __nv_bfloat16* __restrict__ Blo,
    const float* __restrict__ bias,
    float* __restrict__ C, __nv_bfloat16* __restrict__ Chi, __nv_bfloat16* __restrict__ Clo,
    int M, int N, int K)
{
    extern __shared__ char sm[];
    const uint32_t smb = smem_u32(sm);
    const int tid = threadIdx.x;
    const int lane = tid & 31;
    const int wid = tid >> 5;
    const int wm = wid & 1;
    const int wn = wid >> 1;
    const int m0 = blockIdx.y * 128;
    const int n0 = blockIdx.x * 128;

    float acc[4][4][4];
    #pragma unroll
    for (int i = 0; i < 4; i++)
        #pragma unroll
        for (int j = 0; j < 4; j++)
            #pragma unroll
            for (int e = 0; e < 4; e++) acc[i][j][e] = 0.f;

    const uint32_t a_row = (uint32_t)(lane & 15);
    const uint32_t a_kb  = (uint32_t)((lane >> 4) * 16);
    const uint32_t b_row = (uint32_t)(((lane >> 4) & 1) * 8 + (lane & 7));
    const uint32_t b_kb  = (uint32_t)(((lane >> 3) & 1) * 16);

    const int nchunks = K >> 6;

    auto load_chunk = [&](int kc, int st) {
        const int kb = kc << 6;
        const uint32_t base = smb + (uint32_t)st * G_STAGE;
        #pragma unroll
        for (int j = 0; j < 4; j++) {
            int idx = tid + 256 * j;
            int r = idx >> 3;
            int c = idx & 7;
            size_t aoff = (size_t)(m0 + r) * K + kb + c * 8;
            size_t boff = (size_t)(n0 + r) * K + kb + c * 8;
            uint32_t d = (uint32_t)(r * GROW + c * 16);
            cp16(base + G_AHI + d, Ahi + aoff);
            cp16(base + G_ALO + d, Alo + aoff);
            cp16(base + G_BHI + d, Bhi + boff);
            cp16(base + G_BLO + d, Blo + boff);
        }
        CP_COMMIT();
    };

    load_chunk(0, 0);

    for (int kc = 0; kc < nchunks; kc++) {
        const int st = kc & 1;
        if (kc + 1 < nchunks) { load_chunk(kc + 1, st ^ 1); CP_WAIT1(); }
        else                  { CP_WAIT0(); }
        __syncthreads();

        const uint32_t base = smb + (uint32_t)st * G_STAGE;
        #pragma unroll
        for (int ks = 0; ks < 4; ks++) {
            const uint32_t koff = (uint32_t)(ks * 32);
            uint32_t afr[4][4], bhi2[4][2], blo2[4][2];

            #pragma unroll
            for (int mt = 0; mt < 4; mt++)
                ldsm4(afr[mt], base + G_AHI + (uint32_t)(wm*64 + mt*16 + a_row)*GROW + koff + a_kb);
            #pragma unroll
            for (int g = 0; g < 2; g++) {
                uint32_t r4[4];
                ldsm4(r4, base + G_BHI + (uint32_t)(wn*32 + g*16 + b_row)*GROW + koff + b_kb);
                bhi2[g*2  ][0] = r4[0]; bhi2[g*2  ][1] = r4[1];
                bhi2[g*2+1][0] = r4[2]; bhi2[g*2+1][1] = r4[3];
            }
            #pragma unroll
            for (int mt = 0; mt < 4; mt++)
                #pragma unroll
                for (int nt = 0; nt < 4; nt++)
                    mma16816(acc[mt][nt], afr[mt], bhi2[nt]);

            #pragma unroll
            for (int g = 0; g < 2; g++) {
                uint32_t r4[4];
                ldsm4(r4, base + G_BLO + (uint32_t)(wn*32 + g*16 + b_row)*GROW + koff + b_kb);
                blo2[g*2  ][0] = r4[0]; blo2[g*2  ][1] = r4[1];
                blo2[g*2+1][0] = r4[2]; blo2[g*2+1][1] = r4[3];
            }
            #pragma unroll
            for (int mt = 0; mt < 4; mt++)
                #pragma unroll
                for (int nt = 0; nt < 4; nt++)
                    mma16816(acc[mt][nt], afr[mt], blo2[nt]);

            #pragma unroll
            for (int mt = 0; mt < 4; mt++)
                ldsm4(afr[mt], base + G_ALO + (uint32_t)(wm*64 + mt*16 + a_row)*GROW + koff + a_kb);
            #pragma unroll
            for (int mt = 0; mt < 4; mt++)
                #pragma unroll
                for (int nt = 0; nt < 4; nt++)
                    mma16816(acc[mt][nt], afr[mt], bhi2[nt]);
        }
        __syncthreads();
    }

    const int r_in = lane >> 2;
    const int c_in = (lane & 3) * 2;
    #pragma unroll
    for (int mt = 0; mt < 4; mt++) {
        #pragma unroll
        for (int nt = 0; nt < 4; nt++) {
            int col = n0 + wn * 32 + nt * 8 + c_in;
            float b0 = bias[col], b1 = bias[col + 1];
            int row0 = m0 + wm * 64 + mt * 16 + r_in;
            float v00 = acc[mt][nt][0] + b0, v01 = acc[mt][nt][1] + b1;
            float v10 = acc[mt][nt][2] + b0, v11 = acc[mt][nt][3] + b1;
            if (RELU) {
                v00 = fmaxf(v00, 0.f); v01 = fmaxf(v01, 0.f);
                v10 = fmaxf(v10, 0.f); v11 = fmaxf(v11, 0.f);
            }
            if (OUTM == 0) {
                float2 p0, p1;
                p0.x = v00; p0.y = v01; p1.x = v10; p1.y = v11;
                *(float2*)&C[(size_t)row0 * N + col] = p0;
                *(float2*)&C[(size_t)(row0 + 8) * N + col] = p1;
            } else {
                uint32_t lo0, lo1;
                uint32_t hi0 = pack_hi2(v00, v01, lo0);
                uint32_t hi1 = pack_hi2(v10, v11, lo1);
                *(uint32_t*)&Chi[(size_t)row0 * N + col] = hi0;
                *(uint32_t*)&Clo[(size_t)row0 * N + col] = lo0;
                *(uint32_t*)&Chi[(size_t)(row0 + 8) * N + col] = hi1;
                *(uint32_t*)&Clo[(size_t)(row0 + 8) * N + col] = lo1;
            }
        }
    }
}

// ==================== persistent GRU v4: dual-chain pipeline ================
// 64 CTAs = 8 groups x 8 CTAs. Group g owns rows [g*32, g*32+32) as two
// independent 16-row chains A and B, interleaved in time so each chain's
// flag round-trip + h reload hides under the other chain's compute.
// CTA kq owns k-slice [kq*32, kq*32+32): 96 W rows resident in smem.
#define U_WHI 0
#define U_WLO 50688            // 96*528
#define U_HA_HI 101376         // 16*528 = 8448 each
#define U_HA_LO 109824
#define U_HB_HI 118272
#define U_HB_LO 126720
#define U_GH0 135168           // 16*97*4 = 6208
#define U_GH1 141376
#define U_SM_TOTAL 147584
#define USTRIDE 528

__global__ void __launch_bounds__(256, 1) gru_persist(
    const float* __restrict__ GI_,
    const __nv_bfloat16* __restrict__ whh_hi,
    const __nv_bfloat16* __restrict__ whh_lo,
    const float* __restrict__ bhh,
    __nv_bfloat16* __restrict__ HHI_,
    __nv_bfloat16* __restrict__ HLO_,
    unsigned int* __restrict__ flags)
{
    extern __shared__ char sm[];
    const uint32_t smb = smem_u32(sm);
    float* GH0 = (float*)(sm + U_GH0);
    float* GH1 = (float*)(sm + U_GH1);
    const int tid = threadIdx.x;
    const int lane = tid & 31;
    const int wid = tid >> 5;
    const int wk = wid >> 2;          // 0..1: K half
    const int wn = wid & 3;           // 0..3: N quarter (24 cols of 96)
    const int cta = blockIdx.x;
    const int grp = cta >> 3;         // 0..7
    const int kq  = cta & 7;          // 0..7
    const int b0 = grp * 32;
    const int k0 = kq * 32;

    // ---- load W slice once: 96 rows (3 gates x 32 k-offsets), hi+lo ----
    for (int i = tid; i < 3072; i += 256) {
        int j = i >> 5;
        int c = i & 31;
        int gate = j >> 5, jr = j & 31;
        size_t soff = (size_t)(gate * 256 + k0 + jr) * 256 + c * 8;
        uint32_t d = (uint32_t)(j * USTRIDE + c * 16);
        cp16(smb + U_WHI + d, whh_hi + soff);
        cp16(smb + U_WLO + d, whh_lo + soff);
    }
    CP_COMMIT();

    for (int i = tid; i < 16 * 97; i += 256) { GH0[i] = 0.f; GH1[i] = 0.f; }

    // ---- per-thread gate constants: 2 outputs per chain ----
    int bloc[2], kloc[2];
    size_t off_oA[2], off_oB[2], gioA[2], gioB[2];
    float brr[2], brz[2], brn[2];
    float hpA[2] = {0.f, 0.f}, hpB[2] = {0.f, 0.f};
    #pragma unroll
    for (int i = 0; i < 2; i++) {
        int idx = tid + 256 * i;
        int b = idx >> 5, ko = idx & 31;
        bloc[i] = b; kloc[i] = ko;
        int kg = k0 + ko;
        off_oA[i] = (size_t)(b0 + b) * 256 + kg;
        off_oB[i] = (size_t)(b0 + 16 + b) * 256 + kg;
        gioA[i] = (size_t)(b0 + b) * 768 + kg;
        gioB[i] = (size_t)(b0 + 16 + b) * 768 + kg;
        brr[i] = bhh[kg];
        brz[i] = bhh[256 + kg];
        brn[i] = bhh[512 + kg];
    }

    // ---- mma addressing ----
    const uint32_t a_row = (uint32_t)(lane & 15);
    const uint32_t a_kb  = (uint32_t)((lane >> 4) * 16);
    const uint32_t b_row = (uint32_t)(((lane >> 4) & 1) * 8 + (lane & 7));
    const uint32_t b_kb  = (uint32_t)(((lane >> 3) & 1) * 16);
    const uint32_t b2_row = (uint32_t)(lane & 7);
    const uint32_t b2_kb  = (uint32_t)(((lane >> 3) & 1) * 16);
    const uint32_t kofs = (uint32_t)(wk * 256);

    const uint32_t aHiA = smb + U_HA_HI + a_row * USTRIDE + a_kb + kofs;
    const uint32_t aLoA = smb + U_HA_LO + a_row * USTRIDE + a_kb + kofs;
    const uint32_t aHiB = smb + U_HB_HI + a_row * USTRIDE + a_kb + kofs;
    const uint32_t aLoB = smb + U_HB_LO + a_row * USTRIDE + a_kb + kofs;
    const uint32_t bBaseHi4 = smb + U_WHI + (uint32_t)(wn * 24 + b_row) * USTRIDE + b_kb + kofs;
    const uint32_t bBaseLo4 = smb + U_WLO + (uint32_t)(wn * 24 + b_row) * USTRIDE + b_kb + kofs;
    const uint32_t bBaseHi2 = smb + U_WHI + (uint32_t)(wn * 24 + 16 + b2_row) * USTRIDE + b2_kb + kofs;
    const uint32_t bBaseLo2 = smb + U_WLO + (uint32_t)(wn * 24 + 16 + b2_row) * USTRIDE + b2_kb + kofs;
    float* GHw = wk ? GH1 : GH0;

    // flag addresses (padded to 128B per flag)
    unsigned int* myflagA = flags + (cta * 2 + 0) * 32;
    unsigned int* myflagB = flags + (cta * 2 + 1) * 32;
    unsigned int* pollA = flags + (((grp * GRP) + (tid & 7)) * 2 + 0) * 32;
    unsigned int* pollB = flags + (((grp * GRP) + (tid & 7)) * 2 + 1) * 32;

    // ---- mma phase lambda ----
    auto do_mma = [&](uint32_t aHi, uint32_t aLo) {
        float acc[3][4];
        #pragma unroll
        for (int i = 0; i < 3; i++)
            #pragma unroll
            for (int e = 0; e < 4; e++) acc[i][e] = 0.f;

        #pragma unroll
        for (int ks = 0; ks < 8; ks++) {
            const uint32_t koff = (uint32_t)(ks * 32);
            uint32_t a[4], bh[3][2], bl[3][2], r4[4];

            ldsm4(a, aHi + koff);
            ldsm4(r4, bBaseHi4 + koff);
            bh[0][0] = r4[0]; bh[0][1] = r4[1]; bh[1][0] = r4[2]; bh[1][1] = r4[3];
            ldsm2(bh[2], bBaseHi2 + koff);
            #pragma unroll
            for (int nt = 0; nt < 3; nt++) mma16816(acc[nt], a, bh[nt]);

            ldsm4(r4, bBaseLo4 + koff);
            bl[0][0] = r4[0]; bl[0][1] = r4[1]; bl[1][0] = r4[2]; bl[1][1] = r4[3];
            ldsm2(bl[2], bBaseLo2 + koff);
            #pragma unroll
            for (int nt = 0; nt < 3; nt++) mma16816(acc[nt], a, bl[nt]);

            ldsm4(a, aLo + koff);
            #pragma unroll
            for (int nt = 0; nt < 3; nt++) mma16816(acc[nt], a, bh[nt]);
        }
        const int r0 = lane >> 2;
        const int cc = (lane & 3) * 2;
        #pragma unroll
        for (int nt = 0; nt < 3; nt++) {
            int col = wn * 24 + nt * 8 + cc;
            GHw[r0 * 97 + col]           = acc[nt][0];
            GHw[r0 * 97 + col + 1]       = acc[nt][1];
            GHw[(r0 + 8) * 97 + col]     = acc[nt][2];
            GHw[(r0 + 8) * 97 + col + 1] = acc[nt][3];
        }
    };

    // gate phase: computes h_new, stores to global, updates hp
    auto do_gates = [&](int t, const size_t* off_o, float* hp,
                        float* ir, float* iz, float* in_) {
        __nv_bfloat16* hoh = HHI_ + (size_t)t * (BB * HH);
        __nv_bfloat16* hol = HLO_ + (size_t)t * (BB * HH);
        #pragma unroll
        for (int i = 0; i < 2; i++) {
            int b = bloc[i], ko = kloc[i];
            float hr = GH0[b * 97 + ko]      + GH1[b * 97 + ko]      + brr[i];
            float hz = GH0[b * 97 + 32 + ko] + GH1[b * 97 + 32 + ko] + brz[i];
            float hn = GH0[b * 97 + 64 + ko] + GH1[b * 97 + 64 + ko] + brn[i];

            float r = 1.f / (1.f + __expf(-(ir[i] + hr)));
            float z = 1.f / (1.f + __expf(-(iz[i] + hz)));
            float n = tanhf(in_[i] + r * hn);
            float hnew = (1.f - z) * n + z * hp[i];
            hp[i] = hnew;

            __nv_bfloat16 hh = __float2bfloat16(hnew);
            hoh[off_o[i]] = hh;
            hol[off_o[i]] = __float2bfloat16(hnew - __bfloat162float(hh));
        }
    };

    auto load_h = [&](int t, int bOff, uint32_t hiBuf, uint32_t loBuf) {
        const __nv_bfloat16* hph = HHI_ + (size_t)t * (BB * HH);
        const __nv_bfloat16* hpl = HLO_ + (size_t)t * (BB * HH);
        #pragma unroll
        for (int i = 0; i < 2; i++) {
            int idx = tid + 256 * i;
            int r = idx >> 5;
            int c = idx & 31;
            size_t soff = (size_t)(b0 + bOff + r) * 256 + c * 8;
            uint32_t d = (uint32_t)(r * USTRIDE + c * 16);
            cp16(hiBuf + d, hph + soff);
            cp16(loBuf + d, hpl + soff);
        }
        CP_COMMIT();
    };

    auto signal_spin = [&](unsigned int* myflag, unsigned int* poll, unsigned int target) {
        __syncthreads();
        if (tid == 0) {
            asm volatile("st.release.gpu.u32 [%0], %1;"
                :: "l"(myflag), "r"(target) : "memory");
        }
        if (tid < GRP) {
            unsigned int v;
            do {
                asm volatile("ld.acquire.gpu.u32 %0, [%1];"
                    : "=r"(v) : "l"(poll) : "memory");
            } while (v < target);
        }
        __syncthreads();
    };

    // gi registers per chain
    float irA[2], izA[2], inA[2], irB[2], izB[2], inB[2];
    #pragma unroll
    for (int i = 0; i < 2; i++) {
        irA[i] = __ldg(GI_ + gioA[i]);
        izA[i] = __ldg(GI_ + gioA[i] + 256);
        inA[i] = __ldg(GI_ + gioA[i] + 512);
        irB[i] = __ldg(GI_ + gioB[i]);
        izB[i] = __ldg(GI_ + gioB[i] + 256);
        inB[i] = __ldg(GI_ + gioB[i] + 512);
    }

    // ---- prologue (t = 0): gates with gh = 0 ----
    CP_WAIT0();          // W loaded
    __syncthreads();     // GH zeros + W visible

    do_gates(0, off_oA, hpA, irA, izA, inA);
    {
        const float* gin = GI_ + (size_t)1 * (BB * 768);
        #pragma unroll
        for (int i = 0; i < 2; i++) {
            irA[i] = __ldg(gin + gioA[i]);
            izA[i] = __ldg(gin + gioA[i] + 256);
            inA[i] = __ldg(gin + gioA[i] + 512);
        }
    }
    signal_spin(myflagA, pollA, 1u);
    load_h(0, 0, smb + U_HA_HI, smb + U_HA_LO);

    do_gates(0, off_oB, hpB, irB, izB, inB);
    {
        const float* gin = GI_ + (size_t)1 * (BB * 768);
        #pragma unroll
        for (int i = 0; i < 2; i++) {
            irB[i] = __ldg(gin + gioB[i]);
            izB[i] = __ldg(gin + gioB[i] + 256);
            inB[i] = __ldg(gin + gioB[i] + 512);
        }
    }
    signal_spin(myflagB, pollB, 1u);
    load_h(0, 16, smb + U_HB_HI, smb + U_HB_LO);

    // ---- main loop ----
    for (int t = 1; t < TT; t++) {
        // === chain A ===
        CP_WAIT1();          // hA[t-1] arrived (hB load may still be in flight)
        __syncthreads();
        do_mma(aHiA, aLoA);
        __syncthreads();
        do_gates(t, off_oA, hpA, irA, izA, inA);
        if (t + 1 < TT) {
            const float* gin = GI_ + (size_t)(t + 1) * (BB * 768);
            #pragma unroll
            for (int i = 0; i < 2; i++) {
                irA[i] = __ldg(gin + gioA[i]);
                izA[i] = __ldg(gin + gioA[i] + 256);
                inA[i] = __ldg(gin + gioA[i] + 512);
            }
        }
        signal_spin(myflagA, pollA, (unsigned int)(t + 1));
        load_h(t, 0, smb + U_HA_HI, smb + U_HA_LO);   // always commit (t=511 load unused)

        // === chain B ===
        CP_WAIT1();          // hB[t-1] arrived
        __syncthreads();
        do_mma(aHiB, aLoB);
        __syncthreads();
        do_gates(t, off_oB, hpB, irB, izB, inB);
        if (t + 1 < TT) {
            const float* gin = GI_ + (size_t)(t + 1) * (BB * 768);
            #pragma unroll
            for (int i = 0; i < 2; i++) {
                irB[i] = __ldg(gin + gioB[i]);
                izB[i] = __ldg(gin + gioB[i] + 256);
                inB[i] = __ldg(gin + gioB[i] + 512);
            }
        }
        signal_spin(myflagB, pollB, (unsigned int)(t + 1));
        load_h(t, 16, smb + U_HB_HI, smb + U_HB_LO);
    }
    CP_WAIT0();   // drain trailing loads
}

// -------------------- fc2b head -------------------------------------------
__global__ void __launch_bounds__(256, 2) head_gemm(
    const float* __restrict__ A,
    const float* __restrict__ Wb,
    const float* __restrict__ bias,
    float* __restrict__ out, int M)
{
    __shared__ float Ws[18][512];
    const int tid = threadIdx.x;
    #pragma unroll
    for (int i = 0; i < 9; i++) {
        int idx = tid + 256 * i;
        ((float4*)&Ws[0][0])[idx] = ((const float4*)Wb)[idx];
    }
    __syncthreads();

    const size_t mbase = (size_t)blockIdx.x * 1024 + tid;

    float acc[4][18];
    #pragma unroll
    for (int i = 0; i < 4; i++)
        #pragma unroll
        for (int j = 0; j < 18; j++) acc[i][j] = 0.f;

    for (int k4 = 0; k4 < 128; k4++) {
        float4 a[4];
        #pragma unroll
        for (int i = 0; i < 4; i++)
            a[i] = *(const float4*)&A[(mbase + 256 * i) * 512 + k4 * 4];
        #pragma unroll
        for (int j = 0; j < 18; j++) {
            float4 w = *(const float4*)&Ws[j][k4 * 4];
            #pragma unroll
            for (int i = 0; i < 4; i++) {
                acc[i][j] += a[i].x * w.x;
                acc[i][j] += a[i].y * w.y;
                acc[i][j] += a[i].z * w.z;
                acc[i][j] += a[i].w * w.w;
            }
        }
    }

    #pragma unroll
    for (int i = 0; i < 4; i++) {
        size_t row = mbase + 256 * i;
        #pragma unroll
        for (int j = 0; j < 18; j++)
            out[row * 18 + j] = acc[i][j] + bias[j];
    }
}

// -------------------- launch ------------------------------------------------
extern "C" void kernel_launch(void* const* d_in, const int* in_sizes, int n_in,
                              void* d_out, int out_size)
{
    (void)in_sizes; (void)n_in; (void)out_size;
    const float* x    = (const float*)d_in[0];
    const float* W1a  = (const float*)d_in[1];
    const float* b1a  = (const float*)d_in[2];
    const float* W1b  = (const float*)d_in[3];
    const float* b1b  = (const float*)d_in[4];
    const float* Wih  = (const float*)d_in[5];
    const float* bih  = (const float*)d_in[6];
    const float* Whh  = (const float*)d_in[7];
    const float* bhh  = (const float*)d_in[8];
    const float* W2a  = (const float*)d_in[9];
    const float* b2a  = (const float*)d_in[10];
    const float* W2b  = (const float*)d_in[11];
    const float* b2b  = (const float*)d_in[12];
    float* out = (float*)d_out;

    float *buf1, *GI;
    __nv_bfloat16 *XHI, *XLO, *A1HI, *A1LO, *A2HI, *A2LO, *HHI, *HLO;
    __nv_bfloat16 *W1AHI, *W1ALO, *W1BHI, *W1BLO, *WIHHI, *WIHLO, *W2AHI, *W2ALO, *WHHHI, *WHHLO;
    unsigned int* FLAGS;

    cudaGetSymbolAddress((void**)&buf1, d_buf1);
    cudaGetSymbolAddress((void**)&GI,   d_GI);
    cudaGetSymbolAddress((void**)&XHI,  d_XHI);  cudaGetSymbolAddress((void**)&XLO,  d_XLO);
    cudaGetSymbolAddress((void**)&A1HI, d_A1HI); cudaGetSymbolAddress((void**)&A1LO, d_A1LO);
    cudaGetSymbolAddress((void**)&A2HI, d_A2HI); cudaGetSymbolAddress((void**)&A2LO, d_A2LO);
    cudaGetSymbolAddress((void**)&HHI,  d_HHI);  cudaGetSymbolAddress((void**)&HLO,  d_HLO);
    cudaGetSymbolAddress((void**)&W1AHI, d_W1AHI); cudaGetSymbolAddress((void**)&W1ALO, d_W1ALO);
    cudaGetSymbolAddress((void**)&W1BHI, d_W1BHI); cudaGetSymbolAddress((void**)&W1BLO, d_W1BLO);
    cudaGetSymbolAddress((void**)&WIHHI, d_WIHHI); cudaGetSymbolAddress((void**)&WIHLO, d_WIHLO);
    cudaGetSymbolAddress((void**)&W2AHI, d_W2AHI); cudaGetSymbolAddress((void**)&W2ALO, d_W2ALO);
    cudaGetSymbolAddress((void**)&WHHHI, d_WHHHI); cudaGetSymbolAddress((void**)&WHHLO, d_WHHLO);
    cudaGetSymbolAddress((void**)&FLAGS, d_flags);

    cudaFuncSetAttribute(gemm_bf<true, 0>,  cudaFuncAttributeMaxDynamicSharedMemorySize, G_SM_TOTAL);
    cudaFuncSetAttribute(gemm_bf<true, 1>,  cudaFuncAttributeMaxDynamicSharedMemorySize, G_SM_TOTAL);
    cudaFuncSetAttribute(gemm_bf<false, 0>, cudaFuncAttributeMaxDynamicSharedMemorySize, G_SM_TOTAL);
    cudaFuncSetAttribute(gru_persist, cudaFuncAttributeMaxDynamicSharedMemorySize, U_SM_TOTAL);

    const int M = MTOT;

    // ---- pre-split inputs/weights to bf16 hi/lo ----
    split_f32<<<(M * 256 / 4 + 255) / 256, 256>>>((const float4*)x, (uint2*)XHI, (uint2*)XLO, M * 256 / 4);
    split_f32<<<128, 256>>>((const float4*)W1a, (uint2*)W1AHI, (uint2*)W1ALO, 512 * 256 / 4);
    split_f32<<<128, 256>>>((const float4*)W1b, (uint2*)W1BHI, (uint2*)W1BLO, 256 * 512 / 4);
    split_f32<<<192, 256>>>((const float4*)Wih, (uint2*)WIHHI, (uint2*)WIHLO, 768 * 256 / 4);
    split_f32<<<128, 256>>>((const float4*)W2a, (uint2*)W2AHI, (uint2*)W2ALO, 512 * 256 / 4);
    split_f32<<<192, 256>>>((const float4*)Whh, (uint2*)WHHHI, (uint2*)WHHLO, 768 * 256 / 4);

    zero_u32<<<16, 256>>>((uint32_t*)FLAGS, NCTA_GRU * 2 * 32);

    // ---- batched GEMMs ----
    gemm_bf<true, 1><<<dim3(4, M / 128), 256, G_SM_TOTAL>>>(
        XHI, XLO, W1AHI, W1ALO, b1a, nullptr, A1HI, A1LO, M, 512, 256);
    gemm_bf<true, 1><<<dim3(2, M / 128), 256, G_SM_TOTAL>>>(
        A1HI, A1LO, W1BHI, W1BLO, b1b, nullptr, A2HI, A2LO, M, 256, 512);
    gemm_bf<false, 0><<<dim3(6, M / 128), 256, G_SM_TOTAL>>>(
        A2HI, A2LO, WIHHI, WIHLO, bih, GI, nullptr, nullptr, M, 768, 256);

    // ---- persistent GRU: dual-chain pipeline ----
    gru_persist<<<NCTA_GRU, 256, U_SM_TOTAL>>>(GI, WHHHI, WHHLO, bhh, HHI, HLO, FLAGS);

    // fc2a + head
    gemm_bf<true, 0><<<dim3(4, M / 128), 256, G_SM_TOTAL>>>(
        HHI, HLO, W2AHI, W2ALO, b2a, buf1, nullptr, nullptr, M, 512, 256);
    head_gemm<<<M / 1024, 256>>>(buf1, W2b, b2b, out, M);
}

// round 10
// speedup vs baseline: 1.4059x; 1.1473x over previous
#include <cuda_runtime.h>
#include <cuda_bf16.h>
#include <math.h>
#include <stdint.h>

// Problem constants
#define TT 512
#define BB 256
#define IN_DIM 256
#define H1 512
#define HH 256
#define OUT_DIM 18
#define MTOT (TT*BB)   // 131072
#define NCTA_GRU 64
#define GRP 8          // CTAs per sync group

// -------------------- scratch (static device globals; no allocs) -----------
__device__ float d_buf1[(size_t)MTOT * 512];     // fc2a out (fp32, for head)
__device__ float d_GI  [(size_t)MTOT * 768];     // gi fp32

__device__ __nv_bfloat16 d_XHI[(size_t)MTOT * 256], d_XLO[(size_t)MTOT * 256];
__device__ __nv_bfloat16 d_A1HI[(size_t)MTOT * 512], d_A1LO[(size_t)MTOT * 512];
__device__ __nv_bfloat16 d_A2HI[(size_t)MTOT * 256], d_A2LO[(size_t)MTOT * 256];
__device__ __nv_bfloat16 d_HHI[(size_t)MTOT * 256], d_HLO[(size_t)MTOT * 256];

__device__ __nv_bfloat16 d_W1AHI[512*256], d_W1ALO[512*256];
__device__ __nv_bfloat16 d_W1BHI[256*512], d_W1BLO[256*512];
__device__ __nv_bfloat16 d_WIHHI[768*256], d_WIHLO[768*256];
__device__ __nv_bfloat16 d_W2AHI[512*256], d_W2ALO[512*256];
__device__ __nv_bfloat16 d_WHHHI[768*256], d_WHHLO[768*256];

// padded flags: one 128B line per (cta, chain)
__device__ unsigned int d_flags[NCTA_GRU * 2 * 32];

// ==================== helpers ==============================================
__device__ __forceinline__ uint32_t smem_u32(const void* p) {
    uint32_t a;
    asm("{ .reg .u64 t; cvta.to.shared.u64 t, %1; cvt.u32.u64 %0, t; }"
        : "=r"(a) : "l"(p));
    return a;
}

__device__ __forceinline__ void ldsm4(uint32_t* r, uint32_t addr) {
    asm volatile("ldmatrix.sync.aligned.m8n8.x4.shared.b16 {%0,%1,%2,%3}, [%4];"
        : "=r"(r[0]), "=r"(r[1]), "=r"(r[2]), "=r"(r[3]) : "r"(addr));
}
__device__ __forceinline__ void ldsm2(uint32_t* r, uint32_t addr) {
    asm volatile("ldmatrix.sync.aligned.m8n8.x2.shared.b16 {%0,%1}, [%2];"
        : "=r"(r[0]), "=r"(r[1]) : "r"(addr));
}

__device__ __forceinline__ void mma16816(float* c, const uint32_t* a, const uint32_t* b) {
    asm volatile(
        "mma.sync.aligned.m16n8k16.row.col.f32.bf16.bf16.f32 "
        "{%0,%1,%2,%3}, {%4,%5,%6,%7}, {%8,%9}, {%0,%1,%2,%3};"
        : "+f"(c[0]), "+f"(c[1]), "+f"(c[2]), "+f"(c[3])
        : "r"(a[0]), "r"(a[1]), "r"(a[2]), "r"(a[3]), "r"(b[0]), "r"(b[1]));
}

__device__ __forceinline__ void cp16(uint32_t dst, const void* src) {
    asm volatile("cp.async.cg.shared.global [%0], [%1], 16;"
        :: "r"(dst), "l"(src) : "memory");
}
#define CP_COMMIT() asm volatile("cp.async.commit_group;" ::: "memory")
#define CP_WAIT0()  asm volatile("cp.async.wait_group 0;" ::: "memory")
#define CP_WAIT1()  asm volatile("cp.async.wait_group 1;" ::: "memory")
#define BARX(id)    asm volatile("bar.sync %0, 128;" :: "r"(id) : "memory")

__device__ __forceinline__ void split_bf16x4(float4 v, uint2& hv, uint2& lv) {
    __nv_bfloat16 h0 = __float2bfloat16(v.x);
    __nv_bfloat16 h1 = __float2bfloat16(v.y);
    __nv_bfloat16 h2 = __float2bfloat16(v.z);
    __nv_bfloat16 h3 = __float2bfloat16(v.w);
    __nv_bfloat16 l0 = __float2bfloat16(v.x - __bfloat162float(h0));
    __nv_bfloat16 l1 = __float2bfloat16(v.y - __bfloat162float(h1));
    __nv_bfloat16 l2 = __float2bfloat16(v.z - __bfloat162float(h2));
    __nv_bfloat16 l3 = __float2bfloat16(v.w - __bfloat162float(h3));
    hv.x = (uint32_t)__bfloat16_as_ushort(h0) | ((uint32_t)__bfloat16_as_ushort(h1) << 16);
    hv.y = (uint32_t)__bfloat16_as_ushort(h2) | ((uint32_t)__bfloat16_as_ushort(h3) << 16);
    lv.x = (uint32_t)__bfloat16_as_ushort(l0) | ((uint32_t)__bfloat16_as_ushort(l1) << 16);
    lv.y = (uint32_t)__bfloat16_as_ushort(l2) | ((uint32_t)__bfloat16_as_ushort(l3) << 16);
}

__device__ __forceinline__ uint32_t pack_hi2(float a, float b, uint32_t& lo) {
    __nv_bfloat16 ha = __float2bfloat16(a);
    __nv_bfloat16 hb = __float2bfloat16(b);
    __nv_bfloat16 la = __float2bfloat16(a - __bfloat162float(ha));
    __nv_bfloat16 lb = __float2bfloat16(b - __bfloat162float(hb));
    lo = (uint32_t)__bfloat16_as_ushort(la) | ((uint32_t)__bfloat16_as_ushort(lb) << 16);
    return (uint32_t)__bfloat16_as_ushort(ha) | ((uint32_t)__bfloat16_as_ushort(hb) << 16);
}

// -------------------- split / zero kernels ---------------------------------
__global__ void split_f32(const float4* __restrict__ in,
                          uint2* __restrict__ hi, uint2* __restrict__ lo, int n4) {
    int i = blockIdx.x * blockDim.x + threadIdx.x;
    if (i < n4) {
        uint2 h, l;
        split_bf16x4(in[i], h, l);
        hi[i] = h; lo[i] = l;
    }
}
__global__ void zero_u32(uint32_t* p, int n) {
    int i = blockIdx.x * blockDim.x + threadIdx.x;
    if (i < n) p[i] = 0u;
}

// ==================== pipelined bf16-split GEMM (unchanged, passing) ========
#define GROW 144
#define G_AHI 0
#define G_ALO 18432
#define G_BHI 36864
#define G_BLO 55296
#define G_STAGE 73728
#define G_SM_TOTAL (2*G_STAGE)

template<bool RELU, int OUTM>
__global__ void __launch_bounds__(256, 1) gemm_bf(
    const __nv_bfloat16* __restrict__ Ahi, const __nv_bfloat16* __restrict__ Alo,
    const __nv_bfloat16* __restrict__ Bhi, const __nv_bfloat16* __restrict__ Blo,
    const float* __restrict__ bias,
    float* __restrict__ C, __nv_bfloat16* __restrict__ Chi, __nv_bfloat16* __restrict__ Clo,
    int M, int N, int K)
{
    extern __shared__ char sm[];
    const uint32_t smb = smem_u32(sm);
    const int tid = threadIdx.x;
    const int lane = tid & 31;
    const int wid = tid >> 5;
    const int wm = wid & 1;
    const int wn = wid >> 1;
    const int m0 = blockIdx.y * 128;
    const int n0 = blockIdx.x * 128;

    float acc[4][4][4];
    #pragma unroll
    for (int i = 0; i < 4; i++)
        #pragma unroll
        for (int j = 0; j < 4; j++)
            #pragma unroll
            for (int e = 0; e < 4; e++) acc[i][j][e] = 0.f;

    const uint32_t a_row = (uint32_t)(lane & 15);
    const uint32_t a_kb  = (uint32_t)((lane >> 4) * 16);
    const uint32_t b_row = (uint32_t)(((lane >> 4) & 1) * 8 + (lane & 7));
    const uint32_t b_kb  = (uint32_t)(((lane >> 3) & 1) * 16);

    const int nchunks = K >> 6;

    auto load_chunk = [&](int kc, int st) {
        const int kb = kc << 6;
        const uint32_t base = smb + (uint32_t)st * G_STAGE;
        #pragma unroll
        for (int j = 0; j < 4; j++) {
            int idx = tid + 256 * j;
            int r = idx >> 3;
            int c = idx & 7;
            size_t aoff = (size_t)(m0 + r) * K + kb + c * 8;
            size_t boff = (size_t)(n0 + r) * K + kb + c * 8;
            uint32_t d = (uint32_t)(r * GROW + c * 16);
            cp16(base + G_AHI + d, Ahi + aoff);
            cp16(base + G_ALO + d, Alo + aoff);
            cp16(base + G_BHI + d, Bhi + boff);
            cp16(base + G_BLO + d, Blo + boff);
        }
        CP_COMMIT();
    };

    load_chunk(0, 0);

    for (int kc = 0; kc < nchunks; kc++) {
        const int st = kc & 1;
        if (kc + 1 < nchunks) { load_chunk(kc + 1, st ^ 1); CP_WAIT1(); }
        else                  { CP_WAIT0(); }
        __syncthreads();

        const uint32_t base = smb + (uint32_t)st * G_STAGE;
        #pragma unroll
        for (int ks = 0; ks < 4; ks++) {
            const uint32_t koff = (uint32_t)(ks * 32);
            uint32_t afr[4][4], bhi2[4][2], blo2[4][2];

            #pragma unroll
            for (int mt = 0; mt < 4; mt++)
                ldsm4(afr[mt], base + G_AHI + (uint32_t)(wm*64 + mt*16 + a_row)*GROW + koff + a_kb);
            #pragma unroll
            for (int g = 0; g < 2; g++) {
                uint32_t r4[4];
                ldsm4(r4, base + G_BHI + (uint32_t)(wn*32 + g*16 + b_row)*GROW + koff + b_kb);
                bhi2[g*2  ][0] = r4[0]; bhi2[g*2  ][1] = r4[1];
                bhi2[g*2+1][0] = r4[2]; bhi2[g*2+1][1] = r4[3];
            }
            #pragma unroll
            for (int mt = 0; mt < 4; mt++)
                #pragma unroll
                for (int nt = 0; nt < 4; nt++)
                    mma16816(acc[mt][nt], afr[mt], bhi2[nt]);

            #pragma unroll
            for (int g = 0; g < 2; g++) {
                uint32_t r4[4];
                ldsm4(r4, base + G_BLO + (uint32_t)(wn*32 + g*16 + b_row)*GROW + koff + b_kb);
                blo2[g*2  ][0] = r4[0]; blo2[g*2  ][1] = r4[1];
                blo2[g*2+1][0] = r4[2]; blo2[g*2+1][1] = r4[3];
            }
            #pragma unroll
            for (int mt = 0; mt < 4; mt++)
                #pragma unroll
                for (int nt = 0; nt < 4; nt++)
                    mma16816(acc[mt][nt], afr[mt], blo2[nt]);

            #pragma unroll
            for (int mt = 0; mt < 4; mt++)
                ldsm4(afr[mt], base + G_ALO + (uint32_t)(wm*64 + mt*16 + a_row)*GROW + koff + a_kb);
            #pragma unroll
            for (int mt = 0; mt < 4; mt++)
                #pragma unroll
                for (int nt = 0; nt < 4; nt++)
                    mma16816(acc[mt][nt], afr[mt], bhi2[nt]);
        }
        __syncthreads();
    }

    const int r_in = lane >> 2;
    const int c_in = (lane & 3) * 2;
    #pragma unroll
    for (int mt = 0; mt < 4; mt++) {
        #pragma unroll
        for (int nt = 0; nt < 4; nt++) {
            int col = n0 + wn * 32 + nt * 8 + c_in;
            float b0 = bias[col], b1 = bias[col + 1];
            int row0 = m0 + wm * 64 + mt * 16 + r_in;
            float v00 = acc[mt][nt][0] + b0, v01 = acc[mt][nt][1] + b1;
            float v10 = acc[mt][nt][2] + b0, v11 = acc[mt][nt][3] + b1;
            if (RELU) {
                v00 = fmaxf(v00, 0.f); v01 = fmaxf(v01, 0.f);
                v10 = fmaxf(v10, 0.f); v11 = fmaxf(v11, 0.f);
            }
            if (OUTM == 0) {
                float2 p0, p1;
                p0.x = v00; p0.y = v01; p1.x = v10; p1.y = v11;
                *(float2*)&C[(size_t)row0 * N + col] = p0;
                *(float2*)&C[(size_t)(row0 + 8) * N + col] = p1;
            } else {
                uint32_t lo0, lo1;
                uint32_t hi0 = pack_hi2(v00, v01, lo0);
                uint32_t hi1 = pack_hi2(v10, v11, lo1);
                *(uint32_t*)&Chi[(size_t)row0 * N + col] = hi0;
                *(uint32_t*)&Clo[(size_t)row0 * N + col] = lo0;
                *(uint32_t*)&Chi[(size_t)(row0 + 8) * N + col] = hi1;
                *(uint32_t*)&Clo[(size_t)(row0 + 8) * N + col] = lo1;
            }
        }
    }
}

// ==================== persistent GRU v5: warp-specialized dual chain ========
// 64 CTAs = 8 groups x 8 CTAs; group g owns rows [g*32, g*32+32).
// Warps 0-3 run chain A (rows +0..16); warps 4-7 run chain B (rows +16..32).
// Each 128-thread warp-group runs its OWN full recurrence loop with named
// barriers (bar.sync 1/2, 128) — one chain's spin/load hides under the
// other chain's compute via HW warp scheduling. W slice (96 rows hi/lo)
// is shared in smem; each warp covers 24 of 96 N-cols with full K=256.
#define U_WHI 0
#define U_WLO 50688            // 96*528
#define U_HA_HI 101376         // 16*528 = 8448 each
#define U_HA_LO 109824
#define U_HB_HI 118272
#define U_HB_LO 126720
#define U_GHA 135168           // 16*97*4 = 6208
#define U_GHB 141376
#define U_SM_TOTAL 147584
#define USTRIDE 528

__global__ void __launch_bounds__(256, 1) gru_persist(
    const float* __restrict__ GI_,
    const __nv_bfloat16* __restrict__ whh_hi,
    const __nv_bfloat16* __restrict__ whh_lo,
    const float* __restrict__ bhh,
    __nv_bfloat16* __restrict__ HHI_,
    __nv_bfloat16* __restrict__ HLO_,
    unsigned int* __restrict__ flags)
{
    extern __shared__ char sm[];
    const uint32_t smb = smem_u32(sm);
    const int tid = threadIdx.x;
    const int lane = tid & 31;
    const int wid = tid >> 5;
    const int grpB = wid >> 2;        // 0 = chain A, 1 = chain B
    const int gtid = tid & 127;       // thread id within warp-group
    const int wn = wid & 3;           // 0..3: N quarter (24 cols of 96)
    const int cta = blockIdx.x;
    const int grp = cta >> 3;         // 0..7
    const int kq  = cta & 7;          // 0..7
    const int b0 = grp * 32;
    const int k0 = kq * 32;
    const int barid = 1 + grpB;

    float* GHg = (float*)(sm + (grpB ? U_GHB : U_GHA));
    const uint32_t hHiBuf = smb + (grpB ? U_HB_HI : U_HA_HI);
    const uint32_t hLoBuf = smb + (grpB ? U_HB_LO : U_HA_LO);
    const int bOff = grpB ? 16 : 0;

    // ---- load W slice once: 96 rows (3 gates x 32 k-offsets), hi+lo ----
    for (int i = tid; i < 3072; i += 256) {
        int j = i >> 5;
        int c = i & 31;
        int gate = j >> 5, jr = j & 31;
        size_t soff = (size_t)(gate * 256 + k0 + jr) * 256 + c * 8;
        uint32_t d = (uint32_t)(j * USTRIDE + c * 16);
        cp16(smb + U_WHI + d, whh_hi + soff);
        cp16(smb + U_WLO + d, whh_lo + soff);
    }
    CP_COMMIT();

    {   // zero both GH buffers
        float* GA = (float*)(sm + U_GHA);
        float* GB = (float*)(sm + U_GHB);
        for (int i = tid; i < 16 * 97; i += 256) { GA[i] = 0.f; GB[i] = 0.f; }
    }

    // ---- per-thread gate constants: 4 outputs per thread (512/group) ----
    int bloc[4], kloc[4];
    size_t off_o[4], gio[4];
    float brr[4], brz[4], brn[4], hp[4];
    #pragma unroll
    for (int i = 0; i < 4; i++) {
        int idx = gtid + 128 * i;
        int b = idx >> 5, ko = idx & 31;
        bloc[i] = b; kloc[i] = ko;
        int kg = k0 + ko;
        off_o[i] = (size_t)(b0 + bOff + b) * 256 + kg;
        gio[i] = (size_t)(b0 + bOff + b) * 768 + kg;
        brr[i] = bhh[kg];
        brz[i] = bhh[256 + kg];
        brn[i] = bhh[512 + kg];
        hp[i] = 0.f;
    }

    // ---- mma addressing (full K=256 per warp, 24 N-cols) ----
    const uint32_t a_row = (uint32_t)(lane & 15);
    const uint32_t a_kb  = (uint32_t)((lane >> 4) * 16);
    const uint32_t b_row = (uint32_t)(((lane >> 4) & 1) * 8 + (lane & 7));
    const uint32_t b_kb  = (uint32_t)(((lane >> 3) & 1) * 16);
    const uint32_t b2_row = (uint32_t)(lane & 7);
    const uint32_t b2_kb  = (uint32_t)(((lane >> 3) & 1) * 16);

    const uint32_t aHi = hHiBuf + a_row * USTRIDE + a_kb;
    const uint32_t aLo = hLoBuf + a_row * USTRIDE + a_kb;
    const uint32_t bBaseHi4 = smb + U_WHI + (uint32_t)(wn * 24 + b_row) * USTRIDE + b_kb;
    const uint32_t bBaseLo4 = smb + U_WLO + (uint32_t)(wn * 24 + b_row) * USTRIDE + b_kb;
    const uint32_t bBaseHi2 = smb + U_WHI + (uint32_t)(wn * 24 + 16 + b2_row) * USTRIDE + b2_kb;
    const uint32_t bBaseLo2 = smb + U_WLO + (uint32_t)(wn * 24 + 16 + b2_row) * USTRIDE + b2_kb;

    // flag addresses (padded to 128B per flag)
    unsigned int* myflag = flags + (cta * 2 + grpB) * 32;
    unsigned int* poll   = flags + (((grp * GRP) + (gtid & 7)) * 2 + grpB) * 32;

    auto do_mma = [&]() {
        float acc[3][4];
        #pragma unroll
        for (int i = 0; i < 3; i++)
            #pragma unroll
            for (int e = 0; e < 4; e++) acc[i][e] = 0.f;

        #pragma unroll 4
        for (int ks = 0; ks < 16; ks++) {
            const uint32_t koff = (uint32_t)(ks * 32);
            uint32_t a[4], bh[3][2], bl[3][2], r4[4];

            ldsm4(a, aHi + koff);
            ldsm4(r4, bBaseHi4 + koff);
            bh[0][0] = r4[0]; bh[0][1] = r4[1]; bh[1][0] = r4[2]; bh[1][1] = r4[3];
            ldsm2(bh[2], bBaseHi2 + koff);
            #pragma unroll
            for (int nt = 0; nt < 3; nt++) mma16816(acc[nt], a, bh[nt]);

            ldsm4(r4, bBaseLo4 + koff);
            bl[0][0] = r4[0]; bl[0][1] = r4[1]; bl[1][0] = r4[2]; bl[1][1] = r4[3];
            ldsm2(bl[2], bBaseLo2 + koff);
            #pragma unroll
            for (int nt = 0; nt < 3; nt++) mma16816(acc[nt], a, bl[nt]);

            ldsm4(a, aLo + koff);
            #pragma unroll
            for (int nt = 0; nt < 3; nt++) mma16816(acc[nt], a, bh[nt]);
        }
        const int r0 = lane >> 2;
        const int cc = (lane & 3) * 2;
        #pragma unroll
        for (int nt = 0; nt < 3; nt++) {
            int col = wn * 24 + nt * 8 + cc;
            GHg[r0 * 97 + col]           = acc[nt][0];
            GHg[r0 * 97 + col + 1]       = acc[nt][1];
            GHg[(r0 + 8) * 97 + col]     = acc[nt][2];
            GHg[(r0 + 8) * 97 + col + 1] = acc[nt][3];
        }
    };

    float ir[4], iz[4], in_[4];
    auto prefetch_gi = [&](int t) {
        const float* gin = GI_ + (size_t)t * (BB * 768);
        #pragma unroll
        for (int i = 0; i < 4; i++) {
            ir[i]  = __ldg(gin + gio[i]);
            iz[i]  = __ldg(gin + gio[i] + 256);
            in_[i] = __ldg(gin + gio[i] + 512);
        }
    };

    auto do_gates = [&](int t) {
        __nv_bfloat16* hoh = HHI_ + (size_t)t * (BB * HH);
        __nv_bfloat16* hol = HLO_ + (size_t)t * (BB * HH);
        #pragma unroll
        for (int i = 0; i < 4; i++) {
            int b = bloc[i], ko = kloc[i];
            float hr = GHg[b * 97 + ko]      + brr[i];
            float hz = GHg[b * 97 + 32 + ko] + brz[i];
            float hn = GHg[b * 97 + 64 + ko] + brn[i];

            float r = 1.f / (1.f + __expf(-(ir[i] + hr)));
            float z = 1.f / (1.f + __expf(-(iz[i] + hz)));
            float n = tanhf(in_[i] + r * hn);
            float hnew = (1.f - z) * n + z * hp[i];
            hp[i] = hnew;

            __nv_bfloat16 hh = __float2bfloat16(hnew);
            hoh[off_o[i]] = hh;
            hol[off_o[i]] = __float2bfloat16(hnew - __bfloat162float(hh));
        }
    };

    auto load_h = [&](int t) {
        const __nv_bfloat16* hph = HHI_ + (size_t)t * (BB * HH);
        const __nv_bfloat16* hpl = HLO_ + (size_t)t * (BB * HH);
        #pragma unroll
        for (int i = 0; i < 4; i++) {
            int idx = gtid + 128 * i;      // 0..511
            int r = idx >> 5;              // 0..15
            int c = idx & 31;
            size_t soff = (size_t)(b0 + bOff + r) * 256 + c * 8;
            uint32_t d = (uint32_t)(r * USTRIDE + c * 16);
            cp16(hHiBuf + d, hph + soff);
            cp16(hLoBuf + d, hpl + soff);
        }
        CP_COMMIT();
    };

    auto signal_spin = [&](unsigned int target) {
        BARX(barid);
        if (gtid == 0) {
            asm volatile("st.release.gpu.u32 [%0], %1;"
                :: "l"(myflag), "r"(target) : "memory");
        }
        if (gtid < GRP) {
            unsigned int v;
            do {
                asm volatile("ld.acquire.gpu.u32 %0, [%1];"
                    : "=r"(v) : "l"(poll) : "memory");
            } while (v < target);
        }
        BARX(barid);
    };

    // ---- init sync: W + GH zeros visible to all ----
    CP_WAIT0();
    __syncthreads();

    // ---- prologue (t = 0): gates with gh = 0 ----
    prefetch_gi(0);
    do_gates(0);
    prefetch_gi(1);
    signal_spin(1u);
    load_h(0);

    // ---- main loop (independent per warp-group) ----
    for (int t = 1; t < TT; t++) {
        CP_WAIT0();
        BARX(barid);
        do_mma();
        BARX(barid);
        do_gates(t);
        if (t + 1 < TT) {
            prefetch_gi(t + 1);
            signal_spin((unsigned int)(t + 1));
            load_h(t);
        }
    }
}

// -------------------- fc2b head -------------------------------------------
__global__ void __launch_bounds__(256, 2) head_gemm(
    const float* __restrict__ A,
    const float* __restrict__ Wb,
    const float* __restrict__ bias,
    float* __restrict__ out, int M)
{
    __shared__ float Ws[18][512];
    const int tid = threadIdx.x;
    #pragma unroll
    for (int i = 0; i < 9; i++) {
        int idx = tid + 256 * i;
        ((float4*)&Ws[0][0])[idx] = ((const float4*)Wb)[idx];
    }
    __syncthreads();

    const size_t mbase = (size_t)blockIdx.x * 1024 + tid;

    float acc[4][18];
    #pragma unroll
    for (int i = 0; i < 4; i++)
        #pragma unroll
        for (int j = 0; j < 18; j++) acc[i][j] = 0.f;

    for (int k4 = 0; k4 < 128; k4++) {
        float4 a[4];
        #pragma unroll
        for (int i = 0; i < 4; i++)
            a[i] = *(const float4*)&A[(mbase + 256 * i) * 512 + k4 * 4];
        #pragma unroll
        for (int j = 0; j < 18; j++) {
            float4 w = *(const float4*)&Ws[j][k4 * 4];
            #pragma unroll
            for (int i = 0; i < 4; i++) {
                acc[i][j] += a[i].x * w.x;
                acc[i][j] += a[i].y * w.y;
                acc[i][j] += a[i].z * w.z;
                acc[i][j] += a[i].w * w.w;
            }
        }
    }

    #pragma unroll
    for (int i = 0; i < 4; i++) {
        size_t row = mbase + 256 * i;
        #pragma unroll
        for (int j = 0; j < 18; j++)
            out[row * 18 + j] = acc[i][j] + bias[j];
    }
}

// -------------------- launch ------------------------------------------------
extern "C" void kernel_launch(void* const* d_in, const int* in_sizes, int n_in,
                              void* d_out, int out_size)
{
    (void)in_sizes; (void)n_in; (void)out_size;
    const float* x    = (const float*)d_in[0];
    const float* W1a  = (const float*)d_in[1];
    const float* b1a  = (const float*)d_in[2];
    const float* W1b  = (const float*)d_in[3];
    const float* b1b  = (const float*)d_in[4];
    const float* Wih  = (const float*)d_in[5];
    const float* bih  = (const float*)d_in[6];
    const float* Whh  = (const float*)d_in[7];
    const float* bhh  = (const float*)d_in[8];
    const float* W2a  = (const float*)d_in[9];
    const float* b2a  = (const float*)d_in[10];
    const float* W2b  = (const float*)d_in[11];
    const float* b2b  = (const float*)d_in[12];
    float* out = (float*)d_out;

    float *buf1, *GI;
    __nv_bfloat16 *XHI, *XLO, *A1HI, *A1LO, *A2HI, *A2LO, *HHI, *HLO;
    __nv_bfloat16 *W1AHI, *W1ALO, *W1BHI, *W1BLO, *WIHHI, *WIHLO, *W2AHI, *W2ALO, *WHHHI, *WHHLO;
    unsigned int* FLAGS;

    cudaGetSymbolAddress((void**)&buf1, d_buf1);
    cudaGetSymbolAddress((void**)&GI,   d_GI);
    cudaGetSymbolAddress((void**)&XHI,  d_XHI);  cudaGetSymbolAddress((void**)&XLO,  d_XLO);
    cudaGetSymbolAddress((void**)&A1HI, d_A1HI); cudaGetSymbolAddress((void**)&A1LO, d_A1LO);
    cudaGetSymbolAddress((void**)&A2HI, d_A2HI); cudaGetSymbolAddress((void**)&A2LO, d_A2LO);
    cudaGetSymbolAddress((void**)&HHI,  d_HHI);  cudaGetSymbolAddress((void**)&HLO,  d_HLO);
    cudaGetSymbolAddress((void**)&W1AHI, d_W1AHI); cudaGetSymbolAddress((void**)&W1ALO, d_W1ALO);
    cudaGetSymbolAddress((void**)&W1BHI, d_W1BHI); cudaGetSymbolAddress((void**)&W1BLO, d_W1BLO);
    cudaGetSymbolAddress((void**)&WIHHI, d_WIHHI); cudaGetSymbolAddress((void**)&WIHLO, d_WIHLO);
    cudaGetSymbolAddress((void**)&W2AHI, d_W2AHI); cudaGetSymbolAddress((void**)&W2ALO, d_W2ALO);
    cudaGetSymbolAddress((void**)&WHHHI, d_WHHHI); cudaGetSymbolAddress((void**)&WHHLO, d_WHHLO);
    cudaGetSymbolAddress((void**)&FLAGS, d_flags);

    cudaFuncSetAttribute(gemm_bf<true, 0>,  cudaFuncAttributeMaxDynamicSharedMemorySize, G_SM_TOTAL);
    cudaFuncSetAttribute(gemm_bf<true, 1>,  cudaFuncAttributeMaxDynamicSharedMemorySize, G_SM_TOTAL);
    cudaFuncSetAttribute(gemm_bf<false, 0>, cudaFuncAttributeMaxDynamicSharedMemorySize, G_SM_TOTAL);
    cudaFuncSetAttribute(gru_persist, cudaFuncAttributeMaxDynamicSharedMemorySize, U_SM_TOTAL);

    const int M = MTOT;

    // ---- pre-split inputs/weights to bf16 hi/lo ----
    split_f32<<<(M * 256 / 4 + 255) / 256, 256>>>((const float4*)x, (uint2*)XHI, (uint2*)XLO, M * 256 / 4);
    split_f32<<<128, 256>>>((const float4*)W1a, (uint2*)W1AHI, (uint2*)W1ALO, 512 * 256 / 4);
    split_f32<<<128, 256>>>((const float4*)W1b, (uint2*)W1BHI, (uint2*)W1BLO, 256 * 512 / 4);
    split_f32<<<192, 256>>>((const float4*)Wih, (uint2*)WIHHI, (uint2*)WIHLO, 768 * 256 / 4);
    split_f32<<<128, 256>>>((const float4*)W2a, (uint2*)W2AHI, (uint2*)W2ALO, 512 * 256 / 4);
    split_f32<<<192, 256>>>((const float4*)Whh, (uint2*)WHHHI, (uint2*)WHHLO, 768 * 256 / 4);

    zero_u32<<<16, 256>>>((uint32_t*)FLAGS, NCTA_GRU * 2 * 32);

    // ---- batched GEMMs ----
    gemm_bf<true, 1><<<dim3(4, M / 128), 256, G_SM_TOTAL>>>(
        XHI, XLO, W1AHI, W1ALO, b1a, nullptr, A1HI, A1LO, M, 512, 256);
    gemm_bf<true, 1><<<dim3(2, M / 128), 256, G_SM_TOTAL>>>(
        A1HI, A1LO, W1BHI, W1BLO, b1b, nullptr, A2HI, A2LO, M, 256, 512);
    gemm_bf<false, 0><<<dim3(6, M / 128), 256, G_SM_TOTAL>>>(
        A2HI, A2LO, WIHHI, WIHLO, bih, GI, nullptr, nullptr, M, 768, 256);

    // ---- persistent GRU: warp-specialized dual chain ----
    gru_persist<<<NCTA_GRU, 256, U_SM_TOTAL>>>(GI, WHHHI, WHHLO, bhh, HHI, HLO, FLAGS);

    // fc2a + head
    gemm_bf<true, 0><<<dim3(4, M / 128), 256, G_SM_TOTAL>>>(
        HHI, HLO, W2AHI, W2ALO, b2a, buf1, nullptr, nullptr, M, 512, 256);
    head_gemm<<<M / 1024, 256>>>(buf1, W2b, b2b, out, M);
}

// round 11
// speedup vs baseline: 1.5794x; 1.1233x over previous
#include <cuda_runtime.h>
#include <cuda_bf16.h>
#include <math.h>
#include <stdint.h>

// Problem constants
#define TT 512
#define BB 256
#define IN_DIM 256
#define H1 512
#define HH 256
#define OUT_DIM 18
#define MTOT (TT*BB)   // 131072
#define NCTA_GRU 64
#define NCTA_ALL 148
#define NWORK (NCTA_ALL - NCTA_GRU)   // 84
#define GRP 8          // CTAs per sync group

// -------------------- scratch (static device globals; no allocs) -----------
__device__ float d_buf1[(size_t)MTOT * 512];     // fc2a out (fp32, for head)
__device__ float d_GI  [(size_t)MTOT * 768];     // gi fp32

__device__ __nv_bfloat16 d_XHI[(size_t)MTOT * 256], d_XLO[(size_t)MTOT * 256];
__device__ __nv_bfloat16 d_A1HI[(size_t)MTOT * 512], d_A1LO[(size_t)MTOT * 512];
__device__ __nv_bfloat16 d_A2HI[(size_t)MTOT * 256], d_A2LO[(size_t)MTOT * 256];
__device__ __nv_bfloat16 d_HHI[(size_t)MTOT * 256], d_HLO[(size_t)MTOT * 256];

__device__ __nv_bfloat16 d_W1AHI[512*256], d_W1ALO[512*256];
__device__ __nv_bfloat16 d_W1BHI[256*512], d_W1BLO[256*512];
__device__ __nv_bfloat16 d_WIHHI[768*256], d_WIHLO[768*256];
__device__ __nv_bfloat16 d_W2AHI[512*256], d_W2ALO[512*256];
__device__ __nv_bfloat16 d_WHHHI[768*256], d_WHHLO[768*256];

// padded flags: one 128B line per (cta, chain)
__device__ unsigned int d_flags[NCTA_GRU * 2 * 32];

// ==================== helpers ==============================================
__device__ __forceinline__ uint32_t smem_u32(const void* p) {
    uint32_t a;
    asm("{ .reg .u64 t; cvta.to.shared.u64 t, %1; cvt.u32.u64 %0, t; }"
        : "=r"(a) : "l"(p));
    return a;
}

__device__ __forceinline__ void ldsm4(uint32_t* r, uint32_t addr) {
    asm volatile("ldmatrix.sync.aligned.m8n8.x4.shared.b16 {%0,%1,%2,%3}, [%4];"
        : "=r"(r[0]), "=r"(r[1]), "=r"(r[2]), "=r"(r[3]) : "r"(addr));
}
__device__ __forceinline__ void ldsm2(uint32_t* r, uint32_t addr) {
    asm volatile("ldmatrix.sync.aligned.m8n8.x2.shared.b16 {%0,%1}, [%2];"
        : "=r"(r[0]), "=r"(r[1]) : "r"(addr));
}

__device__ __forceinline__ void mma16816(float* c, const uint32_t* a, const uint32_t* b) {
    asm volatile(
        "mma.sync.aligned.m16n8k16.row.col.f32.bf16.bf16.f32 "
        "{%0,%1,%2,%3}, {%4,%5,%6,%7}, {%8,%9}, {%0,%1,%2,%3};"
        : "+f"(c[0]), "+f"(c[1]), "+f"(c[2]), "+f"(c[3])
        : "r"(a[0]), "r"(a[1]), "r"(a[2]), "r"(a[3]), "r"(b[0]), "r"(b[1]));
}

__device__ __forceinline__ void cp16(uint32_t dst, const void* src) {
    asm volatile("cp.async.cg.shared.global [%0], [%1], 16;"
        :: "r"(dst), "l"(src) : "memory");
}
#define CP_COMMIT() asm volatile("cp.async.commit_group;" ::: "memory")
#define CP_WAIT0()  asm volatile("cp.async.wait_group 0;" ::: "memory")
#define CP_WAIT1()  asm volatile("cp.async.wait_group 1;" ::: "memory")
#define BARX(id)    asm volatile("bar.sync %0, 128;" :: "r"(id) : "memory")

__device__ __forceinline__ void split_bf16x4(float4 v, uint2& hv, uint2& lv) {
    __nv_bfloat16 h0 = __float2bfloat16(v.x);
    __nv_bfloat16 h1 = __float2bfloat16(v.y);
    __nv_bfloat16 h2 = __float2bfloat16(v.z);
    __nv_bfloat16 h3 = __float2bfloat16(v.w);
    __nv_bfloat16 l0 = __float2bfloat16(v.x - __bfloat162float(h0));
    __nv_bfloat16 l1 = __float2bfloat16(v.y - __bfloat162float(h1));
    __nv_bfloat16 l2 = __float2bfloat16(v.z - __bfloat162float(h2));
    __nv_bfloat16 l3 = __float2bfloat16(v.w - __bfloat162float(h3));
    hv.x = (uint32_t)__bfloat16_as_ushort(h0) | ((uint32_t)__bfloat16_as_ushort(h1) << 16);
    hv.y = (uint32_t)__bfloat16_as_ushort(h2) | ((uint32_t)__bfloat16_as_ushort(h3) << 16);
    lv.x = (uint32_t)__bfloat16_as_ushort(l0) | ((uint32_t)__bfloat16_as_ushort(l1) << 16);
    lv.y = (uint32_t)__bfloat16_as_ushort(l2) | ((uint32_t)__bfloat16_as_ushort(l3) << 16);
}

__device__ __forceinline__ uint32_t pack_hi2(float a, float b, uint32_t& lo) {
    __nv_bfloat16 ha = __float2bfloat16(a);
    __nv_bfloat16 hb = __float2bfloat16(b);
    __nv_bfloat16 la = __float2bfloat16(a - __bfloat162float(ha));
    __nv_bfloat16 lb = __float2bfloat16(b - __bfloat162float(hb));
    lo = (uint32_t)__bfloat16_as_ushort(la) | ((uint32_t)__bfloat16_as_ushort(lb) << 16);
    return (uint32_t)__bfloat16_as_ushort(ha) | ((uint32_t)__bfloat16_as_ushort(hb) << 16);
}

// -------------------- split / zero kernels ---------------------------------
__global__ void split_f32(const float4* __restrict__ in,
                          uint2* __restrict__ hi, uint2* __restrict__ lo, int n4) {
    int i = blockIdx.x * blockDim.x + threadIdx.x;
    if (i < n4) {
        uint2 h, l;
        split_bf16x4(in[i], h, l);
        hi[i] = h; lo[i] = l;
    }
}
__global__ void zero_u32(uint32_t* p, int n) {
    int i = blockIdx.x * blockDim.x + threadIdx.x;
    if (i < n) p[i] = 0u;
}

// ==================== pipelined bf16-split GEMM (unchanged, passing) ========
#define GROW 144
#define G_AHI 0
#define G_ALO 18432
#define G_BHI 36864
#define G_BLO 55296
#define G_STAGE 73728
#define G_SM_TOTAL (2*G_STAGE)

template<bool RELU, int OUTM>
__global__ void __launch_bounds__(256, 1) gemm_bf(
    const __nv_bfloat16* __restrict__ Ahi, const __nv_bfloat16* __restrict__ Alo,
    const __nv_bfloat16* __restrict__ Bhi, const __nv_bfloat16* __restrict__ Blo,
    const float* __restrict__ bias,
    float* __restrict__ C, __nv_bfloat16* __restrict__ Chi, __nv_bfloat16* __restrict__ Clo,
    int M, int N, int K)
{
    extern __shared__ char sm[];
    const uint32_t smb = smem_u32(sm);
    const int tid = threadIdx.x;
    const int lane = tid & 31;
    const int wid = tid >> 5;
    const int wm = wid & 1;
    const int wn = wid >> 1;
    const int m0 = blockIdx.y * 128;
    const int n0 = blockIdx.x * 128;

    float acc[4][4][4];
    #pragma unroll
    for (int i = 0; i < 4; i++)
        #pragma unroll
        for (int j = 0; j < 4; j++)
            #pragma unroll
            for (int e = 0; e < 4; e++) acc[i][j][e] = 0.f;

    const uint32_t a_row = (uint32_t)(lane & 15);
    const uint32_t a_kb  = (uint32_t)((lane >> 4) * 16);
    const uint32_t b_row = (uint32_t)(((lane >> 4) & 1) * 8 + (lane & 7));
    const uint32_t b_kb  = (uint32_t)(((lane >> 3) & 1) * 16);

    const int nchunks = K >> 6;

    auto load_chunk = [&](int kc, int st) {
        const int kb = kc << 6;
        const uint32_t base = smb + (uint32_t)st * G_STAGE;
        #pragma unroll
        for (int j = 0; j < 4; j++) {
            int idx = tid + 256 * j;
            int r = idx >> 3;
            int c = idx & 7;
            size_t aoff = (size_t)(m0 + r) * K + kb + c * 8;
            size_t boff = (size_t)(n0 + r) * K + kb + c * 8;
            uint32_t d = (uint32_t)(r * GROW + c * 16);
            cp16(base + G_AHI + d, Ahi + aoff);
            cp16(base + G_ALO + d, Alo + aoff);
            cp16(base + G_BHI + d, Bhi + boff);
            cp16(base + G_BLO + d, Blo + boff);
        }
        CP_COMMIT();
    };

    load_chunk(0, 0);

    for (int kc = 0; kc < nchunks; kc++) {
        const int st = kc & 1;
        if (kc + 1 < nchunks) { load_chunk(kc + 1, st ^ 1); CP_WAIT1(); }
        else                  { CP_WAIT0(); }
        __syncthreads();

        const uint32_t base = smb + (uint32_t)st * G_STAGE;
        #pragma unroll
        for (int ks = 0; ks < 4; ks++) {
            const uint32_t koff = (uint32_t)(ks * 32);
            uint32_t afr[4][4], bhi2[4][2], blo2[4][2];

            #pragma unroll
            for (int mt = 0; mt < 4; mt++)
                ldsm4(afr[mt], base + G_AHI + (uint32_t)(wm*64 + mt*16 + a_row)*GROW + koff + a_kb);
            #pragma unroll
            for (int g = 0; g < 2; g++) {
                uint32_t r4[4];
                ldsm4(r4, base + G_BHI + (uint32_t)(wn*32 + g*16 + b_row)*GROW + koff + b_kb);
                bhi2[g*2  ][0] = r4[0]; bhi2[g*2  ][1] = r4[1];
                bhi2[g*2+1][0] = r4[2]; bhi2[g*2+1][1] = r4[3];
            }
            #pragma unroll
            for (int mt = 0; mt < 4; mt++)
                #pragma unroll
                for (int nt = 0; nt < 4; nt++)
                    mma16816(acc[mt][nt], afr[mt], bhi2[nt]);

            #pragma unroll
            for (int g = 0; g < 2; g++) {
                uint32_t r4[4];
                ldsm4(r4, base + G_BLO + (uint32_t)(wn*32 + g*16 + b_row)*GROW + koff + b_kb);
                blo2[g*2  ][0] = r4[0]; blo2[g*2  ][1] = r4[1];
                blo2[g*2+1][0] = r4[2]; blo2[g*2+1][1] = r4[3];
            }
            #pragma unroll
            for (int mt = 0; mt < 4; mt++)
                #pragma unroll
                for (int nt = 0; nt < 4; nt++)
                    mma16816(acc[mt][nt], afr[mt], blo2[nt]);

            #pragma unroll
            for (int mt = 0; mt < 4; mt++)
                ldsm4(afr[mt], base + G_ALO + (uint32_t)(wm*64 + mt*16 + a_row)*GROW + koff + a_kb);
            #pragma unroll
            for (int mt = 0; mt < 4; mt++)
                #pragma unroll
                for (int nt = 0; nt < 4; nt++)
                    mma16816(acc[mt][nt], afr[mt], bhi2[nt]);
        }
        __syncthreads();
    }

    const int r_in = lane >> 2;
    const int c_in = (lane & 3) * 2;
    #pragma unroll
    for (int mt = 0; mt < 4; mt++) {
        #pragma unroll
        for (int nt = 0; nt < 4; nt++) {
            int col = n0 + wn * 32 + nt * 8 + c_in;
            float b0 = bias[col], b1 = bias[col + 1];
            int row0 = m0 + wm * 64 + mt * 16 + r_in;
            float v00 = acc[mt][nt][0] + b0, v01 = acc[mt][nt][1] + b1;
            float v10 = acc[mt][nt][2] + b0, v11 = acc[mt][nt][3] + b1;
            if (RELU) {
                v00 = fmaxf(v00, 0.f); v01 = fmaxf(v01, 0.f);
                v10 = fmaxf(v10, 0.f); v11 = fmaxf(v11, 0.f);
            }
            if (OUTM == 0) {
                float2 p0, p1;
                p0.x = v00; p0.y = v01; p1.x = v10; p1.y = v11;
                *(float2*)&C[(size_t)row0 * N + col] = p0;
                *(float2*)&C[(size_t)(row0 + 8) * N + col] = p1;
            } else {
                uint32_t lo0, lo1;
                uint32_t hi0 = pack_hi2(v00, v01, lo0);
                uint32_t hi1 = pack_hi2(v10, v11, lo1);
                *(uint32_t*)&Chi[(size_t)row0 * N + col] = hi0;
                *(uint32_t*)&Clo[(size_t)row0 * N + col] = lo0;
                *(uint32_t*)&Chi[(size_t)(row0 + 8) * N + col] = hi1;
                *(uint32_t*)&Clo[(size_t)(row0 + 8) * N + col] = lo1;
            }
        }
    }
}

// ==================== persistent GRU + fused fc2a workers ===================
// 148 CTAs: 0-63 GRU (8 groups x 8 CTAs, warp-specialized dual chain, R10),
// 64-147 fc2a workers consuming h_t tiles as producer flags publish them.
#define U_WHI 0
#define U_WLO 50688            // 96*528
#define U_HA_HI 101376         // 16*528 = 8448 each
#define U_HA_LO 109824
#define U_HB_HI 118272
#define U_HB_LO 126720
#define U_GHA 135168           // 16*97*4 = 6208
#define U_GHB 141376
#define U_SM_TOTAL 147584      // >= G_SM_TOTAL (147456) for worker path
#define USTRIDE 528

__global__ void __launch_bounds__(256, 1) gru_persist(
    const float* __restrict__ GI_,
    const __nv_bfloat16* __restrict__ whh_hi,
    const __nv_bfloat16* __restrict__ whh_lo,
    const float* __restrict__ bhh,
    __nv_bfloat16* __restrict__ HHI_,
    __nv_bfloat16* __restrict__ HLO_,
    unsigned int* __restrict__ flags,
    const __nv_bfloat16* __restrict__ w2a_hi,
    const __nv_bfloat16* __restrict__ w2a_lo,
    const float* __restrict__ b2a,
    float* __restrict__ buf1)
{
    extern __shared__ char sm[];
    const uint32_t smb = smem_u32(sm);
    const int tid = threadIdx.x;
    const int lane = tid & 31;
    const int wid = tid >> 5;
    const int cta = blockIdx.x;

    if (cta < NCTA_GRU) {
        // ==================== GRU producer path (R10) =======================
        const int grpB = wid >> 2;        // 0 = chain A, 1 = chain B
        const int gtid = tid & 127;
        const int wn = wid & 3;
        const int grp = cta >> 3;
        const int kq  = cta & 7;
        const int b0 = grp * 32;
        const int k0 = kq * 32;
        const int barid = 1 + grpB;

        float* GHg = (float*)(sm + (grpB ? U_GHB : U_GHA));
        const uint32_t hHiBuf = smb + (grpB ? U_HB_HI : U_HA_HI);
        const uint32_t hLoBuf = smb + (grpB ? U_HB_LO : U_HA_LO);
        const int bOff = grpB ? 16 : 0;

        for (int i = tid; i < 3072; i += 256) {
            int j = i >> 5;
            int c = i & 31;
            int gate = j >> 5, jr = j & 31;
            size_t soff = (size_t)(gate * 256 + k0 + jr) * 256 + c * 8;
            uint32_t d = (uint32_t)(j * USTRIDE + c * 16);
            cp16(smb + U_WHI + d, whh_hi + soff);
            cp16(smb + U_WLO + d, whh_lo + soff);
        }
        CP_COMMIT();

        {
            float* GA = (float*)(sm + U_GHA);
            float* GB = (float*)(sm + U_GHB);
            for (int i = tid; i < 16 * 97; i += 256) { GA[i] = 0.f; GB[i] = 0.f; }
        }

        int bloc[4], kloc[4];
        size_t off_o[4], gio[4];
        float brr[4], brz[4], brn[4], hp[4];
        #pragma unroll
        for (int i = 0; i < 4; i++) {
            int idx = gtid + 128 * i;
            int b = idx >> 5, ko = idx & 31;
            bloc[i] = b; kloc[i] = ko;
            int kg = k0 + ko;
            off_o[i] = (size_t)(b0 + bOff + b) * 256 + kg;
            gio[i] = (size_t)(b0 + bOff + b) * 768 + kg;
            brr[i] = bhh[kg];
            brz[i] = bhh[256 + kg];
            brn[i] = bhh[512 + kg];
            hp[i] = 0.f;
        }

        const uint32_t a_row = (uint32_t)(lane & 15);
        const uint32_t a_kb  = (uint32_t)((lane >> 4) * 16);
        const uint32_t b_row = (uint32_t)(((lane >> 4) & 1) * 8 + (lane & 7));
        const uint32_t b_kb  = (uint32_t)(((lane >> 3) & 1) * 16);
        const uint32_t b2_row = (uint32_t)(lane & 7);
        const uint32_t b2_kb  = (uint32_t)(((lane >> 3) & 1) * 16);

        const uint32_t aHi = hHiBuf + a_row * USTRIDE + a_kb;
        const uint32_t aLo = hLoBuf + a_row * USTRIDE + a_kb;
        const uint32_t bBaseHi4 = smb + U_WHI + (uint32_t)(wn * 24 + b_row) * USTRIDE + b_kb;
        const uint32_t bBaseLo4 = smb + U_WLO + (uint32_t)(wn * 24 + b_row) * USTRIDE + b_kb;
        const uint32_t bBaseHi2 = smb + U_WHI + (uint32_t)(wn * 24 + 16 + b2_row) * USTRIDE + b2_kb;
        const uint32_t bBaseLo2 = smb + U_WLO + (uint32_t)(wn * 24 + 16 + b2_row) * USTRIDE + b2_kb;

        unsigned int* myflag = flags + (cta * 2 + grpB) * 32;
        unsigned int* poll   = flags + (((grp * GRP) + (gtid & 7)) * 2 + grpB) * 32;

        auto do_mma = [&]() {
            float acc[3][4];
            #pragma unroll
            for (int i = 0; i < 3; i++)
                #pragma unroll
                for (int e = 0; e < 4; e++) acc[i][e] = 0.f;

            #pragma unroll 4
            for (int ks = 0; ks < 16; ks++) {
                const uint32_t koff = (uint32_t)(ks * 32);
                uint32_t a[4], bh[3][2], bl[3][2], r4[4];

                ldsm4(a, aHi + koff);
                ldsm4(r4, bBaseHi4 + koff);
                bh[0][0] = r4[0]; bh[0][1] = r4[1]; bh[1][0] = r4[2]; bh[1][1] = r4[3];
                ldsm2(bh[2], bBaseHi2 + koff);
                #pragma unroll
                for (int nt = 0; nt < 3; nt++) mma16816(acc[nt], a, bh[nt]);

                ldsm4(r4, bBaseLo4 + koff);
                bl[0][0] = r4[0]; bl[0][1] = r4[1]; bl[1][0] = r4[2]; bl[1][1] = r4[3];
                ldsm2(bl[2], bBaseLo2 + koff);
                #pragma unroll
                for (int nt = 0; nt < 3; nt++) mma16816(acc[nt], a, bl[nt]);

                ldsm4(a, aLo + koff);
                #pragma unroll
                for (int nt = 0; nt < 3; nt++) mma16816(acc[nt], a, bh[nt]);
            }
            const int r0 = lane >> 2;
            const int cc = (lane & 3) * 2;
            #pragma unroll
            for (int nt = 0; nt < 3; nt++) {
                int col = wn * 24 + nt * 8 + cc;
                GHg[r0 * 97 + col]           = acc[nt][0];
                GHg[r0 * 97 + col + 1]       = acc[nt][1];
                GHg[(r0 + 8) * 97 + col]     = acc[nt][2];
                GHg[(r0 + 8) * 97 + col + 1] = acc[nt][3];
            }
        };

        float ir[4], iz[4], in_[4];
        auto prefetch_gi = [&](int t) {
            const float* gin = GI_ + (size_t)t * (BB * 768);
            #pragma unroll
            for (int i = 0; i < 4; i++) {
                ir[i]  = __ldg(gin + gio[i]);
                iz[i]  = __ldg(gin + gio[i] + 256);
                in_[i] = __ldg(gin + gio[i] + 512);
            }
        };

        auto do_gates = [&](int t) {
            __nv_bfloat16* hoh = HHI_ + (size_t)t * (BB * HH);
            __nv_bfloat16* hol = HLO_ + (size_t)t * (BB * HH);
            #pragma unroll
            for (int i = 0; i < 4; i++) {
                int b = bloc[i], ko = kloc[i];
                float hr = GHg[b * 97 + ko]      + brr[i];
                float hz = GHg[b * 97 + 32 + ko] + brz[i];
                float hn = GHg[b * 97 + 64 + ko] + brn[i];

                float r = 1.f / (1.f + __expf(-(ir[i] + hr)));
                float z = 1.f / (1.f + __expf(-(iz[i] + hz)));
                float n = tanhf(in_[i] + r * hn);
                float hnew = (1.f - z) * n + z * hp[i];
                hp[i] = hnew;

                __nv_bfloat16 hh = __float2bfloat16(hnew);
                hoh[off_o[i]] = hh;
                hol[off_o[i]] = __float2bfloat16(hnew - __bfloat162float(hh));
            }
        };

        auto load_h = [&](int t) {
            const __nv_bfloat16* hph = HHI_ + (size_t)t * (BB * HH);
            const __nv_bfloat16* hpl = HLO_ + (size_t)t * (BB * HH);
            #pragma unroll
            for (int i = 0; i < 4; i++) {
                int idx = gtid + 128 * i;
                int r = idx >> 5;
                int c = idx & 31;
                size_t soff = (size_t)(b0 + bOff + r) * 256 + c * 8;
                uint32_t d = (uint32_t)(r * USTRIDE + c * 16);
                cp16(hHiBuf + d, hph + soff);
                cp16(hLoBuf + d, hpl + soff);
            }
            CP_COMMIT();
        };

        auto signal_spin = [&](unsigned int target) {
            BARX(barid);
            if (gtid == 0) {
                asm volatile("st.release.gpu.u32 [%0], %1;"
                    :: "l"(myflag), "r"(target) : "memory");
            }
            if (gtid < GRP) {
                unsigned int v;
                do {
                    asm volatile("ld.acquire.gpu.u32 %0, [%1];"
                        : "=r"(v) : "l"(poll) : "memory");
                } while (v < target);
            }
            BARX(barid);
        };

        CP_WAIT0();
        __syncthreads();

        prefetch_gi(0);
        do_gates(0);
        prefetch_gi(1);
        signal_spin(1u);
        load_h(0);

        for (int t = 1; t < TT; t++) {
            CP_WAIT0();
            BARX(barid);
            do_mma();
            BARX(barid);
            do_gates(t);
            if (t + 1 < TT) {
                prefetch_gi(t + 1);
                signal_spin((unsigned int)(t + 1));
                load_h(t);
            }
        }
        // final publish so workers can consume h[T-1]
        BARX(barid);
        if (gtid == 0) {
            asm volatile("st.release.gpu.u32 [%0], %1;"
                :: "l"(myflag), "r"((unsigned int)TT) : "memory");
        }
    } else {
        // ==================== fc2a worker path ==============================
        const int wrk = cta - NCTA_GRU;
        const int wm = wid & 1;
        const int wn = wid >> 1;
        const uint32_t a_row = (uint32_t)(lane & 15);
        const uint32_t a_kb  = (uint32_t)((lane >> 4) * 16);
        const uint32_t b_row = (uint32_t)(((lane >> 4) & 1) * 8 + (lane & 7));
        const uint32_t b_kb  = (uint32_t)(((lane >> 3) & 1) * 16);
        const int r_in = lane >> 2;
        const int c_in = (lane & 3) * 2;

        const int nTiles = TT * 8;
        for (int tile = wrk; tile < nTiles; tile += NWORK) {
            const int t = tile >> 3;
            const int mhalf = (tile >> 2) & 1;
            const int nq = tile & 3;

            // wait for the 32 producer CTAs (both chains) of this b-half
            {
                const unsigned int target = (unsigned int)(t + 1);
                if (tid < 64) {
                    unsigned int* f = flags + (((mhalf * 32) + (tid >> 1)) * 2 + (tid & 1)) * 32;
                    unsigned int v;
                    do {
                        asm volatile("ld.acquire.gpu.u32 %0, [%1];"
                            : "=r"(v) : "l"(f) : "memory");
                    } while (v < target);
                }
                __syncthreads();
            }

            const size_t m0 = (size_t)t * 256 + (size_t)mhalf * 128;
            const int n0 = nq * 128;

            float acc[4][4][4];
            #pragma unroll
            for (int i = 0; i < 4; i++)
                #pragma unroll
                for (int j = 0; j < 4; j++)
                    #pragma unroll
                    for (int e = 0; e < 4; e++) acc[i][j][e] = 0.f;

            auto load_chunk = [&](int kc, int st) {
                const int kb = kc << 6;
                const uint32_t base = smb + (uint32_t)st * G_STAGE;
                #pragma unroll
                for (int j = 0; j < 4; j++) {
                    int idx = tid + 256 * j;
                    int r = idx >> 3;
                    int c = idx & 7;
                    size_t aoff = (m0 + r) * 256 + kb + c * 8;
                    size_t boff = (size_t)(n0 + r) * 256 + kb + c * 8;
                    uint32_t d = (uint32_t)(r * GROW + c * 16);
                    cp16(base + G_AHI + d, HHI_ + aoff);
                    cp16(base + G_ALO + d, HLO_ + aoff);
                    cp16(base + G_BHI + d, w2a_hi + boff);
                    cp16(base + G_BLO + d, w2a_lo + boff);
                }
                CP_COMMIT();
            };

            load_chunk(0, 0);
            for (int kc = 0; kc < 4; kc++) {
                const int st = kc & 1;
                if (kc + 1 < 4) { load_chunk(kc + 1, st ^ 1); CP_WAIT1(); }
                else            { CP_WAIT0(); }
                __syncthreads();

                const uint32_t base = smb + (uint32_t)st * G_STAGE;
                #pragma unroll
                for (int ks = 0; ks < 4; ks++) {
                    const uint32_t koff = (uint32_t)(ks * 32);
                    uint32_t afr[4][4], bhi2[4][2], blo2[4][2];

                    #pragma unroll
                    for (int mt = 0; mt < 4; mt++)
                        ldsm4(afr[mt], base + G_AHI + (uint32_t)(wm*64 + mt*16 + a_row)*GROW + koff + a_kb);
                    #pragma unroll
                    for (int g = 0; g < 2; g++) {
                        uint32_t r4[4];
                        ldsm4(r4, base + G_BHI + (uint32_t)(wn*32 + g*16 + b_row)*GROW + koff + b_kb);
                        bhi2[g*2  ][0] = r4[0]; bhi2[g*2  ][1] = r4[1];
                        bhi2[g*2+1][0] = r4[2]; bhi2[g*2+1][1] = r4[3];
                    }
                    #pragma unroll
                    for (int mt = 0; mt < 4; mt++)
                        #pragma unroll
                        for (int nt = 0; nt < 4; nt++)
                            mma16816(acc[mt][nt], afr[mt], bhi2[nt]);

                    #pragma unroll
                    for (int g = 0; g < 2; g++) {
                        uint32_t r4[4];
                        ldsm4(r4, base + G_BLO + (uint32_t)(wn*32 + g*16 + b_row)*GROW + koff + b_kb);
                        blo2[g*2  ][0] = r4[0]; blo2[g*2  ][1] = r4[1];
                        blo2[g*2+1][0] = r4[2]; blo2[g*2+1][1] = r4[3];
                    }
                    #pragma unroll
                    for (int mt = 0; mt < 4; mt++)
                        #pragma unroll
                        for (int nt = 0; nt < 4; nt++)
                            mma16816(acc[mt][nt], afr[mt], blo2[nt]);

                    #pragma unroll
                    for (int mt = 0; mt < 4; mt++)
                        ldsm4(afr[mt], base + G_ALO + (uint32_t)(wm*64 + mt*16 + a_row)*GROW + koff + a_kb);
                    #pragma unroll
                    for (int mt = 0; mt < 4; mt++)
                        #pragma unroll
                        for (int nt = 0; nt < 4; nt++)
                            mma16816(acc[mt][nt], afr[mt], bhi2[nt]);
                }
                __syncthreads();
            }

            // epilogue: bias + relu, fp32 to buf1 [M, 512]
            #pragma unroll
            for (int mt = 0; mt < 4; mt++) {
                #pragma unroll
                for (int nt = 0; nt < 4; nt++) {
                    int col = n0 + wn * 32 + nt * 8 + c_in;
                    float bb0 = b2a[col], bb1 = b2a[col + 1];
                    size_t row0 = m0 + wm * 64 + mt * 16 + r_in;
                    float2 p0, p1;
                    p0.x = fmaxf(acc[mt][nt][0] + bb0, 0.f);
                    p0.y = fmaxf(acc[mt][nt][1] + bb1, 0.f);
                    p1.x = fmaxf(acc[mt][nt][2] + bb0, 0.f);
                    p1.y = fmaxf(acc[mt][nt][3] + bb1, 0.f);
                    *(float2*)&buf1[row0 * 512 + col] = p0;
                    *(float2*)&buf1[(row0 + 8) * 512 + col] = p1;
                }
            }
        }
    }
}

// -------------------- fc2b head -------------------------------------------
__global__ void __launch_bounds__(256, 2) head_gemm(
    const float* __restrict__ A,
    const float* __restrict__ Wb,
    const float* __restrict__ bias,
    float* __restrict__ out, int M)
{
    __shared__ float Ws[18][512];
    const int tid = threadIdx.x;
    #pragma unroll
    for (int i = 0; i < 9; i++) {
        int idx = tid + 256 * i;
        ((float4*)&Ws[0][0])[idx] = ((const float4*)Wb)[idx];
    }
    __syncthreads();

    const size_t mbase = (size_t)blockIdx.x * 1024 + tid;

    float acc[4][18];
    #pragma unroll
    for (int i = 0; i < 4; i++)
        #pragma unroll
        for (int j = 0; j < 18; j++) acc[i][j] = 0.f;

    for (int k4 = 0; k4 < 128; k4++) {
        float4 a[4];
        #pragma unroll
        for (int i = 0; i < 4; i++)
            a[i] = *(const float4*)&A[(mbase + 256 * i) * 512 + k4 * 4];
        #pragma unroll
        for (int j = 0; j < 18; j++) {
            float4 w = *(const float4*)&Ws[j][k4 * 4];
            #pragma unroll
            for (int i = 0; i < 4; i++) {
                acc[i][j] += a[i].x * w.x;
                acc[i][j] += a[i].y * w.y;
                acc[i][j] += a[i].z * w.z;
                acc[i][j] += a[i].w * w.w;
            }
        }
    }

    #pragma unroll
    for (int i = 0; i < 4; i++) {
        size_t row = mbase + 256 * i;
        #pragma unroll
        for (int j = 0; j < 18; j++)
            out[row * 18 + j] = acc[i][j] + bias[j];
    }
}

// -------------------- launch ------------------------------------------------
extern "C" void kernel_launch(void* const* d_in, const int* in_sizes, int n_in,
                              void* d_out, int out_size)
{
    (void)in_sizes; (void)n_in; (void)out_size;
    const float* x    = (const float*)d_in[0];
    const float* W1a  = (const float*)d_in[1];
    const float* b1a  = (const float*)d_in[2];
    const float* W1b  = (const float*)d_in[3];
    const float* b1b  = (const float*)d_in[4];
    const float* Wih  = (const float*)d_in[5];
    const float* bih  = (const float*)d_in[6];
    const float* Whh  = (const float*)d_in[7];
    const float* bhh  = (const float*)d_in[8];
    const float* W2a  = (const float*)d_in[9];
    const float* b2a  = (const float*)d_in[10];
    const float* W2b  = (const float*)d_in[11];
    const float* b2b  = (const float*)d_in[12];
    float* out = (float*)d_out;

    float *buf1, *GI;
    __nv_bfloat16 *XHI, *XLO, *A1HI, *A1LO, *A2HI, *A2LO, *HHI, *HLO;
    __nv_bfloat16 *W1AHI, *W1ALO, *W1BHI, *W1BLO, *WIHHI, *WIHLO, *W2AHI, *W2ALO, *WHHHI, *WHHLO;
    unsigned int* FLAGS;

    cudaGetSymbolAddress((void**)&buf1, d_buf1);
    cudaGetSymbolAddress((void**)&GI,   d_GI);
    cudaGetSymbolAddress((void**)&XHI,  d_XHI);  cudaGetSymbolAddress((void**)&XLO,  d_XLO);
    cudaGetSymbolAddress((void**)&A1HI, d_A1HI); cudaGetSymbolAddress((void**)&A1LO, d_A1LO);
    cudaGetSymbolAddress((void**)&A2HI, d_A2HI); cudaGetSymbolAddress((void**)&A2LO, d_A2LO);
    cudaGetSymbolAddress((void**)&HHI,  d_HHI);  cudaGetSymbolAddress((void**)&HLO,  d_HLO);
    cudaGetSymbolAddress((void**)&W1AHI, d_W1AHI); cudaGetSymbolAddress((void**)&W1ALO, d_W1ALO);
    cudaGetSymbolAddress((void**)&W1BHI, d_W1BHI); cudaGetSymbolAddress((void**)&W1BLO, d_W1BLO);
    cudaGetSymbolAddress((void**)&WIHHI, d_WIHHI); cudaGetSymbolAddress((void**)&WIHLO, d_WIHLO);
    cudaGetSymbolAddress((void**)&W2AHI, d_W2AHI); cudaGetSymbolAddress((void**)&W2ALO, d_W2ALO);
    cudaGetSymbolAddress((void**)&WHHHI, d_WHHHI); cudaGetSymbolAddress((void**)&WHHLO, d_WHHLO);
    cudaGetSymbolAddress((void**)&FLAGS, d_flags);

    cudaFuncSetAttribute(gemm_bf<true, 0>,  cudaFuncAttributeMaxDynamicSharedMemorySize, G_SM_TOTAL);
    cudaFuncSetAttribute(gemm_bf<true, 1>,  cudaFuncAttributeMaxDynamicSharedMemorySize, G_SM_TOTAL);
    cudaFuncSetAttribute(gemm_bf<false, 0>, cudaFuncAttributeMaxDynamicSharedMemorySize, G_SM_TOTAL);
    cudaFuncSetAttribute(gru_persist, cudaFuncAttributeMaxDynamicSharedMemorySize, U_SM_TOTAL);

    const int M = MTOT;

    // ---- pre-split inputs/weights to bf16 hi/lo ----
    split_f32<<<(M * 256 / 4 + 255) / 256, 256>>>((const float4*)x, (uint2*)XHI, (uint2*)XLO, M * 256 / 4);
    split_f32<<<128, 256>>>((const float4*)W1a, (uint2*)W1AHI, (uint2*)W1ALO, 512 * 256 / 4);
    split_f32<<<128, 256>>>((const float4*)W1b, (uint2*)W1BHI, (uint2*)W1BLO, 256 * 512 / 4);
    split_f32<<<192, 256>>>((const float4*)Wih, (uint2*)WIHHI, (uint2*)WIHLO, 768 * 256 / 4);
    split_f32<<<128, 256>>>((const float4*)W2a, (uint2*)W2AHI, (uint2*)W2ALO, 512 * 256 / 4);
    split_f32<<<192, 256>>>((const float4*)Whh, (uint2*)WHHHI, (uint2*)WHHLO, 768 * 256 / 4);

    zero_u32<<<16, 256>>>((uint32_t*)FLAGS, NCTA_GRU * 2 * 32);

    // ---- batched GEMMs ----
    gemm_bf<true, 1><<<dim3(4, M / 128), 256, G_SM_TOTAL>>>(
        XHI, XLO, W1AHI, W1ALO, b1a, nullptr, A1HI, A1LO, M, 512, 256);
    gemm_bf<true, 1><<<dim3(2, M / 128), 256, G_SM_TOTAL>>>(
        A1HI, A1LO, W1BHI, W1BLO, b1b, nullptr, A2HI, A2LO, M, 256, 512);
    gemm_bf<false, 0><<<dim3(6, M / 128), 256, G_SM_TOTAL>>>(
        A2HI, A2LO, WIHHI, WIHLO, bih, GI, nullptr, nullptr, M, 768, 256);

    // ---- persistent GRU + fused fc2a workers (148 CTAs) ----
    gru_persist<<<NCTA_ALL, 256, U_SM_TOTAL>>>(
        GI, WHHHI, WHHLO, bhh, HHI, HLO, FLAGS, W2AHI, W2ALO, b2a, buf1);

    // head
    head_gemm<<<M / 1024, 256>>>(buf1, W2b, b2b, out, M);
}

// round 12
// speedup vs baseline: 1.7879x; 1.1320x over previous
#include <cuda_runtime.h>
#include <cuda_bf16.h>
#include <math.h>
#include <stdint.h>

// Problem constants
#define TT 512
#define BB 256
#define IN_DIM 256
#define H1 512
#define HH 256
#define OUT_DIM 18
#define MTOT (TT*BB)   // 131072
#define NCTA_GRU 64
#define NCTA_ALL 148
#define NWORK (NCTA_ALL - NCTA_GRU)   // 84
#define GRP 8          // CTAs per sync group

// -------------------- scratch (static device globals; no allocs) -----------
__device__ float d_buf1[(size_t)MTOT * 512];     // fc2a out (fp32, for head)
__device__ float d_GI  [(size_t)MTOT * 768];     // gi fp32

__device__ __nv_bfloat16 d_XHI[(size_t)MTOT * 256], d_XLO[(size_t)MTOT * 256];
__device__ __nv_bfloat16 d_A1HI[(size_t)MTOT * 512], d_A1LO[(size_t)MTOT * 512];
__device__ __nv_bfloat16 d_A2HI[(size_t)MTOT * 256], d_A2LO[(size_t)MTOT * 256];
__device__ __nv_bfloat16 d_HHI[(size_t)MTOT * 256], d_HLO[(size_t)MTOT * 256];

__device__ __nv_bfloat16 d_W1AHI[512*256], d_W1ALO[512*256];
__device__ __nv_bfloat16 d_W1BHI[256*512], d_W1BLO[256*512];
__device__ __nv_bfloat16 d_WIHHI[768*256], d_WIHLO[768*256];
__device__ __nv_bfloat16 d_W2AHI[512*256], d_W2ALO[512*256];
__device__ __nv_bfloat16 d_WHHHI[768*256], d_WHHLO[768*256];

// padded flags: one 128B line per (cta, chain); per-t gi counters also padded
__device__ unsigned int d_flags[NCTA_GRU * 2 * 32];
__device__ unsigned int d_gicnt[TT * 32];

// ==================== helpers ==============================================
__device__ __forceinline__ uint32_t smem_u32(const void* p) {
    uint32_t a;
    asm("{ .reg .u64 t; cvta.to.shared.u64 t, %1; cvt.u32.u64 %0, t; }"
        : "=r"(a) : "l"(p));
    return a;
}

__device__ __forceinline__ void ldsm4(uint32_t* r, uint32_t addr) {
    asm volatile("ldmatrix.sync.aligned.m8n8.x4.shared.b16 {%0,%1,%2,%3}, [%4];"
        : "=r"(r[0]), "=r"(r[1]), "=r"(r[2]), "=r"(r[3]) : "r"(addr));
}
__device__ __forceinline__ void ldsm2(uint32_t* r, uint32_t addr) {
    asm volatile("ldmatrix.sync.aligned.m8n8.x2.shared.b16 {%0,%1}, [%2];"
        : "=r"(r[0]), "=r"(r[1]) : "r"(addr));
}

__device__ __forceinline__ void mma16816(float* c, const uint32_t* a, const uint32_t* b) {
    asm volatile(
        "mma.sync.aligned.m16n8k16.row.col.f32.bf16.bf16.f32 "
        "{%0,%1,%2,%3}, {%4,%5,%6,%7}, {%8,%9}, {%0,%1,%2,%3};"
        : "+f"(c[0]), "+f"(c[1]), "+f"(c[2]), "+f"(c[3])
        : "r"(a[0]), "r"(a[1]), "r"(a[2]), "r"(a[3]), "r"(b[0]), "r"(b[1]));
}

__device__ __forceinline__ void cp16(uint32_t dst, const void* src) {
    asm volatile("cp.async.cg.shared.global [%0], [%1], 16;"
        :: "r"(dst), "l"(src) : "memory");
}
#define CP_COMMIT() asm volatile("cp.async.commit_group;" ::: "memory")
#define CP_WAIT0()  asm volatile("cp.async.wait_group 0;" ::: "memory")
#define CP_WAIT1()  asm volatile("cp.async.wait_group 1;" ::: "memory")
#define BARX(id)    asm volatile("bar.sync %0, 128;" :: "r"(id) : "memory")

__device__ __forceinline__ void split_bf16x4(float4 v, uint2& hv, uint2& lv) {
    __nv_bfloat16 h0 = __float2bfloat16(v.x);
    __nv_bfloat16 h1 = __float2bfloat16(v.y);
    __nv_bfloat16 h2 = __float2bfloat16(v.z);
    __nv_bfloat16 h3 = __float2bfloat16(v.w);
    __nv_bfloat16 l0 = __float2bfloat16(v.x - __bfloat162float(h0));
    __nv_bfloat16 l1 = __float2bfloat16(v.y - __bfloat162float(h1));
    __nv_bfloat16 l2 = __float2bfloat16(v.z - __bfloat162float(h2));
    __nv_bfloat16 l3 = __float2bfloat16(v.w - __bfloat162float(h3));
    hv.x = (uint32_t)__bfloat16_as_ushort(h0) | ((uint32_t)__bfloat16_as_ushort(h1) << 16);
    hv.y = (uint32_t)__bfloat16_as_ushort(h2) | ((uint32_t)__bfloat16_as_ushort(h3) << 16);
    lv.x = (uint32_t)__bfloat16_as_ushort(l0) | ((uint32_t)__bfloat16_as_ushort(l1) << 16);
    lv.y = (uint32_t)__bfloat16_as_ushort(l2) | ((uint32_t)__bfloat16_as_ushort(l3) << 16);
}

__device__ __forceinline__ uint32_t pack_hi2(float a, float b, uint32_t& lo) {
    __nv_bfloat16 ha = __float2bfloat16(a);
    __nv_bfloat16 hb = __float2bfloat16(b);
    __nv_bfloat16 la = __float2bfloat16(a - __bfloat162float(ha));
    __nv_bfloat16 lb = __float2bfloat16(b - __bfloat162float(hb));
    lo = (uint32_t)__bfloat16_as_ushort(la) | ((uint32_t)__bfloat16_as_ushort(lb) << 16);
    return (uint32_t)__bfloat16_as_ushort(ha) | ((uint32_t)__bfloat16_as_ushort(hb) << 16);
}

// -------------------- split / zero kernels ---------------------------------
__global__ void split_f32(const float4* __restrict__ in,
                          uint2* __restrict__ hi, uint2* __restrict__ lo, int n4) {
    int i = blockIdx.x * blockDim.x + threadIdx.x;
    if (i < n4) {
        uint2 h, l;
        split_bf16x4(in[i], h, l);
        hi[i] = h; lo[i] = l;
    }
}
__global__ void zero_u32(uint32_t* p, int n) {
    int i = blockIdx.x * blockDim.x + threadIdx.x;
    if (i < n) p[i] = 0u;
}

// ==================== pipelined bf16-split GEMM (standalone launches) =======
#define GROW 144
#define G_AHI 0
#define G_ALO 18432
#define G_BHI 36864
#define G_BLO 55296
#define G_STAGE 73728
#define G_SM_TOTAL (2*G_STAGE)

template<bool RELU, int OUTM>
__global__ void __launch_bounds__(256, 1) gemm_bf(
    const __nv_bfloat16* __restrict__ Ahi, const __nv_bfloat16* __restrict__ Alo,
    const __nv_bfloat16* __restrict__ Bhi, const __nv_bfloat16* __restrict__ Blo,
    const float* __restrict__ bias,
    float* __restrict__ C, __nv_bfloat16* __restrict__ Chi, __nv_bfloat16* __restrict__ Clo,
    int M, int N, int K)
{
    extern __shared__ char sm[];
    const uint32_t smb = smem_u32(sm);
    const int tid = threadIdx.x;
    const int lane = tid & 31;
    const int wid = tid >> 5;
    const int wm = wid & 1;
    const int wn = wid >> 1;
    const int m0 = blockIdx.y * 128;
    const int n0 = blockIdx.x * 128;

    float acc[4][4][4];
    #pragma unroll
    for (int i = 0; i < 4; i++)
        #pragma unroll
        for (int j = 0; j < 4; j++)
            #pragma unroll
            for (int e = 0; e < 4; e++) acc[i][j][e] = 0.f;

    const uint32_t a_row = (uint32_t)(lane & 15);
    const uint32_t a_kb  = (uint32_t)((lane >> 4) * 16);
    const uint32_t b_row = (uint32_t)(((lane >> 4) & 1) * 8 + (lane & 7));
    const uint32_t b_kb  = (uint32_t)(((lane >> 3) & 1) * 16);

    const int nchunks = K >> 6;

    auto load_chunk = [&](int kc, int st) {
        const int kb = kc << 6;
        const uint32_t base = smb + (uint32_t)st * G_STAGE;
        #pragma unroll
        for (int j = 0; j < 4; j++) {
            int idx = tid + 256 * j;
            int r = idx >> 3;
            int c = idx & 7;
            size_t aoff = (size_t)(m0 + r) * K + kb + c * 8;
            size_t boff = (size_t)(n0 + r) * K + kb + c * 8;
            uint32_t d = (uint32_t)(r * GROW + c * 16);
            cp16(base + G_AHI + d, Ahi + aoff);
            cp16(base + G_ALO + d, Alo + aoff);
            cp16(base + G_BHI + d, Bhi + boff);
            cp16(base + G_BLO + d, Blo + boff);
        }
        CP_COMMIT();
    };

    load_chunk(0, 0);

    for (int kc = 0; kc < nchunks; kc++) {
        const int st = kc & 1;
        if (kc + 1 < nchunks) { load_chunk(kc + 1, st ^ 1); CP_WAIT1(); }
        else                  { CP_WAIT0(); }
        __syncthreads();

        const uint32_t base = smb + (uint32_t)st * G_STAGE;
        #pragma unroll
        for (int ks = 0; ks < 4; ks++) {
            const uint32_t koff = (uint32_t)(ks * 32);
            uint32_t afr[4][4], bhi2[4][2], blo2[4][2];

            #pragma unroll
            for (int mt = 0; mt < 4; mt++)
                ldsm4(afr[mt], base + G_AHI + (uint32_t)(wm*64 + mt*16 + a_row)*GROW + koff + a_kb);
            #pragma unroll
            for (int g = 0; g < 2; g++) {
                uint32_t r4[4];
                ldsm4(r4, base + G_BHI + (uint32_t)(wn*32 + g*16 + b_row)*GROW + koff + b_kb);
                bhi2[g*2  ][0] = r4[0]; bhi2[g*2  ][1] = r4[1];
                bhi2[g*2+1][0] = r4[2]; bhi2[g*2+1][1] = r4[3];
            }
            #pragma unroll
            for (int mt = 0; mt < 4; mt++)
                #pragma unroll
                for (int nt = 0; nt < 4; nt++)
                    mma16816(acc[mt][nt], afr[mt], bhi2[nt]);

            #pragma unroll
            for (int g = 0; g < 2; g++) {
                uint32_t r4[4];
                ldsm4(r4, base + G_BLO + (uint32_t)(wn*32 + g*16 + b_row)*GROW + koff + b_kb);
                blo2[g*2  ][0] = r4[0]; blo2[g*2  ][1] = r4[1];
                blo2[g*2+1][0] = r4[2]; blo2[g*2+1][1] = r4[3];
            }
            #pragma unroll
            for (int mt = 0; mt < 4; mt++)
                #pragma unroll
                for (int nt = 0; nt < 4; nt++)
                    mma16816(acc[mt][nt], afr[mt], blo2[nt]);

            #pragma unroll
            for (int mt = 0; mt < 4; mt++)
                ldsm4(afr[mt], base + G_ALO + (uint32_t)(wm*64 + mt*16 + a_row)*GROW + koff + a_kb);
            #pragma unroll
            for (int mt = 0; mt < 4; mt++)
                #pragma unroll
                for (int nt = 0; nt < 4; nt++)
                    mma16816(acc[mt][nt], afr[mt], bhi2[nt]);
        }
        __syncthreads();
    }

    const int r_in = lane >> 2;
    const int c_in = (lane & 3) * 2;
    #pragma unroll
    for (int mt = 0; mt < 4; mt++) {
        #pragma unroll
        for (int nt = 0; nt < 4; nt++) {
            int col = n0 + wn * 32 + nt * 8 + c_in;
            float b0 = bias[col], b1 = bias[col + 1];
            int row0 = m0 + wm * 64 + mt * 16 + r_in;
            float v00 = acc[mt][nt][0] + b0, v01 = acc[mt][nt][1] + b1;
            float v10 = acc[mt][nt][2] + b0, v11 = acc[mt][nt][3] + b1;
            if (RELU) {
                v00 = fmaxf(v00, 0.f); v01 = fmaxf(v01, 0.f);
                v10 = fmaxf(v10, 0.f); v11 = fmaxf(v11, 0.f);
            }
            if (OUTM == 0) {
                float2 p0, p1;
                p0.x = v00; p0.y = v01; p1.x = v10; p1.y = v11;
                *(float2*)&C[(size_t)row0 * N + col] = p0;
                *(float2*)&C[(size_t)(row0 + 8) * N + col] = p1;
            } else {
                uint32_t lo0, lo1;
                uint32_t hi0 = pack_hi2(v00, v01, lo0);
                uint32_t hi1 = pack_hi2(v10, v11, lo1);
                *(uint32_t*)&Chi[(size_t)row0 * N + col] = hi0;
                *(uint32_t*)&Clo[(size_t)row0 * N + col] = lo0;
                *(uint32_t*)&Chi[(size_t)(row0 + 8) * N + col] = hi1;
                *(uint32_t*)&Clo[(size_t)(row0 + 8) * N + col] = lo1;
            }
        }
    }
}

// ==================== persistent GRU + fused gi/fc2a workers ================
// 148 CTAs: 0-63 GRU producers (R10 structure); 64-147 workers that first
// compute gi tiles in t-order (publishing per-t counters the GRU waits on),
// then fc2a tiles gated on GRU h-flags.
#define U_WHI 0
#define U_WLO 50688            // 96*528
#define U_HA_HI 101376         // 16*528 = 8448 each
#define U_HA_LO 109824
#define U_HB_HI 118272
#define U_HB_LO 126720
#define U_GHA 135168           // 16*97*4 = 6208
#define U_GHB 141376
#define U_SM_TOTAL 147584      // >= G_SM_TOTAL (147456) for worker path
#define USTRIDE 528

__global__ void __launch_bounds__(256, 1) gru_persist(
    float* __restrict__ GI_,
    const __nv_bfloat16* __restrict__ whh_hi,
    const __nv_bfloat16* __restrict__ whh_lo,
    const float* __restrict__ bhh,
    __nv_bfloat16* __restrict__ HHI_,
    __nv_bfloat16* __restrict__ HLO_,
    unsigned int* __restrict__ flags,
    const __nv_bfloat16* __restrict__ w2a_hi,
    const __nv_bfloat16* __restrict__ w2a_lo,
    const float* __restrict__ b2a,
    float* __restrict__ buf1,
    const __nv_bfloat16* __restrict__ a2_hi,
    const __nv_bfloat16* __restrict__ a2_lo,
    const __nv_bfloat16* __restrict__ wih_hi,
    const __nv_bfloat16* __restrict__ wih_lo,
    const float* __restrict__ bih,
    unsigned int* __restrict__ gicnt)
{
    extern __shared__ char sm[];
    const uint32_t smb = smem_u32(sm);
    const int tid = threadIdx.x;
    const int lane = tid & 31;
    const int wid = tid >> 5;
    const int cta = blockIdx.x;

    if (cta < NCTA_GRU) {
        // ==================== GRU producer path =============================
        const int grpB = wid >> 2;        // 0 = chain A, 1 = chain B
        const int gtid = tid & 127;
        const int wn = wid & 3;
        const int grp = cta >> 3;
        const int kq  = cta & 7;
        const int b0 = grp * 32;
        const int k0 = kq * 32;
        const int barid = 1 + grpB;

        float* GHg = (float*)(sm + (grpB ? U_GHB : U_GHA));
        const uint32_t hHiBuf = smb + (grpB ? U_HB_HI : U_HA_HI);
        const uint32_t hLoBuf = smb + (grpB ? U_HB_LO : U_HA_LO);
        const int bOff = grpB ? 16 : 0;

        for (int i = tid; i < 3072; i += 256) {
            int j = i >> 5;
            int c = i & 31;
            int gate = j >> 5, jr = j & 31;
            size_t soff = (size_t)(gate * 256 + k0 + jr) * 256 + c * 8;
            uint32_t d = (uint32_t)(j * USTRIDE + c * 16);
            cp16(smb + U_WHI + d, whh_hi + soff);
            cp16(smb + U_WLO + d, whh_lo + soff);
        }
        CP_COMMIT();

        {
            float* GA = (float*)(sm + U_GHA);
            float* GB = (float*)(sm + U_GHB);
            for (int i = tid; i < 16 * 97; i += 256) { GA[i] = 0.f; GB[i] = 0.f; }
        }

        int bloc[4], kloc[4];
        size_t off_o[4], gio[4];
        float brr[4], brz[4], brn[4], hp[4];
        #pragma unroll
        for (int i = 0; i < 4; i++) {
            int idx = gtid + 128 * i;
            int b = idx >> 5, ko = idx & 31;
            bloc[i] = b; kloc[i] = ko;
            int kg = k0 + ko;
            off_o[i] = (size_t)(b0 + bOff + b) * 256 + kg;
            gio[i] = (size_t)(b0 + bOff + b) * 768 + kg;
            brr[i] = bhh[kg];
            brz[i] = bhh[256 + kg];
            brn[i] = bhh[512 + kg];
            hp[i] = 0.f;
        }

        const uint32_t a_row = (uint32_t)(lane & 15);
        const uint32_t a_kb  = (uint32_t)((lane >> 4) * 16);
        const uint32_t b_row = (uint32_t)(((lane >> 4) & 1) * 8 + (lane & 7));
        const uint32_t b_kb  = (uint32_t)(((lane >> 3) & 1) * 16);
        const uint32_t b2_row = (uint32_t)(lane & 7);
        const uint32_t b2_kb  = (uint32_t)(((lane >> 3) & 1) * 16);

        const uint32_t aHi = hHiBuf + a_row * USTRIDE + a_kb;
        const uint32_t aLo = hLoBuf + a_row * USTRIDE + a_kb;
        const uint32_t bBaseHi4 = smb + U_WHI + (uint32_t)(wn * 24 + b_row) * USTRIDE + b_kb;
        const uint32_t bBaseLo4 = smb + U_WLO + (uint32_t)(wn * 24 + b_row) * USTRIDE + b_kb;
        const uint32_t bBaseHi2 = smb + U_WHI + (uint32_t)(wn * 24 + 16 + b2_row) * USTRIDE + b2_kb;
        const uint32_t bBaseLo2 = smb + U_WLO + (uint32_t)(wn * 24 + 16 + b2_row) * USTRIDE + b2_kb;

        unsigned int* myflag = flags + (cta * 2 + grpB) * 32;
        unsigned int* poll   = flags + (((grp * GRP) + (gtid & 7)) * 2 + grpB) * 32;

        auto do_mma = [&]() {
            float acc[3][4];
            #pragma unroll
            for (int i = 0; i < 3; i++)
                #pragma unroll
                for (int e = 0; e < 4; e++) acc[i][e] = 0.f;

            #pragma unroll 4
            for (int ks = 0; ks < 16; ks++) {
                const uint32_t koff = (uint32_t)(ks * 32);
                uint32_t a[4], bh[3][2], bl[3][2], r4[4];

                ldsm4(a, aHi + koff);
                ldsm4(r4, bBaseHi4 + koff);
                bh[0][0] = r4[0]; bh[0][1] = r4[1]; bh[1][0] = r4[2]; bh[1][1] = r4[3];
                ldsm2(bh[2], bBaseHi2 + koff);
                #pragma unroll
                for (int nt = 0; nt < 3; nt++) mma16816(acc[nt], a, bh[nt]);

                ldsm4(r4, bBaseLo4 + koff);
                bl[0][0] = r4[0]; bl[0][1] = r4[1]; bl[1][0] = r4[2]; bl[1][1] = r4[3];
                ldsm2(bl[2], bBaseLo2 + koff);
                #pragma unroll
                for (int nt = 0; nt < 3; nt++) mma16816(acc[nt], a, bl[nt]);

                ldsm4(a, aLo + koff);
                #pragma unroll
                for (int nt = 0; nt < 3; nt++) mma16816(acc[nt], a, bh[nt]);
            }
            const int r0 = lane >> 2;
            const int cc = (lane & 3) * 2;
            #pragma unroll
            for (int nt = 0; nt < 3; nt++) {
                int col = wn * 24 + nt * 8 + cc;
                GHg[r0 * 97 + col]           = acc[nt][0];
                GHg[r0 * 97 + col + 1]       = acc[nt][1];
                GHg[(r0 + 8) * 97 + col]     = acc[nt][2];
                GHg[(r0 + 8) * 97 + col + 1] = acc[nt][3];
            }
        };

        float ir[4], iz[4], in_[4];
        auto wait_gi = [&](int t) {
            const unsigned int* c = gicnt + t * 32;
            unsigned int v;
            do {
                asm volatile("ld.acquire.gpu.u32 %0, [%1];"
                    : "=r"(v) : "l"(c) : "memory");
            } while (v < 12u);
        };
        auto prefetch_gi = [&](int t) {
            const float* gin = GI_ + (size_t)t * (BB * 768);
            #pragma unroll
            for (int i = 0; i < 4; i++) {
                ir[i]  = __ldg(gin + gio[i]);
                iz[i]  = __ldg(gin + gio[i] + 256);
                in_[i] = __ldg(gin + gio[i] + 512);
            }
        };

        auto do_gates = [&](int t) {
            __nv_bfloat16* hoh = HHI_ + (size_t)t * (BB * HH);
            __nv_bfloat16* hol = HLO_ + (size_t)t * (BB * HH);
            #pragma unroll
            for (int i = 0; i < 4; i++) {
                int b = bloc[i], ko = kloc[i];
                float hr = GHg[b * 97 + ko]      + brr[i];
                float hz = GHg[b * 97 + 32 + ko] + brz[i];
                float hn = GHg[b * 97 + 64 + ko] + brn[i];

                float r = 1.f / (1.f + __expf(-(ir[i] + hr)));
                float z = 1.f / (1.f + __expf(-(iz[i] + hz)));
                float n = tanhf(in_[i] + r * hn);
                float hnew = (1.f - z) * n + z * hp[i];
                hp[i] = hnew;

                __nv_bfloat16 hh = __float2bfloat16(hnew);
                hoh[off_o[i]] = hh;
                hol[off_o[i]] = __float2bfloat16(hnew - __bfloat162float(hh));
            }
        };

        auto load_h = [&](int t) {
            const __nv_bfloat16* hph = HHI_ + (size_t)t * (BB * HH);
            const __nv_bfloat16* hpl = HLO_ + (size_t)t * (BB * HH);
            #pragma unroll
            for (int i = 0; i < 4; i++) {
                int idx = gtid + 128 * i;
                int r = idx >> 5;
                int c = idx & 31;
                size_t soff = (size_t)(b0 + bOff + r) * 256 + c * 8;
                uint32_t d = (uint32_t)(r * USTRIDE + c * 16);
                cp16(hHiBuf + d, hph + soff);
                cp16(hLoBuf + d, hpl + soff);
            }
            CP_COMMIT();
        };

        auto signal_spin = [&](unsigned int target) {
            BARX(barid);
            if (gtid == 0) {
                asm volatile("st.release.gpu.u32 [%0], %1;"
                    :: "l"(myflag), "r"(target) : "memory");
            }
            if (gtid < GRP) {
                unsigned int v;
                do {
                    asm volatile("ld.acquire.gpu.u32 %0, [%1];"
                        : "=r"(v) : "l"(poll) : "memory");
                } while (v < target);
            }
            BARX(barid);
        };

        CP_WAIT0();
        __syncthreads();

        wait_gi(0);
        prefetch_gi(0);
        do_gates(0);
        wait_gi(1);
        prefetch_gi(1);
        signal_spin(1u);
        load_h(0);

        for (int t = 1; t < TT; t++) {
            CP_WAIT0();
            BARX(barid);
            do_mma();
            BARX(barid);
            do_gates(t);
            if (t + 1 < TT) {
                wait_gi(t + 1);
                prefetch_gi(t + 1);
                signal_spin((unsigned int)(t + 1));
                load_h(t);
            }
        }
        // final publish so workers can consume h[T-1]
        BARX(barid);
        if (gtid == 0) {
            asm volatile("st.release.gpu.u32 [%0], %1;"
                :: "l"(myflag), "r"((unsigned int)TT) : "memory");
        }
    } else {
        // ==================== worker path: gi tiles, then fc2a ==============
        const int wrk = cta - NCTA_GRU;
        const int wm = wid & 1;
        const int wn = wid >> 1;
        const uint32_t a_row = (uint32_t)(lane & 15);
        const uint32_t a_kb  = (uint32_t)((lane >> 4) * 16);
        const uint32_t b_row = (uint32_t)(((lane >> 4) & 1) * 8 + (lane & 7));
        const uint32_t b_kb  = (uint32_t)(((lane >> 3) & 1) * 16);
        const int r_in = lane >> 2;
        const int c_in = (lane & 3) * 2;

        // generic 128x128xK256 bf16-split tile: out = act(A@B^T + bias)
        auto do_tile = [&](const __nv_bfloat16* Ahi_, const __nv_bfloat16* Alo_,
                           size_t m0,
                           const __nv_bfloat16* Bhi_, const __nv_bfloat16* Blo_,
                           int n0, const float* bias_, float* outp, int outN,
                           bool relu) {
            float acc[4][4][4];
            #pragma unroll
            for (int i = 0; i < 4; i++)
                #pragma unroll
                for (int j = 0; j < 4; j++)
                    #pragma unroll
                    for (int e = 0; e < 4; e++) acc[i][j][e] = 0.f;

            auto load_chunk = [&](int kc, int st) {
                const int kb = kc << 6;
                const uint32_t base = smb + (uint32_t)st * G_STAGE;
                #pragma unroll
                for (int j = 0; j < 4; j++) {
                    int idx = tid + 256 * j;
                    int r = idx >> 3;
                    int c = idx & 7;
                    size_t aoff = (m0 + r) * 256 + kb + c * 8;
                    size_t boff = (size_t)(n0 + r) * 256 + kb + c * 8;
                    uint32_t d = (uint32_t)(r * GROW + c * 16);
                    cp16(base + G_AHI + d, Ahi_ + aoff);
                    cp16(base + G_ALO + d, Alo_ + aoff);
                    cp16(base + G_BHI + d, Bhi_ + boff);
                    cp16(base + G_BLO + d, Blo_ + boff);
                }
                CP_COMMIT();
            };

            load_chunk(0, 0);
            for (int kc = 0; kc < 4; kc++) {
                const int st = kc & 1;
                if (kc + 1 < 4) { load_chunk(kc + 1, st ^ 1); CP_WAIT1(); }
                else            { CP_WAIT0(); }
                __syncthreads();

                const uint32_t base = smb + (uint32_t)st * G_STAGE;
                #pragma unroll
                for (int ks = 0; ks < 4; ks++) {
                    const uint32_t koff = (uint32_t)(ks * 32);
                    uint32_t afr[4][4], bhi2[4][2], blo2[4][2];

                    #pragma unroll
                    for (int mt = 0; mt < 4; mt++)
                        ldsm4(afr[mt], base + G_AHI + (uint32_t)(wm*64 + mt*16 + a_row)*GROW + koff + a_kb);
                    #pragma unroll
                    for (int g = 0; g < 2; g++) {
                        uint32_t r4[4];
                        ldsm4(r4, base + G_BHI + (uint32_t)(wn*32 + g*16 + b_row)*GROW + koff + b_kb);
                        bhi2[g*2  ][0] = r4[0]; bhi2[g*2  ][1] = r4[1];
                        bhi2[g*2+1][0] = r4[2]; bhi2[g*2+1][1] = r4[3];
                    }
                    #pragma unroll
                    for (int mt = 0; mt < 4; mt++)
                        #pragma unroll
                        for (int nt = 0; nt < 4; nt++)
                            mma16816(acc[mt][nt], afr[mt], bhi2[nt]);

                    #pragma unroll
                    for (int g = 0; g < 2; g++) {
                        uint32_t r4[4];
                        ldsm4(r4, base + G_BLO + (uint32_t)(wn*32 + g*16 + b_row)*GROW + koff + b_kb);
                        blo2[g*2  ][0] = r4[0]; blo2[g*2  ][1] = r4[1];
                        blo2[g*2+1][0] = r4[2]; blo2[g*2+1][1] = r4[3];
                    }
                    #pragma unroll
                    for (int mt = 0; mt < 4; mt++)
                        #pragma unroll
                        for (int nt = 0; nt < 4; nt++)
                            mma16816(acc[mt][nt], afr[mt], blo2[nt]);

                    #pragma unroll
                    for (int mt = 0; mt < 4; mt++)
                        ldsm4(afr[mt], base + G_ALO + (uint32_t)(wm*64 + mt*16 + a_row)*GROW + koff + a_kb);
                    #pragma unroll
                    for (int mt = 0; mt < 4; mt++)
                        #pragma unroll
                        for (int nt = 0; nt < 4; nt++)
                            mma16816(acc[mt][nt], afr[mt], bhi2[nt]);
                }
                __syncthreads();
            }

            #pragma unroll
            for (int mt = 0; mt < 4; mt++) {
                #pragma unroll
                for (int nt = 0; nt < 4; nt++) {
                    int col = n0 + wn * 32 + nt * 8 + c_in;
                    float bb0 = bias_[col], bb1 = bias_[col + 1];
                    size_t row0 = m0 + wm * 64 + mt * 16 + r_in;
                    float2 p0, p1;
                    p0.x = acc[mt][nt][0] + bb0; p0.y = acc[mt][nt][1] + bb1;
                    p1.x = acc[mt][nt][2] + bb0; p1.y = acc[mt][nt][3] + bb1;
                    if (relu) {
                        p0.x = fmaxf(p0.x, 0.f); p0.y = fmaxf(p0.y, 0.f);
                        p1.x = fmaxf(p1.x, 0.f); p1.y = fmaxf(p1.y, 0.f);
                    }
                    *(float2*)&outp[row0 * outN + col] = p0;
                    *(float2*)&outp[(row0 + 8) * outN + col] = p1;
                }
            }
        };

        // ---- phase 1: gi tiles (t-ordered; publish per-t counters) ----
        const int nGiTiles = TT * 12;   // per t: 2 m-halves x 6 n-tiles (768)
        for (int idx = wrk; idx < nGiTiles; idx += NWORK) {
            int t = idx / 12;
            int rem = idx - t * 12;
            int mhalf = rem >= 6 ? 1 : 0;
            int nq = rem - mhalf * 6;
            size_t m0 = (size_t)t * 256 + (size_t)mhalf * 128;
            do_tile(a2_hi, a2_lo, m0, wih_hi, wih_lo, nq * 128, bih, GI_, 768, false);
            __threadfence();
            __syncthreads();
            if (tid == 0) {
                asm volatile("red.release.gpu.global.add.u32 [%0], %1;"
                    :: "l"(gicnt + t * 32), "r"(1u) : "memory");
            }
        }

        // ---- phase 2: fc2a tiles (gated on GRU h-flags) ----
        const int nTiles = TT * 8;
        for (int tile = wrk; tile < nTiles; tile += NWORK) {
            const int t = tile >> 3;
            const int mhalf = (tile >> 2) & 1;
            const int nq = tile & 3;

            {
                const unsigned int target = (unsigned int)(t + 1);
                if (tid < 64) {
                    unsigned int* f = flags + (((mhalf * 32) + (tid >> 1)) * 2 + (tid & 1)) * 32;
                    unsigned int v;
                    do {
                        asm volatile("ld.acquire.gpu.u32 %0, [%1];"
                            : "=r"(v) : "l"(f) : "memory");
                    } while (v < target);
                }
                __syncthreads();
            }

            size_t m0 = (size_t)t * 256 + (size_t)mhalf * 128;
            do_tile(HHI_, HLO_, m0, w2a_hi, w2a_lo, nq * 128, b2a, buf1, 512, true);
        }
    }
}

// -------------------- fc2b head -------------------------------------------
__global__ void __launch_bounds__(256, 2) head_gemm(
    const float* __restrict__ A,
    const float* __restrict__ Wb,
    const float* __restrict__ bias,
    float* __restrict__ out, int M)
{
    __shared__ float Ws[18][512];
    const int tid = threadIdx.x;
    #pragma unroll
    for (int i = 0; i < 9; i++) {
        int idx = tid + 256 * i;
        ((float4*)&Ws[0][0])[idx] = ((const float4*)Wb)[idx];
    }
    __syncthreads();

    const size_t mbase = (size_t)blockIdx.x * 1024 + tid;

    float acc[4][18];
    #pragma unroll
    for (int i = 0; i < 4; i++)
        #pragma unroll
        for (int j = 0; j < 18; j++) acc[i][j] = 0.f;

    for (int k4 = 0; k4 < 128; k4++) {
        float4 a[4];
        #pragma unroll
        for (int i = 0; i < 4; i++)
            a[i] = *(const float4*)&A[(mbase + 256 * i) * 512 + k4 * 4];
        #pragma unroll
        for (int j = 0; j < 18; j++) {
            float4 w = *(const float4*)&Ws[j][k4 * 4];
            #pragma unroll
            for (int i = 0; i < 4; i++) {
                acc[i][j] += a[i].x * w.x;
                acc[i][j] += a[i].y * w.y;
                acc[i][j] += a[i].z * w.z;
                acc[i][j] += a[i].w * w.w;
            }
        }
    }

    #pragma unroll
    for (int i = 0; i < 4; i++) {
        size_t row = mbase + 256 * i;
        #pragma unroll
        for (int j = 0; j < 18; j++)
            out[row * 18 + j] = acc[i][j] + bias[j];
    }
}

// -------------------- launch ------------------------------------------------
extern "C" void kernel_launch(void* const* d_in, const int* in_sizes, int n_in,
                              void* d_out, int out_size)
{
    (void)in_sizes; (void)n_in; (void)out_size;
    const float* x    = (const float*)d_in[0];
    const float* W1a  = (const float*)d_in[1];
    const float* b1a  = (const float*)d_in[2];
    const float* W1b  = (const float*)d_in[3];
    const float* b1b  = (const float*)d_in[4];
    const float* Wih  = (const float*)d_in[5];
    const float* bih  = (const float*)d_in[6];
    const float* Whh  = (const float*)d_in[7];
    const float* bhh  = (const float*)d_in[8];
    const float* W2a  = (const float*)d_in[9];
    const float* b2a  = (const float*)d_in[10];
    const float* W2b  = (const float*)d_in[11];
    const float* b2b  = (const float*)d_in[12];
    float* out = (float*)d_out;

    float *buf1, *GI;
    __nv_bfloat16 *XHI, *XLO, *A1HI, *A1LO, *A2HI, *A2LO, *HHI, *HLO;
    __nv_bfloat16 *W1AHI, *W1ALO, *W1BHI, *W1BLO, *WIHHI, *WIHLO, *W2AHI, *W2ALO, *WHHHI, *WHHLO;
    unsigned int *FLAGS, *GICNT;

    cudaGetSymbolAddress((void**)&buf1, d_buf1);
    cudaGetSymbolAddress((void**)&GI,   d_GI);
    cudaGetSymbolAddress((void**)&XHI,  d_XHI);  cudaGetSymbolAddress((void**)&XLO,  d_XLO);
    cudaGetSymbolAddress((void**)&A1HI, d_A1HI); cudaGetSymbolAddress((void**)&A1LO, d_A1LO);
    cudaGetSymbolAddress((void**)&A2HI, d_A2HI); cudaGetSymbolAddress((void**)&A2LO, d_A2LO);
    cudaGetSymbolAddress((void**)&HHI,  d_HHI);  cudaGetSymbolAddress((void**)&HLO,  d_HLO);
    cudaGetSymbolAddress((void**)&W1AHI, d_W1AHI); cudaGetSymbolAddress((void**)&W1ALO, d_W1ALO);
    cudaGetSymbolAddress((void**)&W1BHI, d_W1BHI); cudaGetSymbolAddress((void**)&W1BLO, d_W1BLO);
    cudaGetSymbolAddress((void**)&WIHHI, d_WIHHI); cudaGetSymbolAddress((void**)&WIHLO, d_WIHLO);
    cudaGetSymbolAddress((void**)&W2AHI, d_W2AHI); cudaGetSymbolAddress((void**)&W2ALO, d_W2ALO);
    cudaGetSymbolAddress((void**)&WHHHI, d_WHHHI); cudaGetSymbolAddress((void**)&WHHLO, d_WHHLO);
    cudaGetSymbolAddress((void**)&FLAGS, d_flags);
    cudaGetSymbolAddress((void**)&GICNT, d_gicnt);

    cudaFuncSetAttribute(gemm_bf<true, 0>,  cudaFuncAttributeMaxDynamicSharedMemorySize, G_SM_TOTAL);
    cudaFuncSetAttribute(gemm_bf<true, 1>,  cudaFuncAttributeMaxDynamicSharedMemorySize, G_SM_TOTAL);
    cudaFuncSetAttribute(gru_persist, cudaFuncAttributeMaxDynamicSharedMemorySize, U_SM_TOTAL);

    const int M = MTOT;

    // ---- pre-split inputs/weights to bf16 hi/lo ----
    split_f32<<<(M * 256 / 4 + 255) / 256, 256>>>((const float4*)x, (uint2*)XHI, (uint2*)XLO, M * 256 / 4);
    split_f32<<<128, 256>>>((const float4*)W1a, (uint2*)W1AHI, (uint2*)W1ALO, 512 * 256 / 4);
    split_f32<<<128, 256>>>((const float4*)W1b, (uint2*)W1BHI, (uint2*)W1BLO, 256 * 512 / 4);
    split_f32<<<192, 256>>>((const float4*)Wih, (uint2*)WIHHI, (uint2*)WIHLO, 768 * 256 / 4);
    split_f32<<<128, 256>>>((const float4*)W2a, (uint2*)W2AHI, (uint2*)W2ALO, 512 * 256 / 4);
    split_f32<<<192, 256>>>((const float4*)Whh, (uint2*)WHHHI, (uint2*)WHHLO, 768 * 256 / 4);

    zero_u32<<<16, 256>>>((uint32_t*)FLAGS, NCTA_GRU * 2 * 32);
    zero_u32<<<64, 256>>>((uint32_t*)GICNT, TT * 32);

    // ---- fc1a + fc1b (standalone) ----
    gemm_bf<true, 1><<<dim3(4, M / 128), 256, G_SM_TOTAL>>>(
        XHI, XLO, W1AHI, W1ALO, b1a, nullptr, A1HI, A1LO, M, 512, 256);
    gemm_bf<true, 1><<<dim3(2, M / 128), 256, G_SM_TOTAL>>>(
        A1HI, A1LO, W1BHI, W1BLO, b1b, nullptr, A2HI, A2LO, M, 256, 512);

    // ---- persistent GRU + fused gi/fc2a workers (148 CTAs) ----
    gru_persist<<<NCTA_ALL, 256, U_SM_TOTAL>>>(
        GI, WHHHI, WHHLO, bhh, HHI, HLO, FLAGS, W2AHI, W2ALO, b2a, buf1,
        A2HI, A2LO, WIHHI, WIHLO, bih, GICNT);

    // head
    head_gemm<<<M / 1024, 256>>>(buf1, W2b, b2b, out, M);
}